// round 1
// baseline (speedup 1.0000x reference)
#include <cuda_runtime.h>
#include <math.h>

#define EXP 4
#define NTOK 2048
#define DIM 512
#define NH 8
#define DHEAD 64
#define FFD 2048
#define NL 4
#define MEMSZ 4096

#define ND_ELEMS (NTOK * DIM)                      // 1048576
#define LMD_ELEMS (NL * MEMSZ * DIM)               // 8388608

// ---------------- scratch (device globals; no allocations allowed) ----------------
__device__ float g_xln[EXP * NTOK * DIM];          // LN(tokens) all experts
__device__ float g_x[NTOK * DIM];                  // x after cross-attn
__device__ float g_qkv[NTOK * 3 * DIM];
__device__ float g_big[(size_t)NH * NTOK * NTOK];  // reused: cross logits / attn scores / mem logits
__device__ float g_sa[NTOK * DIM];                 // self-attn out, also ff2 out
__device__ float g_tmp[NTOK * FFD];                // out_proj tmp / ff1
__device__ float g_x1[NTOK * DIM];
__device__ float g_out[EXP * NTOK * DIM];          // expert outputs -> outs
__device__ float g_retr[NL * NTOK * DIM];
__device__ float g_retrp[NTOK * NL * DIM];
__device__ float g_upd[NL * MEMSZ * DIM];          // sum over experts of clipped upd
__device__ float g_glog[EXP];

// ---------------- reduction helpers ----------------
__device__ __forceinline__ float warpReduceSum(float v) {
#pragma unroll
    for (int o = 16; o; o >>= 1) v += __shfl_xor_sync(0xffffffffu, v, o);
    return v;
}
__device__ __forceinline__ float warpReduceMax(float v) {
#pragma unroll
    for (int o = 16; o; o >>= 1) v = fmaxf(v, __shfl_xor_sync(0xffffffffu, v, o));
    return v;
}

// ---------------- generic tiled GEMM ----------------
// MODE 0 (NT): C[M,Nc] = A[M,K] * B[Nc,K]^T          (both K-contiguous)
// MODE 1 (NN): C[M,Nc] = A[M,K] * B[K,Nc]            (B Nc-contiguous)
// MODE 2 (TN): C[M,Nc] = A[K,M]^T * B[K,Nc]
// Epilogue: v = alpha*acc (+bias[col]) (relu) (clip +-clipVal) (+resid) ; C=v or C+=v
// B-row remap (skipLen>0): logical row r -> r + skipLen if r >= skipStart
#define GFLAG_RELU 1
#define GFLAG_ACCUM 2

template <int MODE>
__global__ void __launch_bounds__(256) gemm_k(
    const float* __restrict__ A, const float* __restrict__ B, float* __restrict__ C,
    int M, int Nc, int K, int lda, int ldb, int ldc,
    long long aBatch, long long bBatch, long long cBatch,
    float alpha, const float* __restrict__ bias,
    const float* __restrict__ resid, long long residBatch, int residLd,
    float clipVal, int flags, int skipStart, int skipLen)
{
    __shared__ float As[16][68];
    __shared__ float Bs[16][68];
    int bz = blockIdx.z;
    A += aBatch * bz; B += bBatch * bz; C += cBatch * bz;
    int m0 = blockIdx.y * 64, n0 = blockIdx.x * 64;
    int t = threadIdx.x;
    int tx = t & 15, ty = t >> 4;
    float acc[4][4] = {};

    for (int k0 = 0; k0 < K; k0 += 16) {
        if (MODE == 2) {
            int kr = t >> 4;
            int mq = (t & 15) * 4;
            float4 v = *(const float4*)&A[(long long)(k0 + kr) * lda + m0 + mq];
            As[kr][mq + 0] = v.x; As[kr][mq + 1] = v.y; As[kr][mq + 2] = v.z; As[kr][mq + 3] = v.w;
        } else {
            int r = t >> 2;
            int kq = (t & 3) * 4;
            float4 v = *(const float4*)&A[(long long)(m0 + r) * lda + k0 + kq];
            As[kq + 0][r] = v.x; As[kq + 1][r] = v.y; As[kq + 2][r] = v.z; As[kq + 3][r] = v.w;
        }
        if (MODE == 0) {
            int r = t >> 2;
            int kq = (t & 3) * 4;
            int rl = n0 + r;
            int rp = (skipLen && rl >= skipStart) ? rl + skipLen : rl;
            float4 v = *(const float4*)&B[(long long)rp * ldb + k0 + kq];
            Bs[kq + 0][r] = v.x; Bs[kq + 1][r] = v.y; Bs[kq + 2][r] = v.z; Bs[kq + 3][r] = v.w;
        } else {
            int kr = t >> 4;
            int nq = (t & 15) * 4;
            int rl = k0 + kr;
            int rp = (MODE == 1 && skipLen && rl >= skipStart) ? rl + skipLen : rl;
            float4 v = *(const float4*)&B[(long long)rp * ldb + n0 + nq];
            Bs[kr][nq + 0] = v.x; Bs[kr][nq + 1] = v.y; Bs[kr][nq + 2] = v.z; Bs[kr][nq + 3] = v.w;
        }
        __syncthreads();
#pragma unroll
        for (int kk = 0; kk < 16; kk++) {
            float4 a4 = *(const float4*)&As[kk][ty * 4];
            float4 b4 = *(const float4*)&Bs[kk][tx * 4];
            float a[4] = {a4.x, a4.y, a4.z, a4.w};
            float b[4] = {b4.x, b4.y, b4.z, b4.w};
#pragma unroll
            for (int i = 0; i < 4; i++)
#pragma unroll
                for (int j = 0; j < 4; j++) acc[i][j] += a[i] * b[j];
        }
        __syncthreads();
    }

#pragma unroll
    for (int i = 0; i < 4; i++) {
        int row = m0 + ty * 4 + i;
#pragma unroll
        for (int j = 0; j < 4; j++) {
            int col = n0 + tx * 4 + j;
            float v = alpha * acc[i][j];
            if (bias) v += bias[col];
            if (flags & GFLAG_RELU) v = fmaxf(v, 0.f);
            if (clipVal > 0.f) v = fminf(fmaxf(v, -clipVal), clipVal);
            if (resid) v += resid[residBatch * bz + (long long)row * residLd + col];
            long long ci = (long long)row * ldc + col;
            if (flags & GFLAG_ACCUM) C[ci] += v; else C[ci] = v;
        }
    }
}

// ---------------- row softmax (in place), blockDim 256 ----------------
__global__ void softmax_k(float* __restrict__ p, int cols) {
    float* row = p + (long long)blockIdx.x * cols;
    __shared__ float sh[8];
    __shared__ float sb;
    int tid = threadIdx.x, lane = tid & 31, wid = tid >> 5;
    float m = -1e30f;
    for (int i = tid; i < cols; i += 256) m = fmaxf(m, row[i]);
    m = warpReduceMax(m);
    if (lane == 0) sh[wid] = m;
    __syncthreads();
    if (tid == 0) { float t = sh[0]; for (int w = 1; w < 8; w++) t = fmaxf(t, sh[w]); sb = t; }
    __syncthreads();
    m = sb;
    float s = 0.f;
    for (int i = tid; i < cols; i += 256) { float v = expf(row[i] - m); row[i] = v; s += v; }
    s = warpReduceSum(s);
    if (lane == 0) sh[wid] = s;
    __syncthreads();
    if (tid == 0) { float t = 0; for (int w = 0; w < 8; w++) t += sh[w]; sb = 1.f / t; }
    __syncthreads();
    float inv = sb;
    for (int i = tid; i < cols; i += 256) row[i] *= inv;
}

// ---------------- LayerNorm kernels, blockDim 128, row of 512 ----------------
__global__ void ln_k(const float* __restrict__ src, float* __restrict__ dst) {
    long long row = blockIdx.x;
    const float* x = src + row * DIM;
    float* y = dst + row * DIM;
    int tid = threadIdx.x, lane = tid & 31, wid = tid >> 5;
    float v[4], s = 0.f, s2 = 0.f;
#pragma unroll
    for (int j = 0; j < 4; j++) { v[j] = x[tid + j * 128]; s += v[j]; s2 += v[j] * v[j]; }
    s = warpReduceSum(s); s2 = warpReduceSum(s2);
    __shared__ float sh[2][4]; __shared__ float mv[2];
    if (lane == 0) { sh[0][wid] = s; sh[1][wid] = s2; }
    __syncthreads();
    if (tid == 0) {
        float t = sh[0][0] + sh[0][1] + sh[0][2] + sh[0][3];
        float t2 = sh[1][0] + sh[1][1] + sh[1][2] + sh[1][3];
        float mean = t / DIM;
        float var = t2 / DIM - mean * mean;
        mv[0] = mean; mv[1] = rsqrtf(var + 1e-5f);
    }
    __syncthreads();
    float mean = mv[0], rstd = mv[1];
#pragma unroll
    for (int j = 0; j < 4; j++) y[tid + j * 128] = (v[j] - mean) * rstd;
}

// dst = LN(a+b)*w + bb
__global__ void ln_ra_k(const float* __restrict__ a, const float* __restrict__ b,
                        const float* __restrict__ w, const float* __restrict__ bb,
                        float* __restrict__ dst) {
    long long row = blockIdx.x;
    const float* xa = a + row * DIM;
    const float* xb = b + row * DIM;
    float* y = dst + row * DIM;
    int tid = threadIdx.x, lane = tid & 31, wid = tid >> 5;
    float v[4], s = 0.f, s2 = 0.f;
#pragma unroll
    for (int j = 0; j < 4; j++) {
        int i = tid + j * 128;
        v[j] = xa[i] + xb[i]; s += v[j]; s2 += v[j] * v[j];
    }
    s = warpReduceSum(s); s2 = warpReduceSum(s2);
    __shared__ float sh[2][4]; __shared__ float mv[2];
    if (lane == 0) { sh[0][wid] = s; sh[1][wid] = s2; }
    __syncthreads();
    if (tid == 0) {
        float t = sh[0][0] + sh[0][1] + sh[0][2] + sh[0][3];
        float t2 = sh[1][0] + sh[1][1] + sh[1][2] + sh[1][3];
        float mean = t / DIM;
        float var = t2 / DIM - mean * mean;
        mv[0] = mean; mv[1] = rsqrtf(var + 1e-5f);
    }
    __syncthreads();
    float mean = mv[0], rstd = mv[1];
#pragma unroll
    for (int j = 0; j < 4; j++) {
        int i = tid + j * 128;
        y[i] = (v[j] - mean) * rstd * w[i] + bb[i];
    }
}

// retrp[n, l*D+d] = retr[l, n, d]
__global__ void permute_k(const float* __restrict__ retr, float* __restrict__ rp) {
    long long i = (long long)blockIdx.x * 256 + threadIdx.x;
    if (i < (long long)NL * NTOK * DIM) {
        int d = (int)(i & (DIM - 1));
        long long r = i >> 9;
        int n = (int)(r & (NTOK - 1));
        int l = (int)(r >> 11);
        rp[((long long)n * NL + l) * DIM + d] = retr[i];
    }
}

__global__ void zero_k(float* __restrict__ p, long long n) {
    long long i = (long long)blockIdx.x * 256 + threadIdx.x;
    if (i < n) p[i] = 0.f;
}

// partial dot(outs[e], broadcast gg over rows) -> atomicAdd into glog[e]
__global__ void gate_dot_k(const float* __restrict__ outs, const float* __restrict__ gg,
                           float* __restrict__ glog) {
    int e = blockIdx.x;
    long long chunk = (long long)ND_ELEMS / gridDim.y;
    long long base = (long long)e * ND_ELEMS + (long long)blockIdx.y * chunk;
    float acc = 0.f;
    for (long long i = threadIdx.x; i < chunk; i += blockDim.x) {
        long long idx = base + i;
        acc += outs[idx] * gg[idx & (DIM - 1)];
    }
    acc = warpReduceSum(acc);
    __shared__ float sh[8];
    int lane = threadIdx.x & 31, wid = threadIdx.x >> 5;
    if (lane == 0) sh[wid] = acc;
    __syncthreads();
    if (threadIdx.x == 0) {
        float t = 0;
        for (int w = 0; w < 8; w++) t += sh[w];
        atomicAdd(&glog[e], t);
    }
}

__global__ void gate_softmax_k(const float* __restrict__ glog, float* __restrict__ gw) {
    if (threadIdx.x == 0) {
        float l[EXP], m = -1e30f;
        for (int e = 0; e < EXP; e++) {
            l[e] = fminf(fmaxf(glog[e] / (float)NTOK, -10.f), 10.f);
            m = fmaxf(m, l[e]);
        }
        float s = 0.f;
        for (int e = 0; e < EXP; e++) { l[e] = expf(l[e] - m); s += l[e]; }
        for (int e = 0; e < EXP; e++) gw[e] = l[e] / s;
    }
}

__global__ void fuse_k(const float* __restrict__ outs, const float* __restrict__ gw,
                       float* __restrict__ fused) {
    long long i = (long long)blockIdx.x * 256 + threadIdx.x;
    if (i < (long long)ND_ELEMS) {
        float r = 0.f;
#pragma unroll
        for (int e = 0; e < EXP; e++) r += gw[e] * outs[(long long)e * ND_ELEMS + i];
        fused[i] = r;
    }
}

__global__ void memupd_k(const float* __restrict__ mem, const float* __restrict__ upd,
                         float* __restrict__ o) {
    long long i = (long long)blockIdx.x * 256 + threadIdx.x;
    if (i < (long long)LMD_ELEMS) {
        float u = 0.1f * upd[i];
        u = fminf(fmaxf(u, -0.1f), 0.1f);
        o[i] = 0.9f * mem[i] + u;
    }
}

// ---------------- host side ----------------
static void gemm(int mode, const float* A, const float* B, float* C,
                 int M, int Nc, int K, int lda, int ldb, int ldc,
                 long long aB, long long bB, long long cB, int batches,
                 float alpha, const float* bias,
                 const float* resid, long long residB, int residLd,
                 float clipv, int flags, int skipStart, int skipLen) {
    dim3 grid(Nc / 64, M / 64, batches), block(256);
    if (mode == 0)
        gemm_k<0><<<grid, block>>>(A, B, C, M, Nc, K, lda, ldb, ldc, aB, bB, cB,
                                   alpha, bias, resid, residB, residLd, clipv, flags, skipStart, skipLen);
    else if (mode == 1)
        gemm_k<1><<<grid, block>>>(A, B, C, M, Nc, K, lda, ldb, ldc, aB, bB, cB,
                                   alpha, bias, resid, residB, residLd, clipv, flags, skipStart, skipLen);
    else
        gemm_k<2><<<grid, block>>>(A, B, C, M, Nc, K, lda, ldb, ldc, aB, bB, cB,
                                   alpha, bias, resid, residB, residLd, clipv, flags, skipStart, skipLen);
}

extern "C" void kernel_launch(void* const* d_in, const int* in_sizes, int n_in,
                              void* d_out, int out_size) {
    const float* tokens   = (const float*)d_in[0];
    const float* memories = (const float*)d_in[1];
    const float* ipw      = (const float*)d_in[2];
    const float* ipb      = (const float*)d_in[3];
    const float* opw      = (const float*)d_in[4];
    const float* opb      = (const float*)d_in[5];
    const float* w1       = (const float*)d_in[6];
    const float* b1       = (const float*)d_in[7];
    const float* w2       = (const float*)d_in[8];
    const float* b2       = (const float*)d_in[9];
    const float* n1w      = (const float*)d_in[10];
    const float* n1b      = (const float*)d_in[11];
    const float* n2w      = (const float*)d_in[12];
    const float* n2b      = (const float*)d_in[13];
    const float* aggw     = (const float*)d_in[14];
    const float* aggb     = (const float*)d_in[15];
    const float* gg       = (const float*)d_in[16];

    float* out = (float*)d_out;
    float* out_fused = out;
    float* out_gw = out + ND_ELEMS;
    float* out_mem = out + ND_ELEMS + EXP;

    static float *p_xln = nullptr, *p_x = nullptr, *p_qkv = nullptr, *p_big = nullptr,
                 *p_sa = nullptr, *p_tmp = nullptr, *p_x1 = nullptr, *p_out = nullptr,
                 *p_retr = nullptr, *p_retrp = nullptr, *p_upd = nullptr, *p_glog = nullptr;
    if (!p_xln) {
        cudaGetSymbolAddress((void**)&p_xln, g_xln);
        cudaGetSymbolAddress((void**)&p_x, g_x);
        cudaGetSymbolAddress((void**)&p_qkv, g_qkv);
        cudaGetSymbolAddress((void**)&p_big, g_big);
        cudaGetSymbolAddress((void**)&p_sa, g_sa);
        cudaGetSymbolAddress((void**)&p_tmp, g_tmp);
        cudaGetSymbolAddress((void**)&p_x1, g_x1);
        cudaGetSymbolAddress((void**)&p_out, g_out);
        cudaGetSymbolAddress((void**)&p_retr, g_retr);
        cudaGetSymbolAddress((void**)&p_retrp, g_retrp);
        cudaGetSymbolAddress((void**)&p_upd, g_upd);
        cudaGetSymbolAddress((void**)&p_glog, g_glog);
    }

    const float inv_sqrt_d = 1.0f / sqrtf((float)DIM);
    const float inv_sqrt_dh = 1.0f / sqrtf((float)DHEAD);

    // zero accumulators (must happen every call: graph replays)
    zero_k<<<(LMD_ELEMS + 255) / 256, 256>>>(p_upd, LMD_ELEMS);
    zero_k<<<1, 256>>>(p_glog, EXP);

    // LN of all tokens
    ln_k<<<EXP * NTOK, 128>>>(tokens, p_xln);

    for (int e = 0; e < EXP; e++) {
        const float* Ax = p_xln + (long long)e * ND_ELEMS;
        // cross-expert logits: [N, 3N] = clip(xln_e @ ctx^T / sqrt(D))
        gemm(0, Ax, p_xln, p_big, NTOK, 3 * NTOK, DIM, DIM, DIM, 3 * NTOK,
             0, 0, 0, 1, inv_sqrt_d, nullptr, nullptr, 0, 0, 10.f, 0, e * NTOK, NTOK);
        softmax_k<<<NTOK, 256>>>(p_big, 3 * NTOK);
        // x = probs @ ctx + xln_e
        gemm(1, p_big, p_xln, p_x, NTOK, DIM, 3 * NTOK, 3 * NTOK, DIM, DIM,
             0, 0, 0, 1, 1.f, nullptr, Ax, 0, DIM, 0.f, 0, e * NTOK, NTOK);
        // qkv = x @ ipw^T + ipb
        gemm(0, p_x, ipw + (long long)e * 3 * DIM * DIM, p_qkv, NTOK, 3 * DIM, DIM,
             DIM, DIM, 3 * DIM, 0, 0, 0, 1, 1.f, ipb + e * 3 * DIM,
             nullptr, 0, 0, 0.f, 0, 0, 0);
        // scores[h] = q_h @ k_h^T / sqrt(dh), batched over heads
        gemm(0, p_qkv, p_qkv + DIM, p_big, NTOK, NTOK, DHEAD,
             3 * DIM, 3 * DIM, NTOK, DHEAD, DHEAD, (long long)NTOK * NTOK, NH,
             inv_sqrt_dh, nullptr, nullptr, 0, 0, 0.f, 0, 0, 0);
        softmax_k<<<NH * NTOK, 256>>>(p_big, NTOK);
        // sa[:, h*64:(h+1)*64] = probs_h @ v_h
        gemm(1, p_big, p_qkv + 2 * DIM, p_sa, NTOK, DHEAD, NTOK,
             NTOK, 3 * DIM, DIM, (long long)NTOK * NTOK, DHEAD, DHEAD, NH,
             1.f, nullptr, nullptr, 0, 0, 0.f, 0, 0, 0);
        // out_proj
        gemm(0, p_sa, opw + (long long)e * DIM * DIM, p_tmp, NTOK, DIM, DIM,
             DIM, DIM, DIM, 0, 0, 0, 1, 1.f, opb + e * DIM, nullptr, 0, 0, 0.f, 0, 0, 0);
        // x1 = LN(x + sa_out) * n1w + n1b
        ln_ra_k<<<NTOK, 128>>>(p_x, p_tmp, n1w + e * DIM, n1b + e * DIM, p_x1);
        // ff1 = relu(x1 @ w1^T + b1)
        gemm(0, p_x1, w1 + (long long)e * FFD * DIM, p_tmp, NTOK, FFD, DIM,
             DIM, DIM, FFD, 0, 0, 0, 1, 1.f, b1 + e * FFD, nullptr, 0, 0, 0.f, GFLAG_RELU, 0, 0);
        // ff2 = ff1 @ w2^T + b2
        gemm(0, p_tmp, w2 + (long long)e * DIM * FFD, p_sa, NTOK, DIM, FFD,
             FFD, FFD, DIM, 0, 0, 0, 1, 1.f, b2 + e * DIM, nullptr, 0, 0, 0.f, 0, 0, 0);
        // xout = LN(x1 + ff2) * n2w + n2b
        float* xo = p_out + (long long)e * ND_ELEMS;
        ln_ra_k<<<NTOK, 128>>>(p_x1, p_sa, n2w + e * DIM, n2b + e * DIM, xo);
        // memory logits: [L][N, M] = clip(xout @ mem_l^T / sqrt(D))
        gemm(0, xo, memories, p_big, NTOK, MEMSZ, DIM, DIM, DIM, MEMSZ,
             0, (long long)MEMSZ * DIM, (long long)NTOK * MEMSZ, NL,
             inv_sqrt_d, nullptr, nullptr, 0, 0, 10.f, 0, 0, 0);
        softmax_k<<<NL * NTOK, 256>>>(p_big, MEMSZ);
        // retr[l] = am[l] @ mem_l
        gemm(1, p_big, memories, p_retr, NTOK, DIM, MEMSZ, MEMSZ, DIM, DIM,
             (long long)NTOK * MEMSZ, (long long)MEMSZ * DIM, (long long)NTOK * DIM, NL,
             1.f, nullptr, nullptr, 0, 0, 0.f, 0, 0, 0);
        // upd[l] += clip(am[l]^T @ xout, +-1)
        gemm(2, p_big, xo, p_upd, MEMSZ, DIM, NTOK, MEMSZ, DIM, DIM,
             (long long)NTOK * MEMSZ, 0, (long long)MEMSZ * DIM, NL,
             1.f, nullptr, nullptr, 0, 0, 1.f, GFLAG_ACCUM, 0, 0);
        // permute retr -> [N, L*D]
        permute_k<<<(NL * ND_ELEMS + 255) / 256, 256>>>(p_retr, p_retrp);
        // outs[e] = xout + retrp @ aggw^T + aggb   (in-place residual)
        gemm(0, p_retrp, aggw, xo, NTOK, DIM, NL * DIM,
             NL * DIM, NL * DIM, DIM, 0, 0, 0, 1,
             1.f, aggb, xo, 0, DIM, 0.f, 0, 0, 0);
    }

    // gating + fuse + memory EMA
    dim3 ggrid(EXP, 16);
    gate_dot_k<<<ggrid, 256>>>(p_out, gg, p_glog);
    gate_softmax_k<<<1, 32>>>(p_glog, out_gw);
    fuse_k<<<(ND_ELEMS + 255) / 256, 256>>>(p_out, out_gw, out_fused);
    memupd_k<<<(LMD_ELEMS + 255) / 256, 256>>>(memories, p_upd, out_mem);

    (void)in_sizes; (void)n_in; (void)out_size;
}

// round 3
// speedup vs baseline: 3.2816x; 3.2816x over previous
#include <cuda_runtime.h>
#include <math.h>
#include <stdint.h>

#define EXP 4
#define NTOK 2048
#define DIM 512
#define NH 8
#define DHEAD 64
#define FFD 2048
#define NL 4
#define MEMSZ 4096

#define ND_ELEMS (NTOK * DIM)
#define LMD_ELEMS (NL * MEMSZ * DIM)

#define GFLAG_RELU 1
#define GFLAG_ACCUM 2

// ---------------- scratch ----------------
__device__ float g_xln[EXP * NTOK * DIM];
__device__ float g_x[NTOK * DIM];
__device__ float g_qkv[NTOK * 3 * DIM];
__device__ float g_big[(size_t)NH * NTOK * NTOK];
__device__ float g_sa[NTOK * DIM];
__device__ float g_tmp[NTOK * FFD];
__device__ float g_x1[NTOK * DIM];
__device__ float g_out[EXP * NTOK * DIM];
__device__ float g_retr[NL * NTOK * DIM];
__device__ float g_retrp[NTOK * NL * DIM];
__device__ float g_upd[NL * MEMSZ * DIM];
__device__ float g_glog[EXP];

// ---------------- helpers ----------------
__device__ __forceinline__ uint32_t tf(float x) {
    uint32_t u; asm("cvt.rna.tf32.f32 %0, %1;" : "=r"(u) : "f"(x)); return u;
}
__device__ __forceinline__ void mma8(float* c, const uint32_t* a, const uint32_t* b) {
    asm volatile(
        "mma.sync.aligned.m16n8k8.row.col.f32.tf32.tf32.f32 "
        "{%0,%1,%2,%3}, {%4,%5,%6,%7}, {%8,%9}, {%0,%1,%2,%3};"
        : "+f"(c[0]), "+f"(c[1]), "+f"(c[2]), "+f"(c[3])
        : "r"(a[0]), "r"(a[1]), "r"(a[2]), "r"(a[3]), "r"(b[0]), "r"(b[1]));
}

// ---------------- GEMM tile loaders ----------------
// SMEM layouts: As[m][k] stride 36, Bs[n][k] stride 36, k-chunk 32.
#define KST 36

template <bool TR>
__device__ __forceinline__ void ldgA(float* r, const float* __restrict__ A, int lda,
                                     int m0, int k0, int t, int l, int w) {
    if (!TR) {
#pragma unroll
        for (int j = 0; j < 4; j++)
            *(float4*)&r[j * 4] = *(const float4*)&A[(long long)(m0 + (t >> 3) + j * 32) * lda + k0 + (t & 7) * 4];
    } else {
#pragma unroll
        for (int j = 0; j < 4; j++)
            *(float4*)&r[j * 4] = *(const float4*)&A[(long long)(k0 + l) * lda + m0 + w * 16 + j * 4];
    }
}
template <bool TR>
__device__ __forceinline__ void stsA(float* As, const float* r, int t, int l, int w) {
    if (!TR) {
#pragma unroll
        for (int j = 0; j < 4; j++) {
            uint4 u = make_uint4(tf(r[j * 4]), tf(r[j * 4 + 1]), tf(r[j * 4 + 2]), tf(r[j * 4 + 3]));
            *(uint4*)&As[((t >> 3) + j * 32) * KST + (t & 7) * 4] = u;
        }
    } else {
#pragma unroll
        for (int j = 0; j < 4; j++)
#pragma unroll
            for (int q = 0; q < 4; q++)
                ((uint32_t*)As)[(w * 16 + j * 4 + q) * KST + l] = tf(r[j * 4 + q]);
    }
}
template <int NT_, bool TR>
__device__ __forceinline__ void ldgB(float* r, const float* __restrict__ B, int ldb,
                                     int n0, int k0, int rs, int rl, int t, int l, int w) {
    if (!TR) {
#pragma unroll
        for (int j = 0; j < NT_ / 32; j++) {
            int n = n0 + (t >> 3) + j * 32;
            if (rl && n >= rs) n += rl;
            *(float4*)&r[j * 4] = *(const float4*)&B[(long long)n * ldb + k0 + (t & 7) * 4];
        }
    } else {
        int g = k0 + l;
        if (rl && g >= rs) g += rl;
#pragma unroll
        for (int j = 0; j < NT_ / 32; j++)
            *(float4*)&r[j * 4] = *(const float4*)&B[(long long)g * ldb + n0 + w * (NT_ / 8) + j * 4];
    }
}
template <int NT_, bool TR>
__device__ __forceinline__ void stsB(float* Bs, const float* r, int t, int l, int w) {
    if (!TR) {
#pragma unroll
        for (int j = 0; j < NT_ / 32; j++) {
            uint4 u = make_uint4(tf(r[j * 4]), tf(r[j * 4 + 1]), tf(r[j * 4 + 2]), tf(r[j * 4 + 3]));
            *(uint4*)&Bs[((t >> 3) + j * 32) * KST + (t & 7) * 4] = u;
        }
    } else {
#pragma unroll
        for (int j = 0; j < NT_ / 32; j++)
#pragma unroll
            for (int q = 0; q < 4; q++)
                ((uint32_t*)Bs)[(w * (NT_ / 8) + j * 4 + q) * KST + l] = tf(r[j * 4 + q]);
    }
}

// ---------------- tf32 mma.sync GEMM ----------------
// C[M,Nc] = alpha*op(A)*op(B) (+bias)(relu)(clip)(+resid)(accum)
// ATR: A stored [K,M] (M contig). BTR: B stored [K,Nc] (Nc contig). Else K-contig.
template <int NT_, bool ATR, bool BTR>
__global__ void __launch_bounds__(256, 1) gemmMMA(
    const float* __restrict__ A, const float* __restrict__ B, float* __restrict__ C,
    int K, int lda, int ldb, int ldc,
    long long aB, long long bB, long long cB,
    float alpha, const float* __restrict__ bias,
    const float* __restrict__ resid, long long residB, int residLd,
    float clipVal, int flags, int rs, int rl)
{
    extern __shared__ float sm[];
    float* As = sm;                       // [2][128*KST]
    float* Bs = sm + 2 * 128 * KST;       // [2][NT_*KST]

    const int t = threadIdx.x, l = t & 31, w = t >> 5;
    const int bz = blockIdx.z;
    A += aB * bz; B += bB * bz; C += cB * bz;
    const int m0 = blockIdx.y * 128, n0 = blockIdx.x * NT_;

    constexpr int WN = NT_ / 4;
    constexpr int NB = WN / 8;
    const int wm0 = (w >> 2) * 64, wn0 = (w & 3) * WN;

    float acc[4][NB][4];
#pragma unroll
    for (int a = 0; a < 4; a++)
#pragma unroll
        for (int b = 0; b < NB; b++)
#pragma unroll
            for (int c = 0; c < 4; c++) acc[a][b][c] = 0.f;

    float ra[16], rb[16];
    const int nK = K / 32;

    ldgA<ATR>(ra, A, lda, m0, 0, t, l, w);
    ldgB<NT_, BTR>(rb, B, ldb, n0, 0, rs, rl, t, l, w);
    stsA<ATR>(As, ra, t, l, w);
    stsB<NT_, BTR>(Bs, rb, t, l, w);
    __syncthreads();

    for (int i = 0; i < nK; i++) {
        int cur = i & 1;
        if (i + 1 < nK) {
            ldgA<ATR>(ra, A, lda, m0, (i + 1) * 32, t, l, w);
            ldgB<NT_, BTR>(rb, B, ldb, n0, (i + 1) * 32, rs, rl, t, l, w);
        }
        const float* Ab = As + cur * 128 * KST;
        const float* Bb = Bs + cur * NT_ * KST;
#pragma unroll
        for (int kk = 0; kk < 4; kk++) {
            const int kc = kk * 8;
            uint32_t af[4][4], bf[NB][2];
#pragma unroll
            for (int mi = 0; mi < 4; mi++) {
                const float* ap = &Ab[(wm0 + mi * 16 + (l >> 2)) * KST + kc + (l & 3)];
                af[mi][0] = __float_as_uint(ap[0]);
                af[mi][1] = __float_as_uint(ap[8 * KST]);
                af[mi][2] = __float_as_uint(ap[4]);
                af[mi][3] = __float_as_uint(ap[8 * KST + 4]);
            }
#pragma unroll
            for (int ni = 0; ni < NB; ni++) {
                const float* bp = &Bb[(wn0 + ni * 8 + (l >> 2)) * KST + kc + (l & 3)];
                bf[ni][0] = __float_as_uint(bp[0]);
                bf[ni][1] = __float_as_uint(bp[4]);
            }
#pragma unroll
            for (int mi = 0; mi < 4; mi++)
#pragma unroll
                for (int ni = 0; ni < NB; ni++) mma8(acc[mi][ni], af[mi], bf[ni]);
        }
        if (i + 1 < nK) {
            stsA<ATR>(As + (1 - cur) * 128 * KST, ra, t, l, w);
            stsB<NT_, BTR>(Bs + (1 - cur) * NT_ * KST, rb, t, l, w);
        }
        __syncthreads();
    }

    // epilogue: regs -> global (float2 per c-pair)
#pragma unroll
    for (int mi = 0; mi < 4; mi++) {
        int row0 = m0 + wm0 + mi * 16 + (l >> 2);
#pragma unroll
        for (int ni = 0; ni < NB; ni++) {
            int col = n0 + wn0 + ni * 8 + (l & 3) * 2;
#pragma unroll
            for (int h = 0; h < 2; h++) {
                int row = row0 + h * 8;
                float vx = alpha * acc[mi][ni][h * 2];
                float vy = alpha * acc[mi][ni][h * 2 + 1];
                if (bias) { vx += bias[col]; vy += bias[col + 1]; }
                if (flags & GFLAG_RELU) { vx = fmaxf(vx, 0.f); vy = fmaxf(vy, 0.f); }
                if (clipVal > 0.f) {
                    vx = fminf(fmaxf(vx, -clipVal), clipVal);
                    vy = fminf(fmaxf(vy, -clipVal), clipVal);
                }
                if (resid) {
                    float2 rv = *(const float2*)&resid[residB * bz + (long long)row * residLd + col];
                    vx += rv.x; vy += rv.y;
                }
                float2* cp = (float2*)&C[(long long)row * ldc + col];
                if (flags & GFLAG_ACCUM) {
                    float2 o = *cp;
                    vx += o.x; vy += o.y;
                }
                *cp = make_float2(vx, vy);
            }
        }
    }
}

// ---------------- reductions ----------------
__device__ __forceinline__ float warpReduceSum(float v) {
#pragma unroll
    for (int o = 16; o; o >>= 1) v += __shfl_xor_sync(0xffffffffu, v, o);
    return v;
}
__device__ __forceinline__ float warpReduceMax(float v) {
#pragma unroll
    for (int o = 16; o; o >>= 1) v = fmaxf(v, __shfl_xor_sync(0xffffffffu, v, o));
    return v;
}

// ---------------- smem-cached row softmax ----------------
__global__ void softmax_k(float* __restrict__ p, int cols) {
    extern __shared__ float sbuf[];
    float* row = p + (long long)blockIdx.x * cols;
    __shared__ float sh[8];
    __shared__ float sb;
    int tid = threadIdx.x, lane = tid & 31, wid = tid >> 5;
    float m = -1e30f;
    for (int i = tid; i < cols; i += 256) { float v = row[i]; sbuf[i] = v; m = fmaxf(m, v); }
    m = warpReduceMax(m);
    if (lane == 0) sh[wid] = m;
    __syncthreads();
    if (tid == 0) { float x = sh[0]; for (int q = 1; q < 8; q++) x = fmaxf(x, sh[q]); sb = x; }
    __syncthreads();
    m = sb;
    float s = 0.f;
    for (int i = tid; i < cols; i += 256) { float v = expf(sbuf[i] - m); sbuf[i] = v; s += v; }
    s = warpReduceSum(s);
    if (lane == 0) sh[wid] = s;
    __syncthreads();
    if (tid == 0) { float x = 0; for (int q = 0; q < 8; q++) x += sh[q]; sb = 1.f / x; }
    __syncthreads();
    float inv = sb;
    for (int i = tid; i < cols; i += 256) row[i] = sbuf[i] * inv;
}

// ---------------- LayerNorm ----------------
__global__ void ln_k(const float* __restrict__ src, float* __restrict__ dst) {
    long long row = blockIdx.x;
    const float* x = src + row * DIM;
    float* y = dst + row * DIM;
    int tid = threadIdx.x, lane = tid & 31, wid = tid >> 5;
    float v[4], s = 0.f, s2 = 0.f;
#pragma unroll
    for (int j = 0; j < 4; j++) { v[j] = x[tid + j * 128]; s += v[j]; s2 += v[j] * v[j]; }
    s = warpReduceSum(s); s2 = warpReduceSum(s2);
    __shared__ float sh[2][4]; __shared__ float mv[2];
    if (lane == 0) { sh[0][wid] = s; sh[1][wid] = s2; }
    __syncthreads();
    if (tid == 0) {
        float a = sh[0][0] + sh[0][1] + sh[0][2] + sh[0][3];
        float b = sh[1][0] + sh[1][1] + sh[1][2] + sh[1][3];
        float mean = a / DIM;
        mv[0] = mean; mv[1] = rsqrtf(b / DIM - mean * mean + 1e-5f);
    }
    __syncthreads();
    float mean = mv[0], rstd = mv[1];
#pragma unroll
    for (int j = 0; j < 4; j++) y[tid + j * 128] = (v[j] - mean) * rstd;
}

__global__ void ln_ra_k(const float* __restrict__ a, const float* __restrict__ b,
                        const float* __restrict__ w, const float* __restrict__ bb,
                        float* __restrict__ dst) {
    long long row = blockIdx.x;
    const float* xa = a + row * DIM;
    const float* xb = b + row * DIM;
    float* y = dst + row * DIM;
    int tid = threadIdx.x, lane = tid & 31, wid = tid >> 5;
    float v[4], s = 0.f, s2 = 0.f;
#pragma unroll
    for (int j = 0; j < 4; j++) {
        int i = tid + j * 128;
        v[j] = xa[i] + xb[i]; s += v[j]; s2 += v[j] * v[j];
    }
    s = warpReduceSum(s); s2 = warpReduceSum(s2);
    __shared__ float sh[2][4]; __shared__ float mv[2];
    if (lane == 0) { sh[0][wid] = s; sh[1][wid] = s2; }
    __syncthreads();
    if (tid == 0) {
        float p = sh[0][0] + sh[0][1] + sh[0][2] + sh[0][3];
        float q = sh[1][0] + sh[1][1] + sh[1][2] + sh[1][3];
        float mean = p / DIM;
        mv[0] = mean; mv[1] = rsqrtf(q / DIM - mean * mean + 1e-5f);
    }
    __syncthreads();
    float mean = mv[0], rstd = mv[1];
#pragma unroll
    for (int j = 0; j < 4; j++) {
        int i = tid + j * 128;
        y[i] = (v[j] - mean) * rstd * w[i] + bb[i];
    }
}

__global__ void permute_k(const float* __restrict__ retr, float* __restrict__ rp) {
    long long i = (long long)blockIdx.x * 256 + threadIdx.x;
    if (i < (long long)NL * NTOK * DIM) {
        int d = (int)(i & (DIM - 1));
        long long r = i >> 9;
        int n = (int)(r & (NTOK - 1));
        int l = (int)(r >> 11);
        rp[((long long)n * NL + l) * DIM + d] = retr[i];
    }
}

__global__ void zero_k(float* __restrict__ p, long long n) {
    long long i = (long long)blockIdx.x * 256 + threadIdx.x;
    if (i < n) p[i] = 0.f;
}

__global__ void gate_dot_k(const float* __restrict__ outs, const float* __restrict__ gg,
                           float* __restrict__ glog) {
    int e = blockIdx.x;
    long long chunk = (long long)ND_ELEMS / gridDim.y;
    long long base = (long long)e * ND_ELEMS + (long long)blockIdx.y * chunk;
    float acc = 0.f;
    for (long long i = threadIdx.x; i < chunk; i += blockDim.x) {
        long long idx = base + i;
        acc += outs[idx] * gg[idx & (DIM - 1)];
    }
    acc = warpReduceSum(acc);
    __shared__ float sh[8];
    int lane = threadIdx.x & 31, wid = threadIdx.x >> 5;
    if (lane == 0) sh[wid] = acc;
    __syncthreads();
    if (threadIdx.x == 0) {
        float x = 0;
        for (int q = 0; q < 8; q++) x += sh[q];
        atomicAdd(&glog[e], x);
    }
}

__global__ void gate_softmax_k(const float* __restrict__ glog, float* __restrict__ gw) {
    if (threadIdx.x == 0) {
        float l[EXP], m = -1e30f;
        for (int e = 0; e < EXP; e++) {
            l[e] = fminf(fmaxf(glog[e] / (float)NTOK, -10.f), 10.f);
            m = fmaxf(m, l[e]);
        }
        float s = 0.f;
        for (int e = 0; e < EXP; e++) { l[e] = expf(l[e] - m); s += l[e]; }
        for (int e = 0; e < EXP; e++) gw[e] = l[e] / s;
    }
}

__global__ void fuse_k(const float* __restrict__ outs, const float* __restrict__ gw,
                       float* __restrict__ fused) {
    long long i = (long long)blockIdx.x * 256 + threadIdx.x;
    if (i < (long long)ND_ELEMS) {
        float r = 0.f;
#pragma unroll
        for (int e = 0; e < EXP; e++) r += gw[e] * outs[(long long)e * ND_ELEMS + i];
        fused[i] = r;
    }
}

__global__ void memupd_k(const float* __restrict__ mem, const float* __restrict__ upd,
                         float* __restrict__ o) {
    long long i = (long long)blockIdx.x * 256 + threadIdx.x;
    if (i < (long long)LMD_ELEMS) {
        float u = 0.1f * upd[i];
        u = fminf(fmaxf(u, -0.1f), 0.1f);
        o[i] = 0.9f * mem[i] + u;
    }
}

// ---------------- host ----------------
#define SMEM_128 (2 * (128 + 128) * KST * 4)
#define SMEM_64  (2 * (128 + 64) * KST * 4)

extern "C" void kernel_launch(void* const* d_in, const int* in_sizes, int n_in,
                              void* d_out, int out_size) {
    const float* tokens   = (const float*)d_in[0];
    const float* memories = (const float*)d_in[1];
    const float* ipw      = (const float*)d_in[2];
    const float* ipb      = (const float*)d_in[3];
    const float* opw      = (const float*)d_in[4];
    const float* opb      = (const float*)d_in[5];
    const float* w1       = (const float*)d_in[6];
    const float* b1       = (const float*)d_in[7];
    const float* w2       = (const float*)d_in[8];
    const float* b2       = (const float*)d_in[9];
    const float* n1w      = (const float*)d_in[10];
    const float* n1b      = (const float*)d_in[11];
    const float* n2w      = (const float*)d_in[12];
    const float* n2b      = (const float*)d_in[13];
    const float* aggw     = (const float*)d_in[14];
    const float* aggb     = (const float*)d_in[15];
    const float* gg       = (const float*)d_in[16];

    float* out = (float*)d_out;
    float* out_fused = out;
    float* out_gw = out + ND_ELEMS;
    float* out_mem = out + ND_ELEMS + EXP;

    static float *p_xln = nullptr, *p_x = nullptr, *p_qkv = nullptr, *p_big = nullptr,
                 *p_sa = nullptr, *p_tmp = nullptr, *p_x1 = nullptr, *p_out = nullptr,
                 *p_retr = nullptr, *p_retrp = nullptr, *p_upd = nullptr, *p_glog = nullptr;
    if (!p_xln) {
        cudaGetSymbolAddress((void**)&p_xln, g_xln);
        cudaGetSymbolAddress((void**)&p_x, g_x);
        cudaGetSymbolAddress((void**)&p_qkv, g_qkv);
        cudaGetSymbolAddress((void**)&p_big, g_big);
        cudaGetSymbolAddress((void**)&p_sa, g_sa);
        cudaGetSymbolAddress((void**)&p_tmp, g_tmp);
        cudaGetSymbolAddress((void**)&p_x1, g_x1);
        cudaGetSymbolAddress((void**)&p_out, g_out);
        cudaGetSymbolAddress((void**)&p_retr, g_retr);
        cudaGetSymbolAddress((void**)&p_retrp, g_retrp);
        cudaGetSymbolAddress((void**)&p_upd, g_upd);
        cudaGetSymbolAddress((void**)&p_glog, g_glog);
        cudaFuncSetAttribute(gemmMMA<128, false, false>, cudaFuncAttributeMaxDynamicSharedMemorySize, SMEM_128);
        cudaFuncSetAttribute(gemmMMA<128, false, true>,  cudaFuncAttributeMaxDynamicSharedMemorySize, SMEM_128);
        cudaFuncSetAttribute(gemmMMA<128, true,  true>,  cudaFuncAttributeMaxDynamicSharedMemorySize, SMEM_128);
        cudaFuncSetAttribute(gemmMMA<64,  false, true>,  cudaFuncAttributeMaxDynamicSharedMemorySize, SMEM_64);
    }

    const float inv_sqrt_d = 1.0f / sqrtf((float)DIM);
    const float inv_sqrt_dh = 1.0f / sqrtf((float)DHEAD);

    zero_k<<<(LMD_ELEMS + 255) / 256, 256>>>(p_upd, LMD_ELEMS);
    zero_k<<<1, 256>>>(p_glog, EXP);
    ln_k<<<EXP * NTOK, 128>>>(tokens, p_xln);

    for (int e = 0; e < EXP; e++) {
        const float* Ax = p_xln + (long long)e * ND_ELEMS;
        float* xo = p_out + (long long)e * ND_ELEMS;

        // cross logits [2048, 6144] = clip(x @ ctx^T / sqrt(D), 10)
        gemmMMA<128, false, false><<<dim3(48, 16, 1), 256, SMEM_128>>>(
            Ax, p_xln, p_big, DIM, DIM, DIM, 3 * NTOK, 0, 0, 0,
            inv_sqrt_d, nullptr, nullptr, 0, 0, 10.f, 0, e * NTOK, NTOK);
        softmax_k<<<NTOK, 256, 3 * NTOK * 4>>>(p_big, 3 * NTOK);
        // x = probs @ ctx + x   (B stored [k, n], remapped k)
        gemmMMA<128, false, true><<<dim3(4, 16, 1), 256, SMEM_128>>>(
            p_big, p_xln, p_x, 3 * NTOK, 3 * NTOK, DIM, DIM, 0, 0, 0,
            1.f, nullptr, Ax, 0, DIM, 0.f, 0, e * NTOK, NTOK);
        // qkv [2048, 1536]
        gemmMMA<128, false, false><<<dim3(12, 16, 1), 256, SMEM_128>>>(
            p_x, ipw + (long long)e * 3 * DIM * DIM, p_qkv, DIM, DIM, DIM, 3 * DIM, 0, 0, 0,
            1.f, ipb + e * 3 * DIM, nullptr, 0, 0, 0.f, 0, 0, 0);
        // scores [h][2048, 2048] = q_h k_h^T / sqrt(dh)
        gemmMMA<128, false, false><<<dim3(16, 16, NH), 256, SMEM_128>>>(
            p_qkv, p_qkv + DIM, p_big, DHEAD, 3 * DIM, 3 * DIM, NTOK,
            DHEAD, DHEAD, (long long)NTOK * NTOK,
            inv_sqrt_dh, nullptr, nullptr, 0, 0, 0.f, 0, 0, 0);
        softmax_k<<<NH * NTOK, 256, NTOK * 4>>>(p_big, NTOK);
        // sa[:, h*64:] = probs_h @ v_h  (B stored [k, n] ld 1536)
        gemmMMA<64, false, true><<<dim3(1, 16, NH), 256, SMEM_64>>>(
            p_big, p_qkv + 2 * DIM, p_sa, NTOK, NTOK, 3 * DIM, DIM,
            (long long)NTOK * NTOK, DHEAD, DHEAD,
            1.f, nullptr, nullptr, 0, 0, 0.f, 0, 0, 0);
        // out_proj
        gemmMMA<128, false, false><<<dim3(4, 16, 1), 256, SMEM_128>>>(
            p_sa, opw + (long long)e * DIM * DIM, p_tmp, DIM, DIM, DIM, DIM, 0, 0, 0,
            1.f, opb + e * DIM, nullptr, 0, 0, 0.f, 0, 0, 0);
        ln_ra_k<<<NTOK, 128>>>(p_x, p_tmp, n1w + e * DIM, n1b + e * DIM, p_x1);
        // ff1 relu
        gemmMMA<128, false, false><<<dim3(16, 16, 1), 256, SMEM_128>>>(
            p_x1, w1 + (long long)e * FFD * DIM, p_tmp, DIM, DIM, DIM, FFD, 0, 0, 0,
            1.f, b1 + e * FFD, nullptr, 0, 0, 0.f, GFLAG_RELU, 0, 0);
        // ff2
        gemmMMA<128, false, false><<<dim3(4, 16, 1), 256, SMEM_128>>>(
            p_tmp, w2 + (long long)e * DIM * FFD, p_sa, FFD, FFD, FFD, DIM, 0, 0, 0,
            1.f, b2 + e * DIM, nullptr, 0, 0, 0.f, 0, 0, 0);
        ln_ra_k<<<NTOK, 128>>>(p_x1, p_sa, n2w + e * DIM, n2b + e * DIM, xo);
        // memory logits [l][2048, 4096]
        gemmMMA<128, false, false><<<dim3(32, 16, NL), 256, SMEM_128>>>(
            xo, memories, p_big, DIM, DIM, DIM, MEMSZ,
            0, (long long)MEMSZ * DIM, (long long)NTOK * MEMSZ,
            inv_sqrt_d, nullptr, nullptr, 0, 0, 10.f, 0, 0, 0);
        softmax_k<<<NL * NTOK, 256, MEMSZ * 4>>>(p_big, MEMSZ);
        // retr[l] = am[l] @ mem_l  (B stored [k, n] ld 512)
        gemmMMA<128, false, true><<<dim3(4, 16, NL), 256, SMEM_128>>>(
            p_big, memories, p_retr, MEMSZ, MEMSZ, DIM, DIM,
            (long long)NTOK * MEMSZ, (long long)MEMSZ * DIM, (long long)NTOK * DIM,
            1.f, nullptr, nullptr, 0, 0, 0.f, 0, 0, 0);
        // upd[l] += clip(am[l]^T @ xout, 1)  (A stored [k, m] ld 4096, B stored [k, n] ld 512)
        gemmMMA<128, true, true><<<dim3(4, 32, NL), 256, SMEM_128>>>(
            p_big, xo, p_upd, NTOK, MEMSZ, DIM, DIM,
            (long long)NTOK * MEMSZ, 0, (long long)MEMSZ * DIM,
            1.f, nullptr, nullptr, 0, 0, 1.f, GFLAG_ACCUM, 0, 0);
        permute_k<<<(NL * ND_ELEMS + 255) / 256, 256>>>(p_retr, p_retrp);
        // outs[e] = xout + retrp @ aggw^T + aggb
        gemmMMA<128, false, false><<<dim3(4, 16, 1), 256, SMEM_128>>>(
            p_retrp, aggw, xo, NL * DIM, NL * DIM, NL * DIM, DIM, 0, 0, 0,
            1.f, aggb, xo, 0, DIM, 0.f, 0, 0, 0);
    }

    dim3 ggrid(EXP, 16);
    gate_dot_k<<<ggrid, 256>>>(p_out, gg, p_glog);
    gate_softmax_k<<<1, 32>>>(p_glog, out_gw);
    fuse_k<<<(ND_ELEMS + 255) / 256, 256>>>(p_out, out_gw, out_fused);
    memupd_k<<<(LMD_ELEMS + 255) / 256, 256>>>(memories, p_upd, out_mem);

    (void)in_sizes; (void)n_in; (void)out_size;
}

// round 4
// speedup vs baseline: 4.1310x; 1.2588x over previous
#include <cuda_runtime.h>
#include <math.h>
#include <stdint.h>

#define EXP 4
#define NTOK 2048
#define DIM 512
#define NH 8
#define DHEAD 64
#define FFD 2048
#define NL 4
#define MEMSZ 4096

#define ND_ELEMS (NTOK * DIM)
#define LMD_ELEMS (NL * MEMSZ * DIM)

#define GFLAG_RELU 1
#define GFLAG_ACCUM 2

// ---------------- scratch ----------------
__device__ float g_xln[EXP * NTOK * DIM];
__device__ float g_x[NTOK * DIM];
__device__ float g_qkv[NTOK * 3 * DIM];
__device__ float g_big[(size_t)NH * NTOK * NTOK];
__device__ float g_sa[NTOK * DIM];
__device__ float g_tmp[NTOK * FFD];
__device__ float g_x1[NTOK * DIM];
__device__ float g_out[EXP * NTOK * DIM];
__device__ float g_retr[NL * NTOK * DIM];
__device__ float g_retrp[NTOK * NL * DIM];
__device__ float g_upd[NL * MEMSZ * DIM];
__device__ float g_glog[EXP];

// ---------------- helpers ----------------
__device__ __forceinline__ uint32_t tf(float x) {
    uint32_t u; asm("cvt.rna.tf32.f32 %0, %1;" : "=r"(u) : "f"(x)); return u;
}
__device__ __forceinline__ void mma8(float* c, const uint32_t* a, const uint32_t* b) {
    asm volatile(
        "mma.sync.aligned.m16n8k8.row.col.f32.tf32.tf32.f32 "
        "{%0,%1,%2,%3}, {%4,%5,%6,%7}, {%8,%9}, {%0,%1,%2,%3};"
        : "+f"(c[0]), "+f"(c[1]), "+f"(c[2]), "+f"(c[3])
        : "r"(a[0]), "r"(a[1]), "r"(a[2]), "r"(a[3]), "r"(b[0]), "r"(b[1]));
}
__device__ __forceinline__ void cpa16(uint32_t s, const float* g) {
    asm volatile("cp.async.cg.shared.global [%0], [%1], 16;" :: "r"(s), "l"(g));
}

// ---------------- cp.async tf32 mma GEMM ----------------
// C[M,Nc] = alpha*op(A)*op(B) (+bias)(relu)(clip)(+resid)(accum)
// ATR: A stored [K,M] (M contig, MT must be 128). BTR: B stored [K,Nc] (Nc contig).
// remap (rl>0): for !BTR remaps B n-rows; for BTR remaps B k-rows (ctx skip).
template <int MT, int NT, bool ATR, bool BTR>
__global__ void __launch_bounds__(256, 1) gemmCP(
    const float* __restrict__ A, const float* __restrict__ B, float* __restrict__ C,
    int K, int lda, int ldb, int ldc,
    long long aB, long long bB, long long cB,
    float alpha, const float* __restrict__ bias,
    const float* __restrict__ resid, long long residB, int residLd,
    float clipVal, int flags, int rs, int rl)
{
    static_assert(!ATR || MT == 128, "ATR requires MT=128");
    constexpr int KC = 16;
    constexpr int AST = 20;        // K-contig row stride (floats)
    constexpr int MST = 136;       // A-transposed row stride
    constexpr int NST = NT + 8;    // B-transposed row stride
    constexpr int ASZ = ATR ? KC * MST : MT * AST;
    constexpr int BSZ = BTR ? KC * NST : NT * AST;
    constexpr int STG = ASZ + BSZ;
    constexpr int MI = MT / 32;
    constexpr int NB = NT / 32;

    extern __shared__ float sm[];
    uint32_t smb = (uint32_t)__cvta_generic_to_shared(sm);

    const int t = threadIdx.x, l = t & 31, w = t >> 5;
    const int bz = blockIdx.z;
    A += aB * bz; B += bB * bz; C += cB * bz;
    const int m0 = blockIdx.y * MT, n0 = blockIdx.x * NT;
    const int wm0 = (w >> 2) * (MT / 2), wn0 = (w & 3) * (NT / 4);

    float acc[MI][NB][4];
#pragma unroll
    for (int a = 0; a < MI; a++)
#pragma unroll
        for (int b = 0; b < NB; b++)
#pragma unroll
            for (int c = 0; c < 4; c++) acc[a][b][c] = 0.f;

    const int nK = K / KC;

    auto issue = [&](int s, int k0) {
        uint32_t ab = smb + (uint32_t)(s * STG * 4);
        uint32_t bb = ab + ASZ * 4;
        if (!ATR) {
            constexpr int ACH = MT * 4;
#pragma unroll
            for (int c0 = 0; c0 < ACH; c0 += 256) {
                int c = c0 + t;
                int row = c >> 2, kq = c & 3;
                cpa16(ab + (uint32_t)(row * AST + kq * 4) * 4,
                      &A[(long long)(m0 + row) * lda + k0 + kq * 4]);
            }
        } else {
#pragma unroll
            for (int c0 = 0; c0 < 512; c0 += 256) {
                int c = c0 + t;
                int kr = c >> 5, mq = c & 31;
                cpa16(ab + (uint32_t)(kr * MST + mq * 4) * 4,
                      &A[(long long)(k0 + kr) * lda + m0 + mq * 4]);
            }
        }
        if (!BTR) {
            constexpr int BCH = NT * 4;
#pragma unroll
            for (int c0 = 0; c0 < BCH; c0 += 256) {
                int c = c0 + t;
                int row = c >> 2, kq = c & 3;
                int n = n0 + row;
                if (rl && n >= rs) n += rl;
                cpa16(bb + (uint32_t)(row * AST + kq * 4) * 4,
                      &B[(long long)n * ldb + k0 + kq * 4]);
            }
        } else {
            constexpr int NQ = NT / 4;
            constexpr int SH = (NT == 128) ? 5 : 4;
            constexpr int BCH = KC * NQ;
#pragma unroll
            for (int c0 = 0; c0 < BCH; c0 += 256) {
                int c = c0 + t;
                int kr = c >> SH, nq = c & (NQ - 1);
                int g = k0 + kr;
                if (rl && g >= rs) g += rl;
                cpa16(bb + (uint32_t)(kr * NST + nq * 4) * 4,
                      &B[(long long)g * ldb + n0 + nq * 4]);
            }
        }
        asm volatile("cp.async.commit_group;" ::: "memory");
    };

    // prologue: 3 stages in flight (all our K >= 64 -> nK >= 4)
    issue(0, 0);
    issue(1, KC);
    issue(2, 2 * KC);

    for (int i = 0; i < nK; i++) {
        asm volatile("cp.async.wait_group 2;" ::: "memory");
        __syncthreads();
        if (i + 3 < nK) issue((i + 3) & 3, (i + 3) * KC);

        const float* Ab = sm + (i & 3) * STG;
        const float* Bb = Ab + ASZ;
#pragma unroll
        for (int kk = 0; kk < 2; kk++) {
            const int kc = kk * 8;
            uint32_t af[MI][4], bf[NB][2];
#pragma unroll
            for (int mi = 0; mi < MI; mi++) {
                if (!ATR) {
                    const float* ap = &Ab[(wm0 + mi * 16 + (l >> 2)) * AST + kc + (l & 3)];
                    af[mi][0] = tf(ap[0]);
                    af[mi][1] = tf(ap[8 * AST]);
                    af[mi][2] = tf(ap[4]);
                    af[mi][3] = tf(ap[8 * AST + 4]);
                } else {
                    const float* ap = &Ab[(kc + (l & 3)) * MST + wm0 + mi * 16 + (l >> 2)];
                    af[mi][0] = tf(ap[0]);
                    af[mi][1] = tf(ap[8]);
                    af[mi][2] = tf(ap[4 * MST]);
                    af[mi][3] = tf(ap[4 * MST + 8]);
                }
            }
#pragma unroll
            for (int ni = 0; ni < NB; ni++) {
                if (!BTR) {
                    const float* bp = &Bb[(wn0 + ni * 8 + (l >> 2)) * AST + kc + (l & 3)];
                    bf[ni][0] = tf(bp[0]);
                    bf[ni][1] = tf(bp[4]);
                } else {
                    const float* bp = &Bb[(kc + (l & 3)) * NST + wn0 + ni * 8 + (l >> 2)];
                    bf[ni][0] = tf(bp[0]);
                    bf[ni][1] = tf(bp[4 * NST]);
                }
            }
#pragma unroll
            for (int mi = 0; mi < MI; mi++)
#pragma unroll
                for (int ni = 0; ni < NB; ni++) mma8(acc[mi][ni], af[mi], bf[ni]);
        }
    }

    // epilogue: regs -> global
#pragma unroll
    for (int mi = 0; mi < MI; mi++) {
        int row0 = m0 + wm0 + mi * 16 + (l >> 2);
#pragma unroll
        for (int ni = 0; ni < NB; ni++) {
            int col = n0 + wn0 + ni * 8 + (l & 3) * 2;
#pragma unroll
            for (int h = 0; h < 2; h++) {
                int row = row0 + h * 8;
                float vx = alpha * acc[mi][ni][h * 2];
                float vy = alpha * acc[mi][ni][h * 2 + 1];
                if (bias) { vx += bias[col]; vy += bias[col + 1]; }
                if (flags & GFLAG_RELU) { vx = fmaxf(vx, 0.f); vy = fmaxf(vy, 0.f); }
                if (clipVal > 0.f) {
                    vx = fminf(fmaxf(vx, -clipVal), clipVal);
                    vy = fminf(fmaxf(vy, -clipVal), clipVal);
                }
                if (resid) {
                    float2 rv = *(const float2*)&resid[residB * bz + (long long)row * residLd + col];
                    vx += rv.x; vy += rv.y;
                }
                float2* cp = (float2*)&C[(long long)row * ldc + col];
                if (flags & GFLAG_ACCUM) {
                    float2 o = *cp;
                    vx += o.x; vy += o.y;
                }
                *cp = make_float2(vx, vy);
            }
        }
    }
}

// ---------------- reductions ----------------
__device__ __forceinline__ float warpReduceSum(float v) {
#pragma unroll
    for (int o = 16; o; o >>= 1) v += __shfl_xor_sync(0xffffffffu, v, o);
    return v;
}
__device__ __forceinline__ float warpReduceMax(float v) {
#pragma unroll
    for (int o = 16; o; o >>= 1) v = fmaxf(v, __shfl_xor_sync(0xffffffffu, v, o));
    return v;
}

// ---------------- smem-cached row softmax ----------------
__global__ void softmax_k(float* __restrict__ p, int cols) {
    extern __shared__ float sbuf[];
    float* row = p + (long long)blockIdx.x * cols;
    __shared__ float sh[8];
    __shared__ float sb;
    int tid = threadIdx.x, lane = tid & 31, wid = tid >> 5;
    float m = -1e30f;
    for (int i = tid; i < cols; i += 256) { float v = row[i]; sbuf[i] = v; m = fmaxf(m, v); }
    m = warpReduceMax(m);
    if (lane == 0) sh[wid] = m;
    __syncthreads();
    if (tid == 0) { float x = sh[0]; for (int q = 1; q < 8; q++) x = fmaxf(x, sh[q]); sb = x; }
    __syncthreads();
    m = sb;
    float s = 0.f;
    for (int i = tid; i < cols; i += 256) { float v = expf(sbuf[i] - m); sbuf[i] = v; s += v; }
    s = warpReduceSum(s);
    if (lane == 0) sh[wid] = s;
    __syncthreads();
    if (tid == 0) { float x = 0; for (int q = 0; q < 8; q++) x += sh[q]; sb = 1.f / x; }
    __syncthreads();
    float inv = sb;
    for (int i = tid; i < cols; i += 256) row[i] = sbuf[i] * inv;
}

// ---------------- LayerNorm ----------------
__global__ void ln_k(const float* __restrict__ src, float* __restrict__ dst) {
    long long row = blockIdx.x;
    const float* x = src + row * DIM;
    float* y = dst + row * DIM;
    int tid = threadIdx.x, lane = tid & 31, wid = tid >> 5;
    float v[4], s = 0.f, s2 = 0.f;
#pragma unroll
    for (int j = 0; j < 4; j++) { v[j] = x[tid + j * 128]; s += v[j]; s2 += v[j] * v[j]; }
    s = warpReduceSum(s); s2 = warpReduceSum(s2);
    __shared__ float sh[2][4]; __shared__ float mv[2];
    if (lane == 0) { sh[0][wid] = s; sh[1][wid] = s2; }
    __syncthreads();
    if (tid == 0) {
        float a = sh[0][0] + sh[0][1] + sh[0][2] + sh[0][3];
        float b = sh[1][0] + sh[1][1] + sh[1][2] + sh[1][3];
        float mean = a / DIM;
        mv[0] = mean; mv[1] = rsqrtf(b / DIM - mean * mean + 1e-5f);
    }
    __syncthreads();
    float mean = mv[0], rstd = mv[1];
#pragma unroll
    for (int j = 0; j < 4; j++) y[tid + j * 128] = (v[j] - mean) * rstd;
}

__global__ void ln_ra_k(const float* __restrict__ a, const float* __restrict__ b,
                        const float* __restrict__ w, const float* __restrict__ bb,
                        float* __restrict__ dst) {
    long long row = blockIdx.x;
    const float* xa = a + row * DIM;
    const float* xb = b + row * DIM;
    float* y = dst + row * DIM;
    int tid = threadIdx.x, lane = tid & 31, wid = tid >> 5;
    float v[4], s = 0.f, s2 = 0.f;
#pragma unroll
    for (int j = 0; j < 4; j++) {
        int i = tid + j * 128;
        v[j] = xa[i] + xb[i]; s += v[j]; s2 += v[j] * v[j];
    }
    s = warpReduceSum(s); s2 = warpReduceSum(s2);
    __shared__ float sh[2][4]; __shared__ float mv[2];
    if (lane == 0) { sh[0][wid] = s; sh[1][wid] = s2; }
    __syncthreads();
    if (tid == 0) {
        float p = sh[0][0] + sh[0][1] + sh[0][2] + sh[0][3];
        float q = sh[1][0] + sh[1][1] + sh[1][2] + sh[1][3];
        float mean = p / DIM;
        mv[0] = mean; mv[1] = rsqrtf(q / DIM - mean * mean + 1e-5f);
    }
    __syncthreads();
    float mean = mv[0], rstd = mv[1];
#pragma unroll
    for (int j = 0; j < 4; j++) {
        int i = tid + j * 128;
        y[i] = (v[j] - mean) * rstd * w[i] + bb[i];
    }
}

__global__ void permute_k(const float* __restrict__ retr, float* __restrict__ rp) {
    long long i = (long long)blockIdx.x * 256 + threadIdx.x;
    if (i < (long long)NL * NTOK * DIM) {
        int d = (int)(i & (DIM - 1));
        long long r = i >> 9;
        int n = (int)(r & (NTOK - 1));
        int l = (int)(r >> 11);
        rp[((long long)n * NL + l) * DIM + d] = retr[i];
    }
}

__global__ void zero_k(float* __restrict__ p, long long n) {
    long long i = (long long)blockIdx.x * 256 + threadIdx.x;
    if (i < n) p[i] = 0.f;
}

__global__ void gate_dot_k(const float* __restrict__ outs, const float* __restrict__ gg,
                           float* __restrict__ glog) {
    int e = blockIdx.x;
    long long chunk = (long long)ND_ELEMS / gridDim.y;
    long long base = (long long)e * ND_ELEMS + (long long)blockIdx.y * chunk;
    float acc = 0.f;
    for (long long i = threadIdx.x; i < chunk; i += blockDim.x) {
        long long idx = base + i;
        acc += outs[idx] * gg[idx & (DIM - 1)];
    }
    acc = warpReduceSum(acc);
    __shared__ float sh[8];
    int lane = threadIdx.x & 31, wid = threadIdx.x >> 5;
    if (lane == 0) sh[wid] = acc;
    __syncthreads();
    if (threadIdx.x == 0) {
        float x = 0;
        for (int q = 0; q < 8; q++) x += sh[q];
        atomicAdd(&glog[e], x);
    }
}

__global__ void gate_softmax_k(const float* __restrict__ glog, float* __restrict__ gw) {
    if (threadIdx.x == 0) {
        float l[EXP], m = -1e30f;
        for (int e = 0; e < EXP; e++) {
            l[e] = fminf(fmaxf(glog[e] / (float)NTOK, -10.f), 10.f);
            m = fmaxf(m, l[e]);
        }
        float s = 0.f;
        for (int e = 0; e < EXP; e++) { l[e] = expf(l[e] - m); s += l[e]; }
        for (int e = 0; e < EXP; e++) gw[e] = l[e] / s;
    }
}

__global__ void fuse_k(const float* __restrict__ outs, const float* __restrict__ gw,
                       float* __restrict__ fused) {
    long long i = (long long)blockIdx.x * 256 + threadIdx.x;
    if (i < (long long)ND_ELEMS) {
        float r = 0.f;
#pragma unroll
        for (int e = 0; e < EXP; e++) r += gw[e] * outs[(long long)e * ND_ELEMS + i];
        fused[i] = r;
    }
}

__global__ void memupd_k(const float* __restrict__ mem, const float* __restrict__ upd,
                         float* __restrict__ o) {
    long long i = (long long)blockIdx.x * 256 + threadIdx.x;
    if (i < (long long)LMD_ELEMS) {
        float u = 0.1f * upd[i];
        u = fminf(fmaxf(u, -0.1f), 0.1f);
        o[i] = 0.9f * mem[i] + u;
    }
}

// ---------------- host ----------------
static constexpr int stgFl(int MT, int NT, bool ATR, bool BTR) {
    return (ATR ? 16 * 136 : MT * 20) + (BTR ? 16 * (NT + 8) : NT * 20);
}
#define SMEMB(MT, NT, ATR, BTR) (4 * stgFl(MT, NT, ATR, BTR) * 4)

extern "C" void kernel_launch(void* const* d_in, const int* in_sizes, int n_in,
                              void* d_out, int out_size) {
    const float* tokens   = (const float*)d_in[0];
    const float* memories = (const float*)d_in[1];
    const float* ipw      = (const float*)d_in[2];
    const float* ipb      = (const float*)d_in[3];
    const float* opw      = (const float*)d_in[4];
    const float* opb      = (const float*)d_in[5];
    const float* w1       = (const float*)d_in[6];
    const float* b1       = (const float*)d_in[7];
    const float* w2       = (const float*)d_in[8];
    const float* b2       = (const float*)d_in[9];
    const float* n1w      = (const float*)d_in[10];
    const float* n1b      = (const float*)d_in[11];
    const float* n2w      = (const float*)d_in[12];
    const float* n2b      = (const float*)d_in[13];
    const float* aggw     = (const float*)d_in[14];
    const float* aggb     = (const float*)d_in[15];
    const float* gg       = (const float*)d_in[16];

    float* out = (float*)d_out;
    float* out_fused = out;
    float* out_gw = out + ND_ELEMS;
    float* out_mem = out + ND_ELEMS + EXP;

    static float *p_xln = nullptr, *p_x = nullptr, *p_qkv = nullptr, *p_big = nullptr,
                 *p_sa = nullptr, *p_tmp = nullptr, *p_x1 = nullptr, *p_out = nullptr,
                 *p_retr = nullptr, *p_retrp = nullptr, *p_upd = nullptr, *p_glog = nullptr;
    if (!p_xln) {
        cudaGetSymbolAddress((void**)&p_xln, g_xln);
        cudaGetSymbolAddress((void**)&p_x, g_x);
        cudaGetSymbolAddress((void**)&p_qkv, g_qkv);
        cudaGetSymbolAddress((void**)&p_big, g_big);
        cudaGetSymbolAddress((void**)&p_sa, g_sa);
        cudaGetSymbolAddress((void**)&p_tmp, g_tmp);
        cudaGetSymbolAddress((void**)&p_x1, g_x1);
        cudaGetSymbolAddress((void**)&p_out, g_out);
        cudaGetSymbolAddress((void**)&p_retr, g_retr);
        cudaGetSymbolAddress((void**)&p_retrp, g_retrp);
        cudaGetSymbolAddress((void**)&p_upd, g_upd);
        cudaGetSymbolAddress((void**)&p_glog, g_glog);
        cudaFuncSetAttribute(gemmCP<128, 128, false, false>, cudaFuncAttributeMaxDynamicSharedMemorySize, SMEMB(128, 128, false, false));
        cudaFuncSetAttribute(gemmCP<64, 128, false, false>,  cudaFuncAttributeMaxDynamicSharedMemorySize, SMEMB(64, 128, false, false));
        cudaFuncSetAttribute(gemmCP<128, 128, false, true>,  cudaFuncAttributeMaxDynamicSharedMemorySize, SMEMB(128, 128, false, true));
        cudaFuncSetAttribute(gemmCP<64, 128, false, true>,   cudaFuncAttributeMaxDynamicSharedMemorySize, SMEMB(64, 128, false, true));
        cudaFuncSetAttribute(gemmCP<128, 64, false, true>,   cudaFuncAttributeMaxDynamicSharedMemorySize, SMEMB(128, 64, false, true));
        cudaFuncSetAttribute(gemmCP<128, 128, true, true>,   cudaFuncAttributeMaxDynamicSharedMemorySize, SMEMB(128, 128, true, true));
    }

    const float inv_sqrt_d = 1.0f / sqrtf((float)DIM);
    const float inv_sqrt_dh = 1.0f / sqrtf((float)DHEAD);

    zero_k<<<(LMD_ELEMS + 255) / 256, 256>>>(p_upd, LMD_ELEMS);
    zero_k<<<1, 256>>>(p_glog, EXP);
    ln_k<<<EXP * NTOK, 128>>>(tokens, p_xln);

    for (int e = 0; e < EXP; e++) {
        const float* Ax = p_xln + (long long)e * ND_ELEMS;
        float* xo = p_out + (long long)e * ND_ELEMS;

        // cross logits [2048, 6144] = clip(x @ ctx^T / sqrt(D), 10)
        gemmCP<128, 128, false, false><<<dim3(48, 16, 1), 256, SMEMB(128, 128, false, false)>>>(
            Ax, p_xln, p_big, DIM, DIM, DIM, 3 * NTOK, 0, 0, 0,
            inv_sqrt_d, nullptr, nullptr, 0, 0, 10.f, 0, e * NTOK, NTOK);
        softmax_k<<<NTOK, 256, 3 * NTOK * 4>>>(p_big, 3 * NTOK);
        // x = probs @ ctx + x   (B stored [k, n], remap on k)
        gemmCP<64, 128, false, true><<<dim3(4, 32, 1), 256, SMEMB(64, 128, false, true)>>>(
            p_big, p_xln, p_x, 3 * NTOK, 3 * NTOK, DIM, DIM, 0, 0, 0,
            1.f, nullptr, Ax, 0, DIM, 0.f, 0, e * NTOK, NTOK);
        // qkv [2048, 1536]
        gemmCP<64, 128, false, false><<<dim3(12, 32, 1), 256, SMEMB(64, 128, false, false)>>>(
            p_x, ipw + (long long)e * 3 * DIM * DIM, p_qkv, DIM, DIM, DIM, 3 * DIM, 0, 0, 0,
            1.f, ipb + e * 3 * DIM, nullptr, 0, 0, 0.f, 0, 0, 0);
        // scores [h][2048, 2048] = q_h k_h^T / sqrt(dh)
        gemmCP<128, 128, false, false><<<dim3(16, 16, NH), 256, SMEMB(128, 128, false, false)>>>(
            p_qkv, p_qkv + DIM, p_big, DHEAD, 3 * DIM, 3 * DIM, NTOK,
            DHEAD, DHEAD, (long long)NTOK * NTOK,
            inv_sqrt_dh, nullptr, nullptr, 0, 0, 0.f, 0, 0, 0);
        softmax_k<<<NH * NTOK, 256, NTOK * 4>>>(p_big, NTOK);
        // sa[:, h*64:] = probs_h @ v_h  (B stored [k, n] ld 1536)
        gemmCP<128, 64, false, true><<<dim3(1, 16, NH), 256, SMEMB(128, 64, false, true)>>>(
            p_big, p_qkv + 2 * DIM, p_sa, NTOK, NTOK, 3 * DIM, DIM,
            (long long)NTOK * NTOK, DHEAD, DHEAD,
            1.f, nullptr, nullptr, 0, 0, 0.f, 0, 0, 0);
        // out_proj
        gemmCP<64, 128, false, false><<<dim3(4, 32, 1), 256, SMEMB(64, 128, false, false)>>>(
            p_sa, opw + (long long)e * DIM * DIM, p_tmp, DIM, DIM, DIM, DIM, 0, 0, 0,
            1.f, opb + e * DIM, nullptr, 0, 0, 0.f, 0, 0, 0);
        ln_ra_k<<<NTOK, 128>>>(p_x, p_tmp, n1w + e * DIM, n1b + e * DIM, p_x1);
        // ff1 relu
        gemmCP<128, 128, false, false><<<dim3(16, 16, 1), 256, SMEMB(128, 128, false, false)>>>(
            p_x1, w1 + (long long)e * FFD * DIM, p_tmp, DIM, DIM, DIM, FFD, 0, 0, 0,
            1.f, b1 + e * FFD, nullptr, 0, 0, 0.f, GFLAG_RELU, 0, 0);
        // ff2
        gemmCP<64, 128, false, false><<<dim3(4, 32, 1), 256, SMEMB(64, 128, false, false)>>>(
            p_tmp, w2 + (long long)e * DIM * FFD, p_sa, FFD, FFD, FFD, DIM, 0, 0, 0,
            1.f, b2 + e * DIM, nullptr, 0, 0, 0.f, 0, 0, 0);
        ln_ra_k<<<NTOK, 128>>>(p_x1, p_sa, n2w + e * DIM, n2b + e * DIM, xo);
        // memory logits [l][2048, 4096]
        gemmCP<128, 128, false, false><<<dim3(32, 16, NL), 256, SMEMB(128, 128, false, false)>>>(
            xo, memories, p_big, DIM, DIM, DIM, MEMSZ,
            0, (long long)MEMSZ * DIM, (long long)NTOK * MEMSZ,
            inv_sqrt_d, nullptr, nullptr, 0, 0, 10.f, 0, 0, 0);
        softmax_k<<<NL * NTOK, 256, MEMSZ * 4>>>(p_big, MEMSZ);
        // retr[l] = am[l] @ mem_l  (B stored [k, n] ld 512)
        gemmCP<128, 128, false, true><<<dim3(4, 16, NL), 256, SMEMB(128, 128, false, true)>>>(
            p_big, memories, p_retr, MEMSZ, MEMSZ, DIM, DIM,
            (long long)NTOK * MEMSZ, (long long)MEMSZ * DIM, (long long)NTOK * DIM,
            1.f, nullptr, nullptr, 0, 0, 0.f, 0, 0, 0);
        // upd[l] += clip(am[l]^T @ xout, 1)  (A stored [k, m] ld 4096, B stored [k, n] ld 512)
        gemmCP<128, 128, true, true><<<dim3(4, 32, NL), 256, SMEMB(128, 128, true, true)>>>(
            p_big, xo, p_upd, NTOK, MEMSZ, DIM, DIM,
            (long long)NTOK * MEMSZ, 0, (long long)MEMSZ * DIM,
            1.f, nullptr, nullptr, 0, 0, 1.f, GFLAG_ACCUM, 0, 0);
        permute_k<<<(NL * ND_ELEMS + 255) / 256, 256>>>(p_retr, p_retrp);
        // outs[e] = xout + retrp @ aggw^T + aggb
        gemmCP<64, 128, false, false><<<dim3(4, 32, 1), 256, SMEMB(64, 128, false, false)>>>(
            p_retrp, aggw, xo, NL * DIM, NL * DIM, NL * DIM, DIM, 0, 0, 0,
            1.f, aggb, xo, 0, DIM, 0.f, 0, 0, 0);
    }

    dim3 ggrid(EXP, 16);
    gate_dot_k<<<ggrid, 256>>>(p_out, gg, p_glog);
    gate_softmax_k<<<1, 32>>>(p_glog, out_gw);
    fuse_k<<<(ND_ELEMS + 255) / 256, 256>>>(p_out, out_gw, out_fused);
    memupd_k<<<(LMD_ELEMS + 255) / 256, 256>>>(memories, p_upd, out_mem);

    (void)in_sizes; (void)n_in; (void)out_size;
}

// round 5
// speedup vs baseline: 4.4083x; 1.0671x over previous
#include <cuda_runtime.h>
#include <math.h>
#include <stdint.h>

#define EXP 4
#define NTOK 2048
#define DIM 512
#define NH 8
#define DHEAD 64
#define FFD 2048
#define NL 4
#define MEMSZ 4096

#define ND_ELEMS (NTOK * DIM)
#define LMD_ELEMS (NL * MEMSZ * DIM)

#define GFLAG_RELU 1
#define GFLAG_ACCUM 2

// ---------------- scratch ----------------
__device__ float g_xln[EXP * NTOK * DIM];
__device__ float g_x[NTOK * DIM];
__device__ float g_qkv[NTOK * 3 * DIM];
__device__ float g_big[(size_t)NH * NTOK * NTOK];
__device__ float g_sa[NTOK * DIM];
__device__ float g_tmp[NTOK * FFD];
__device__ float g_x1[NTOK * DIM];
__device__ float g_out[EXP * NTOK * DIM];
__device__ float g_retr[NL * NTOK * DIM];
__device__ float g_retrp[NTOK * NL * DIM];
__device__ float g_upd[NL * MEMSZ * DIM];
__device__ float g_glog[EXP];

// ---------------- helpers ----------------
__device__ __forceinline__ uint32_t tf(float x) {
    uint32_t u; asm("cvt.rna.tf32.f32 %0, %1;" : "=r"(u) : "f"(x)); return u;
}
__device__ __forceinline__ void mma8(float* c, const uint32_t* a, const uint32_t* b) {
    asm volatile(
        "mma.sync.aligned.m16n8k8.row.col.f32.tf32.tf32.f32 "
        "{%0,%1,%2,%3}, {%4,%5,%6,%7}, {%8,%9}, {%0,%1,%2,%3};"
        : "+f"(c[0]), "+f"(c[1]), "+f"(c[2]), "+f"(c[3])
        : "r"(a[0]), "r"(a[1]), "r"(a[2]), "r"(a[3]), "r"(b[0]), "r"(b[1]));
}
__device__ __forceinline__ void cpa16(uint32_t s, const float* g) {
    asm volatile("cp.async.cg.shared.global [%0], [%1], 16;" :: "r"(s), "l"(g));
}

// ---------------- cp.async tf32 mma GEMM, MT=64 tiles, 2 CTAs/SM ----------------
// C[M,Nc] = alpha*op(A)*op(B) (+bias)(relu)(clip)(+resid)(accum)
// ATR: A stored [K,M] (M contig). BTR: B stored [K,Nc] (Nc contig). Else K-contig rows.
// remap (rl>0): for !BTR remaps B n-rows; for BTR remaps B k-rows (ctx skip).
template <int MT, int NT, bool ATR, bool BTR>
__global__ void __launch_bounds__(256, 2) gemmCP(
    const float* __restrict__ A, const float* __restrict__ B, float* __restrict__ C,
    int K, int lda, int ldb, int ldc,
    long long aB, long long bB, long long cB,
    float alpha, const float* __restrict__ bias,
    const float* __restrict__ resid, long long residB, int residLd,
    float clipVal, int flags, int rs, int rl)
{
    constexpr int KC = 16;
    constexpr int AST = 20;            // K-contig row stride (floats)
    constexpr int MST = MT + 8;        // A-transposed row stride
    constexpr int NST = NT + 8;        // B-transposed row stride
    constexpr int ASZ = ATR ? KC * MST : MT * AST;
    constexpr int BSZ = BTR ? KC * NST : NT * AST;
    constexpr int STG = ASZ + BSZ;
    constexpr int MI = MT / 32;        // m16 frags per warp (warp m-extent MT/2)
    constexpr int NB = NT / 32;        // n8 frags per warp (warp n-extent NT/4)

    extern __shared__ float sm[];
    uint32_t smb = (uint32_t)__cvta_generic_to_shared(sm);

    const int t = threadIdx.x, l = t & 31, w = t >> 5;
    const int bz = blockIdx.z;
    A += aB * bz; B += bB * bz; C += cB * bz;
    const int m0 = blockIdx.y * MT, n0 = blockIdx.x * NT;
    const int wm0 = (w >> 2) * (MT / 2), wn0 = (w & 3) * (NT / 4);

    float acc[MI][NB][4];
#pragma unroll
    for (int a = 0; a < MI; a++)
#pragma unroll
        for (int b = 0; b < NB; b++)
#pragma unroll
            for (int c = 0; c < 4; c++) acc[a][b][c] = 0.f;

    const int nK = K / KC;

    auto issue = [&](int s, int k0) {
        uint32_t ab = smb + (uint32_t)(s * STG * 4);
        uint32_t bb = ab + ASZ * 4;
        if (!ATR) {
            constexpr int ACH = MT * 4;
#pragma unroll
            for (int c0 = 0; c0 < ACH; c0 += 256) {
                int c = c0 + t;
                int row = c >> 2, kq = c & 3;
                cpa16(ab + (uint32_t)(row * AST + kq * 4) * 4,
                      &A[(long long)(m0 + row) * lda + k0 + kq * 4]);
            }
        } else {
            constexpr int AQ = MT / 4;
            constexpr int ASH = (MT == 128) ? 5 : 4;
            constexpr int ACH = KC * AQ;
#pragma unroll
            for (int c0 = 0; c0 < ACH; c0 += 256) {
                int c = c0 + t;
                int kr = c >> ASH, mq = c & (AQ - 1);
                cpa16(ab + (uint32_t)(kr * MST + mq * 4) * 4,
                      &A[(long long)(k0 + kr) * lda + m0 + mq * 4]);
            }
        }
        if (!BTR) {
            constexpr int BCH = NT * 4;
#pragma unroll
            for (int c0 = 0; c0 < BCH; c0 += 256) {
                int c = c0 + t;
                int row = c >> 2, kq = c & 3;
                int n = n0 + row;
                if (rl && n >= rs) n += rl;
                cpa16(bb + (uint32_t)(row * AST + kq * 4) * 4,
                      &B[(long long)n * ldb + k0 + kq * 4]);
            }
        } else {
            constexpr int NQ = NT / 4;
            constexpr int SH = (NT == 128) ? 5 : 4;
            constexpr int BCH = KC * NQ;
#pragma unroll
            for (int c0 = 0; c0 < BCH; c0 += 256) {
                int c = c0 + t;
                int kr = c >> SH, nq = c & (NQ - 1);
                int g = k0 + kr;
                if (rl && g >= rs) g += rl;
                cpa16(bb + (uint32_t)(kr * NST + nq * 4) * 4,
                      &B[(long long)g * ldb + n0 + nq * 4]);
            }
        }
        asm volatile("cp.async.commit_group;" ::: "memory");
    };

    // prologue: 3 stages in flight (all K >= 64 -> nK >= 4)
    issue(0, 0);
    issue(1, KC);
    issue(2, 2 * KC);

    for (int i = 0; i < nK; i++) {
        asm volatile("cp.async.wait_group 2;" ::: "memory");
        __syncthreads();
        if (i + 3 < nK) issue((i + 3) & 3, (i + 3) * KC);

        const float* Ab = sm + (i & 3) * STG;
        const float* Bb = Ab + ASZ;
#pragma unroll
        for (int kk = 0; kk < 2; kk++) {
            const int kc = kk * 8;
            uint32_t af[MI][4], bf[NB][2];
#pragma unroll
            for (int mi = 0; mi < MI; mi++) {
                if (!ATR) {
                    const float* ap = &Ab[(wm0 + mi * 16 + (l >> 2)) * AST + kc + (l & 3)];
                    af[mi][0] = tf(ap[0]);
                    af[mi][1] = tf(ap[8 * AST]);
                    af[mi][2] = tf(ap[4]);
                    af[mi][3] = tf(ap[8 * AST + 4]);
                } else {
                    const float* ap = &Ab[(kc + (l & 3)) * MST + wm0 + mi * 16 + (l >> 2)];
                    af[mi][0] = tf(ap[0]);
                    af[mi][1] = tf(ap[8]);
                    af[mi][2] = tf(ap[4 * MST]);
                    af[mi][3] = tf(ap[4 * MST + 8]);
                }
            }
#pragma unroll
            for (int ni = 0; ni < NB; ni++) {
                if (!BTR) {
                    const float* bp = &Bb[(wn0 + ni * 8 + (l >> 2)) * AST + kc + (l & 3)];
                    bf[ni][0] = tf(bp[0]);
                    bf[ni][1] = tf(bp[4]);
                } else {
                    const float* bp = &Bb[(kc + (l & 3)) * NST + wn0 + ni * 8 + (l >> 2)];
                    bf[ni][0] = tf(bp[0]);
                    bf[ni][1] = tf(bp[4 * NST]);
                }
            }
#pragma unroll
            for (int mi = 0; mi < MI; mi++)
#pragma unroll
                for (int ni = 0; ni < NB; ni++) mma8(acc[mi][ni], af[mi], bf[ni]);
        }
    }

    // epilogue: regs -> global
#pragma unroll
    for (int mi = 0; mi < MI; mi++) {
        int row0 = m0 + wm0 + mi * 16 + (l >> 2);
#pragma unroll
        for (int ni = 0; ni < NB; ni++) {
            int col = n0 + wn0 + ni * 8 + (l & 3) * 2;
#pragma unroll
            for (int h = 0; h < 2; h++) {
                int row = row0 + h * 8;
                float vx = alpha * acc[mi][ni][h * 2];
                float vy = alpha * acc[mi][ni][h * 2 + 1];
                if (bias) { vx += bias[col]; vy += bias[col + 1]; }
                if (flags & GFLAG_RELU) { vx = fmaxf(vx, 0.f); vy = fmaxf(vy, 0.f); }
                if (clipVal > 0.f) {
                    vx = fminf(fmaxf(vx, -clipVal), clipVal);
                    vy = fminf(fmaxf(vy, -clipVal), clipVal);
                }
                if (resid) {
                    float2 rv = *(const float2*)&resid[residB * bz + (long long)row * residLd + col];
                    vx += rv.x; vy += rv.y;
                }
                float2* cp = (float2*)&C[(long long)row * ldc + col];
                if (flags & GFLAG_ACCUM) {
                    float2 o = *cp;
                    vx += o.x; vy += o.y;
                }
                *cp = make_float2(vx, vy);
            }
        }
    }
}

// ---------------- reductions ----------------
__device__ __forceinline__ float warpReduceSum(float v) {
#pragma unroll
    for (int o = 16; o; o >>= 1) v += __shfl_xor_sync(0xffffffffu, v, o);
    return v;
}
__device__ __forceinline__ float warpReduceMax(float v) {
#pragma unroll
    for (int o = 16; o; o >>= 1) v = fmaxf(v, __shfl_xor_sync(0xffffffffu, v, o));
    return v;
}

// ---------------- smem-cached row softmax ----------------
__global__ void softmax_k(float* __restrict__ p, int cols) {
    extern __shared__ float sbuf[];
    float* row = p + (long long)blockIdx.x * cols;
    __shared__ float sh[8];
    __shared__ float sb;
    int tid = threadIdx.x, lane = tid & 31, wid = tid >> 5;
    float m = -1e30f;
    for (int i = tid; i < cols; i += 256) { float v = row[i]; sbuf[i] = v; m = fmaxf(m, v); }
    m = warpReduceMax(m);
    if (lane == 0) sh[wid] = m;
    __syncthreads();
    if (tid == 0) { float x = sh[0]; for (int q = 1; q < 8; q++) x = fmaxf(x, sh[q]); sb = x; }
    __syncthreads();
    m = sb;
    float s = 0.f;
    for (int i = tid; i < cols; i += 256) { float v = expf(sbuf[i] - m); sbuf[i] = v; s += v; }
    s = warpReduceSum(s);
    if (lane == 0) sh[wid] = s;
    __syncthreads();
    if (tid == 0) { float x = 0; for (int q = 0; q < 8; q++) x += sh[q]; sb = 1.f / x; }
    __syncthreads();
    float inv = sb;
    for (int i = tid; i < cols; i += 256) row[i] = sbuf[i] * inv;
}

// ---------------- LayerNorm ----------------
__global__ void ln_k(const float* __restrict__ src, float* __restrict__ dst) {
    long long row = blockIdx.x;
    const float* x = src + row * DIM;
    float* y = dst + row * DIM;
    int tid = threadIdx.x, lane = tid & 31, wid = tid >> 5;
    float v[4], s = 0.f, s2 = 0.f;
#pragma unroll
    for (int j = 0; j < 4; j++) { v[j] = x[tid + j * 128]; s += v[j]; s2 += v[j] * v[j]; }
    s = warpReduceSum(s); s2 = warpReduceSum(s2);
    __shared__ float sh[2][4]; __shared__ float mv[2];
    if (lane == 0) { sh[0][wid] = s; sh[1][wid] = s2; }
    __syncthreads();
    if (tid == 0) {
        float a = sh[0][0] + sh[0][1] + sh[0][2] + sh[0][3];
        float b = sh[1][0] + sh[1][1] + sh[1][2] + sh[1][3];
        float mean = a / DIM;
        mv[0] = mean; mv[1] = rsqrtf(b / DIM - mean * mean + 1e-5f);
    }
    __syncthreads();
    float mean = mv[0], rstd = mv[1];
#pragma unroll
    for (int j = 0; j < 4; j++) y[tid + j * 128] = (v[j] - mean) * rstd;
}

__global__ void ln_ra_k(const float* __restrict__ a, const float* __restrict__ b,
                        const float* __restrict__ w, const float* __restrict__ bb,
                        float* __restrict__ dst) {
    long long row = blockIdx.x;
    const float* xa = a + row * DIM;
    const float* xb = b + row * DIM;
    float* y = dst + row * DIM;
    int tid = threadIdx.x, lane = tid & 31, wid = tid >> 5;
    float v[4], s = 0.f, s2 = 0.f;
#pragma unroll
    for (int j = 0; j < 4; j++) {
        int i = tid + j * 128;
        v[j] = xa[i] + xb[i]; s += v[j]; s2 += v[j] * v[j];
    }
    s = warpReduceSum(s); s2 = warpReduceSum(s2);
    __shared__ float sh[2][4]; __shared__ float mv[2];
    if (lane == 0) { sh[0][wid] = s; sh[1][wid] = s2; }
    __syncthreads();
    if (tid == 0) {
        float p = sh[0][0] + sh[0][1] + sh[0][2] + sh[0][3];
        float q = sh[1][0] + sh[1][1] + sh[1][2] + sh[1][3];
        float mean = p / DIM;
        mv[0] = mean; mv[1] = rsqrtf(q / DIM - mean * mean + 1e-5f);
    }
    __syncthreads();
    float mean = mv[0], rstd = mv[1];
#pragma unroll
    for (int j = 0; j < 4; j++) {
        int i = tid + j * 128;
        y[i] = (v[j] - mean) * rstd * w[i] + bb[i];
    }
}

__global__ void permute_k(const float* __restrict__ retr, float* __restrict__ rp) {
    long long i = (long long)blockIdx.x * 256 + threadIdx.x;
    if (i < (long long)NL * NTOK * DIM) {
        int d = (int)(i & (DIM - 1));
        long long r = i >> 9;
        int n = (int)(r & (NTOK - 1));
        int l = (int)(r >> 11);
        rp[((long long)n * NL + l) * DIM + d] = retr[i];
    }
}

__global__ void zero_k(float* __restrict__ p, long long n) {
    long long i = (long long)blockIdx.x * 256 + threadIdx.x;
    if (i < n) p[i] = 0.f;
}

__global__ void gate_dot_k(const float* __restrict__ outs, const float* __restrict__ gg,
                           float* __restrict__ glog) {
    int e = blockIdx.x;
    long long chunk = (long long)ND_ELEMS / gridDim.y;
    long long base = (long long)e * ND_ELEMS + (long long)blockIdx.y * chunk;
    float acc = 0.f;
    for (long long i = threadIdx.x; i < chunk; i += blockDim.x) {
        long long idx = base + i;
        acc += outs[idx] * gg[idx & (DIM - 1)];
    }
    acc = warpReduceSum(acc);
    __shared__ float sh[8];
    int lane = threadIdx.x & 31, wid = threadIdx.x >> 5;
    if (lane == 0) sh[wid] = acc;
    __syncthreads();
    if (threadIdx.x == 0) {
        float x = 0;
        for (int q = 0; q < 8; q++) x += sh[q];
        atomicAdd(&glog[e], x);
    }
}

__global__ void gate_softmax_k(const float* __restrict__ glog, float* __restrict__ gw) {
    if (threadIdx.x == 0) {
        float l[EXP], m = -1e30f;
        for (int e = 0; e < EXP; e++) {
            l[e] = fminf(fmaxf(glog[e] / (float)NTOK, -10.f), 10.f);
            m = fmaxf(m, l[e]);
        }
        float s = 0.f;
        for (int e = 0; e < EXP; e++) { l[e] = expf(l[e] - m); s += l[e]; }
        for (int e = 0; e < EXP; e++) gw[e] = l[e] / s;
    }
}

__global__ void fuse_k(const float* __restrict__ outs, const float* __restrict__ gw,
                       float* __restrict__ fused) {
    long long i = (long long)blockIdx.x * 256 + threadIdx.x;
    if (i < (long long)ND_ELEMS) {
        float r = 0.f;
#pragma unroll
        for (int e = 0; e < EXP; e++) r += gw[e] * outs[(long long)e * ND_ELEMS + i];
        fused[i] = r;
    }
}

__global__ void memupd_k(const float* __restrict__ mem, const float* __restrict__ upd,
                         float* __restrict__ o) {
    long long i = (long long)blockIdx.x * 256 + threadIdx.x;
    if (i < (long long)LMD_ELEMS) {
        float u = 0.1f * upd[i];
        u = fminf(fmaxf(u, -0.1f), 0.1f);
        o[i] = 0.9f * mem[i] + u;
    }
}

// ---------------- host ----------------
static constexpr int stgFl(int MT, int NT, bool ATR, bool BTR) {
    return (ATR ? 16 * (MT + 8) : MT * 20) + (BTR ? 16 * (NT + 8) : NT * 20);
}
#define SMEMB(MT, NT, ATR, BTR) (4 * stgFl(MT, NT, ATR, BTR) * 4)

extern "C" void kernel_launch(void* const* d_in, const int* in_sizes, int n_in,
                              void* d_out, int out_size) {
    const float* tokens   = (const float*)d_in[0];
    const float* memories = (const float*)d_in[1];
    const float* ipw      = (const float*)d_in[2];
    const float* ipb      = (const float*)d_in[3];
    const float* opw      = (const float*)d_in[4];
    const float* opb      = (const float*)d_in[5];
    const float* w1       = (const float*)d_in[6];
    const float* b1       = (const float*)d_in[7];
    const float* w2       = (const float*)d_in[8];
    const float* b2       = (const float*)d_in[9];
    const float* n1w      = (const float*)d_in[10];
    const float* n1b      = (const float*)d_in[11];
    const float* n2w      = (const float*)d_in[12];
    const float* n2b      = (const float*)d_in[13];
    const float* aggw     = (const float*)d_in[14];
    const float* aggb     = (const float*)d_in[15];
    const float* gg       = (const float*)d_in[16];

    float* out = (float*)d_out;
    float* out_fused = out;
    float* out_gw = out + ND_ELEMS;
    float* out_mem = out + ND_ELEMS + EXP;

    static float *p_xln = nullptr, *p_x = nullptr, *p_qkv = nullptr, *p_big = nullptr,
                 *p_sa = nullptr, *p_tmp = nullptr, *p_x1 = nullptr, *p_out = nullptr,
                 *p_retr = nullptr, *p_retrp = nullptr, *p_upd = nullptr, *p_glog = nullptr;
    if (!p_xln) {
        cudaGetSymbolAddress((void**)&p_xln, g_xln);
        cudaGetSymbolAddress((void**)&p_x, g_x);
        cudaGetSymbolAddress((void**)&p_qkv, g_qkv);
        cudaGetSymbolAddress((void**)&p_big, g_big);
        cudaGetSymbolAddress((void**)&p_sa, g_sa);
        cudaGetSymbolAddress((void**)&p_tmp, g_tmp);
        cudaGetSymbolAddress((void**)&p_x1, g_x1);
        cudaGetSymbolAddress((void**)&p_out, g_out);
        cudaGetSymbolAddress((void**)&p_retr, g_retr);
        cudaGetSymbolAddress((void**)&p_retrp, g_retrp);
        cudaGetSymbolAddress((void**)&p_upd, g_upd);
        cudaGetSymbolAddress((void**)&p_glog, g_glog);
        cudaFuncSetAttribute(gemmCP<64, 128, false, false>, cudaFuncAttributeMaxDynamicSharedMemorySize, SMEMB(64, 128, false, false));
        cudaFuncSetAttribute(gemmCP<64, 128, false, true>,  cudaFuncAttributeMaxDynamicSharedMemorySize, SMEMB(64, 128, false, true));
        cudaFuncSetAttribute(gemmCP<64, 64, false, true>,   cudaFuncAttributeMaxDynamicSharedMemorySize, SMEMB(64, 64, false, true));
        cudaFuncSetAttribute(gemmCP<64, 128, true, true>,   cudaFuncAttributeMaxDynamicSharedMemorySize, SMEMB(64, 128, true, true));
    }

    const float inv_sqrt_d = 1.0f / sqrtf((float)DIM);
    const float inv_sqrt_dh = 1.0f / sqrtf((float)DHEAD);

    zero_k<<<(LMD_ELEMS + 255) / 256, 256>>>(p_upd, LMD_ELEMS);
    zero_k<<<1, 256>>>(p_glog, EXP);
    ln_k<<<EXP * NTOK, 128>>>(tokens, p_xln);

    for (int e = 0; e < EXP; e++) {
        const float* Ax = p_xln + (long long)e * ND_ELEMS;
        float* xo = p_out + (long long)e * ND_ELEMS;

        // cross logits [2048, 6144] = clip(x @ ctx^T / sqrt(D), 10)
        gemmCP<64, 128, false, false><<<dim3(48, 32, 1), 256, SMEMB(64, 128, false, false)>>>(
            Ax, p_xln, p_big, DIM, DIM, DIM, 3 * NTOK, 0, 0, 0,
            inv_sqrt_d, nullptr, nullptr, 0, 0, 10.f, 0, e * NTOK, NTOK);
        softmax_k<<<NTOK, 256, 3 * NTOK * 4>>>(p_big, 3 * NTOK);
        // x = probs @ ctx + x   (B stored [k, n], remap on k)
        gemmCP<64, 128, false, true><<<dim3(4, 32, 1), 256, SMEMB(64, 128, false, true)>>>(
            p_big, p_xln, p_x, 3 * NTOK, 3 * NTOK, DIM, DIM, 0, 0, 0,
            1.f, nullptr, Ax, 0, DIM, 0.f, 0, e * NTOK, NTOK);
        // qkv [2048, 1536]
        gemmCP<64, 128, false, false><<<dim3(12, 32, 1), 256, SMEMB(64, 128, false, false)>>>(
            p_x, ipw + (long long)e * 3 * DIM * DIM, p_qkv, DIM, DIM, DIM, 3 * DIM, 0, 0, 0,
            1.f, ipb + e * 3 * DIM, nullptr, 0, 0, 0.f, 0, 0, 0);
        // scores [h][2048, 2048] = q_h k_h^T / sqrt(dh)
        gemmCP<64, 128, false, false><<<dim3(16, 32, NH), 256, SMEMB(64, 128, false, false)>>>(
            p_qkv, p_qkv + DIM, p_big, DHEAD, 3 * DIM, 3 * DIM, NTOK,
            DHEAD, DHEAD, (long long)NTOK * NTOK,
            inv_sqrt_dh, nullptr, nullptr, 0, 0, 0.f, 0, 0, 0);
        softmax_k<<<NH * NTOK, 256, NTOK * 4>>>(p_big, NTOK);
        // sa[:, h*64:] = probs_h @ v_h  (B stored [k, n] ld 1536)
        gemmCP<64, 64, false, true><<<dim3(1, 32, NH), 256, SMEMB(64, 64, false, true)>>>(
            p_big, p_qkv + 2 * DIM, p_sa, NTOK, NTOK, 3 * DIM, DIM,
            (long long)NTOK * NTOK, DHEAD, DHEAD,
            1.f, nullptr, nullptr, 0, 0, 0.f, 0, 0, 0);
        // out_proj
        gemmCP<64, 128, false, false><<<dim3(4, 32, 1), 256, SMEMB(64, 128, false, false)>>>(
            p_sa, opw + (long long)e * DIM * DIM, p_tmp, DIM, DIM, DIM, DIM, 0, 0, 0,
            1.f, opb + e * DIM, nullptr, 0, 0, 0.f, 0, 0, 0);
        ln_ra_k<<<NTOK, 128>>>(p_x, p_tmp, n1w + e * DIM, n1b + e * DIM, p_x1);
        // ff1 relu
        gemmCP<64, 128, false, false><<<dim3(16, 32, 1), 256, SMEMB(64, 128, false, false)>>>(
            p_x1, w1 + (long long)e * FFD * DIM, p_tmp, DIM, DIM, DIM, FFD, 0, 0, 0,
            1.f, b1 + e * FFD, nullptr, 0, 0, 0.f, GFLAG_RELU, 0, 0);
        // ff2
        gemmCP<64, 128, false, false><<<dim3(4, 32, 1), 256, SMEMB(64, 128, false, false)>>>(
            p_tmp, w2 + (long long)e * DIM * FFD, p_sa, FFD, FFD, FFD, DIM, 0, 0, 0,
            1.f, b2 + e * DIM, nullptr, 0, 0, 0.f, 0, 0, 0);
        ln_ra_k<<<NTOK, 128>>>(p_x1, p_sa, n2w + e * DIM, n2b + e * DIM, xo);
        // memory logits [l][2048, 4096]
        gemmCP<64, 128, false, false><<<dim3(32, 32, NL), 256, SMEMB(64, 128, false, false)>>>(
            xo, memories, p_big, DIM, DIM, DIM, MEMSZ,
            0, (long long)MEMSZ * DIM, (long long)NTOK * MEMSZ,
            inv_sqrt_d, nullptr, nullptr, 0, 0, 10.f, 0, 0, 0);
        softmax_k<<<NL * NTOK, 256, MEMSZ * 4>>>(p_big, MEMSZ);
        // retr[l] = am[l] @ mem_l  (B stored [k, n] ld 512)
        gemmCP<64, 128, false, true><<<dim3(4, 32, NL), 256, SMEMB(64, 128, false, true)>>>(
            p_big, memories, p_retr, MEMSZ, MEMSZ, DIM, DIM,
            (long long)NTOK * MEMSZ, (long long)MEMSZ * DIM, (long long)NTOK * DIM,
            1.f, nullptr, nullptr, 0, 0, 0.f, 0, 0, 0);
        // upd[l] += clip(am[l]^T @ xout, 1)  (A stored [k, m] ld 4096, B stored [k, n] ld 512)
        gemmCP<64, 128, true, true><<<dim3(4, 64, NL), 256, SMEMB(64, 128, true, true)>>>(
            p_big, xo, p_upd, NTOK, MEMSZ, DIM, DIM,
            (long long)NTOK * MEMSZ, 0, (long long)MEMSZ * DIM,
            1.f, nullptr, nullptr, 0, 0, 1.f, GFLAG_ACCUM, 0, 0);
        permute_k<<<(NL * ND_ELEMS + 255) / 256, 256>>>(p_retr, p_retrp);
        // outs[e] = xout + retrp @ aggw^T + aggb
        gemmCP<64, 128, false, false><<<dim3(4, 32, 1), 256, SMEMB(64, 128, false, false)>>>(
            p_retrp, aggw, xo, NL * DIM, NL * DIM, NL * DIM, DIM, 0, 0, 0,
            1.f, aggb, xo, 0, DIM, 0.f, 0, 0, 0);
    }

    dim3 ggrid(EXP, 16);
    gate_dot_k<<<ggrid, 256>>>(p_out, gg, p_glog);
    gate_softmax_k<<<1, 32>>>(p_glog, out_gw);
    fuse_k<<<(ND_ELEMS + 255) / 256, 256>>>(p_out, out_gw, out_fused);
    memupd_k<<<(LMD_ELEMS + 255) / 256, 256>>>(memories, p_upd, out_mem);

    (void)in_sizes; (void)n_in; (void)out_size;
}

// round 6
// speedup vs baseline: 4.4977x; 1.0203x over previous
#include <cuda_runtime.h>
#include <math.h>
#include <stdint.h>

#define EXP 4
#define NTOK 2048
#define DIM 512
#define NH 8
#define DHEAD 64
#define FFD 2048
#define NL 4
#define MEMSZ 4096

#define ND_ELEMS (NTOK * DIM)
#define LMD_ELEMS (NL * MEMSZ * DIM)

#define GFLAG_RELU 1
#define GFLAG_ACCUM 2
#define GFLAG_TFOUT 4

// ---------------- scratch ----------------
__device__ float g_xln[EXP * NTOK * DIM];
__device__ float g_x[NTOK * DIM];
__device__ float g_qkv[NTOK * 3 * DIM];
__device__ float g_big[(size_t)NH * NTOK * NTOK];
__device__ float g_sa[NTOK * DIM];
__device__ float g_tmp[NTOK * FFD];
__device__ float g_x1[NTOK * DIM];
__device__ float g_x1r[NTOK * DIM];
__device__ float g_xor[NTOK * DIM];
__device__ float g_out[EXP * NTOK * DIM];
__device__ float g_retr[NL * NTOK * DIM];
__device__ float g_retrp[NTOK * NL * DIM];
__device__ float g_upd[NL * MEMSZ * DIM];
__device__ float g_glog[EXP];
// pre-rounded weights
__device__ float g_ipw_r[EXP * 3 * DIM * DIM];
__device__ float g_opw_r[EXP * DIM * DIM];
__device__ float g_w1_r[EXP * FFD * DIM];
__device__ float g_w2_r[EXP * DIM * FFD];
__device__ float g_aggw_r[DIM * NL * DIM];
__device__ float g_mem_r[LMD_ELEMS];

// ---------------- helpers ----------------
__device__ __forceinline__ uint32_t tf(float x) {
    uint32_t u; asm("cvt.rna.tf32.f32 %0, %1;" : "=r"(u) : "f"(x)); return u;
}
__device__ __forceinline__ float tff(float x) { return __uint_as_float(tf(x)); }
__device__ __forceinline__ void mma8(float* c, const uint32_t* a, const uint32_t* b) {
    asm volatile(
        "mma.sync.aligned.m16n8k8.row.col.f32.tf32.tf32.f32 "
        "{%0,%1,%2,%3}, {%4,%5,%6,%7}, {%8,%9}, {%0,%1,%2,%3};"
        : "+f"(c[0]), "+f"(c[1]), "+f"(c[2]), "+f"(c[3])
        : "r"(a[0]), "r"(a[1]), "r"(a[2]), "r"(a[3]), "r"(b[0]), "r"(b[1]));
}
__device__ __forceinline__ void cpa16(uint32_t s, const float* g) {
    asm volatile("cp.async.cg.shared.global [%0], [%1], 16;" :: "r"(s), "l"(g));
}

__global__ void tfround_k(const float* __restrict__ s, float* __restrict__ d, long long n) {
    long long i = (long long)blockIdx.x * 256 + threadIdx.x;
    if (i < n) d[i] = tff(s[i]);
}

// ---------------- cp.async tf32 mma GEMM (inputs pre-rounded to tf32) ----------------
// C[M,Nc] = alpha*op(A)*op(B) (+bias)(relu)(clip)(+resid)(accum)(tfout)
// ATR: A stored [K,M] (M contig). BTR: B stored [K,Nc] (Nc contig). Else K-contig rows.
// remap (rl>0): for !BTR remaps B n-rows; for BTR remaps B k-rows (ctx skip).
template <int MT, int NT, bool ATR, bool BTR>
__global__ void __launch_bounds__(256, 2) gemmCP(
    const float* __restrict__ A, const float* __restrict__ B, float* __restrict__ C,
    int K, int lda, int ldb, int ldc,
    long long aB, long long bB, long long cB,
    float alpha, const float* __restrict__ bias,
    const float* __restrict__ resid, long long residB, int residLd,
    float clipVal, int flags, int rs, int rl)
{
    constexpr int KC = 16;
    constexpr int AST = 20;
    constexpr int MST = MT + 8;
    constexpr int NST = NT + 8;
    constexpr int ASZ = ATR ? KC * MST : MT * AST;
    constexpr int BSZ = BTR ? KC * NST : NT * AST;
    constexpr int STG = ASZ + BSZ;
    constexpr int MI = MT / 32;
    constexpr int NB = NT / 32;

    extern __shared__ float sm[];
    uint32_t smb = (uint32_t)__cvta_generic_to_shared(sm);

    const int t = threadIdx.x, l = t & 31, w = t >> 5;
    const int bz = blockIdx.z;
    A += aB * bz; B += bB * bz; C += cB * bz;
    const int m0 = blockIdx.y * MT, n0 = blockIdx.x * NT;
    const int wm0 = (w >> 2) * (MT / 2), wn0 = (w & 3) * (NT / 4);

    float acc[MI][NB][4];
#pragma unroll
    for (int a = 0; a < MI; a++)
#pragma unroll
        for (int b = 0; b < NB; b++)
#pragma unroll
            for (int c = 0; c < 4; c++) acc[a][b][c] = 0.f;

    const int nK = K / KC;

    auto issue = [&](int s, int k0) {
        uint32_t ab = smb + (uint32_t)(s * STG * 4);
        uint32_t bb = ab + ASZ * 4;
        if (!ATR) {
            constexpr int ACH = MT * 4;
#pragma unroll
            for (int c0 = 0; c0 < ACH; c0 += 256) {
                int c = c0 + t;
                int row = c >> 2, kq = c & 3;
                cpa16(ab + (uint32_t)(row * AST + kq * 4) * 4,
                      &A[(long long)(m0 + row) * lda + k0 + kq * 4]);
            }
        } else {
            constexpr int AQ = MT / 4;
            constexpr int ASH = (MT == 128) ? 5 : 4;
            constexpr int ACH = KC * AQ;
#pragma unroll
            for (int c0 = 0; c0 < ACH; c0 += 256) {
                int c = c0 + t;
                int kr = c >> ASH, mq = c & (AQ - 1);
                cpa16(ab + (uint32_t)(kr * MST + mq * 4) * 4,
                      &A[(long long)(k0 + kr) * lda + m0 + mq * 4]);
            }
        }
        if (!BTR) {
            constexpr int BCH = NT * 4;
#pragma unroll
            for (int c0 = 0; c0 < BCH; c0 += 256) {
                int c = c0 + t;
                int row = c >> 2, kq = c & 3;
                int n = n0 + row;
                if (rl && n >= rs) n += rl;
                cpa16(bb + (uint32_t)(row * AST + kq * 4) * 4,
                      &B[(long long)n * ldb + k0 + kq * 4]);
            }
        } else {
            constexpr int NQ = NT / 4;
            constexpr int SH = (NT == 128) ? 5 : 4;
            constexpr int BCH = KC * NQ;
#pragma unroll
            for (int c0 = 0; c0 < BCH; c0 += 256) {
                int c = c0 + t;
                int kr = c >> SH, nq = c & (NQ - 1);
                int g = k0 + kr;
                if (rl && g >= rs) g += rl;
                cpa16(bb + (uint32_t)(kr * NST + nq * 4) * 4,
                      &B[(long long)g * ldb + n0 + nq * 4]);
            }
        }
        asm volatile("cp.async.commit_group;" ::: "memory");
    };

    issue(0, 0);
    issue(1, KC);
    issue(2, 2 * KC);

    for (int i = 0; i < nK; i++) {
        asm volatile("cp.async.wait_group 2;" ::: "memory");
        __syncthreads();
        if (i + 3 < nK) issue((i + 3) & 3, (i + 3) * KC);

        const float* Ab = sm + (i & 3) * STG;
        const float* Bb = Ab + ASZ;
#pragma unroll
        for (int kk = 0; kk < 2; kk++) {
            const int kc = kk * 8;
            uint32_t af[MI][4], bf[NB][2];
#pragma unroll
            for (int mi = 0; mi < MI; mi++) {
                if (!ATR) {
                    const uint32_t* ap = (const uint32_t*)&Ab[(wm0 + mi * 16 + (l >> 2)) * AST + kc + (l & 3)];
                    af[mi][0] = ap[0];
                    af[mi][1] = ap[8 * AST];
                    af[mi][2] = ap[4];
                    af[mi][3] = ap[8 * AST + 4];
                } else {
                    const uint32_t* ap = (const uint32_t*)&Ab[(kc + (l & 3)) * MST + wm0 + mi * 16 + (l >> 2)];
                    af[mi][0] = ap[0];
                    af[mi][1] = ap[8];
                    af[mi][2] = ap[4 * MST];
                    af[mi][3] = ap[4 * MST + 8];
                }
            }
#pragma unroll
            for (int ni = 0; ni < NB; ni++) {
                if (!BTR) {
                    const uint32_t* bp = (const uint32_t*)&Bb[(wn0 + ni * 8 + (l >> 2)) * AST + kc + (l & 3)];
                    bf[ni][0] = bp[0];
                    bf[ni][1] = bp[4];
                } else {
                    const uint32_t* bp = (const uint32_t*)&Bb[(kc + (l & 3)) * NST + wn0 + ni * 8 + (l >> 2)];
                    bf[ni][0] = bp[0];
                    bf[ni][1] = bp[4 * NST];
                }
            }
#pragma unroll
            for (int mi = 0; mi < MI; mi++)
#pragma unroll
                for (int ni = 0; ni < NB; ni++) mma8(acc[mi][ni], af[mi], bf[ni]);
        }
    }

    // epilogue
#pragma unroll
    for (int mi = 0; mi < MI; mi++) {
        int row0 = m0 + wm0 + mi * 16 + (l >> 2);
#pragma unroll
        for (int ni = 0; ni < NB; ni++) {
            int col = n0 + wn0 + ni * 8 + (l & 3) * 2;
#pragma unroll
            for (int h = 0; h < 2; h++) {
                int row = row0 + h * 8;
                float vx = alpha * acc[mi][ni][h * 2];
                float vy = alpha * acc[mi][ni][h * 2 + 1];
                if (bias) { vx += bias[col]; vy += bias[col + 1]; }
                if (flags & GFLAG_RELU) { vx = fmaxf(vx, 0.f); vy = fmaxf(vy, 0.f); }
                if (clipVal > 0.f) {
                    vx = fminf(fmaxf(vx, -clipVal), clipVal);
                    vy = fminf(fmaxf(vy, -clipVal), clipVal);
                }
                if (resid) {
                    float2 rv = *(const float2*)&resid[residB * bz + (long long)row * residLd + col];
                    vx += rv.x; vy += rv.y;
                }
                float2* cp = (float2*)&C[(long long)row * ldc + col];
                if (flags & GFLAG_ACCUM) {
                    float2 o = *cp;
                    vx += o.x; vy += o.y;
                }
                if (flags & GFLAG_TFOUT) { vx = tff(vx); vy = tff(vy); }
                *cp = make_float2(vx, vy);
            }
        }
    }
}

// ---------------- reductions ----------------
__device__ __forceinline__ float warpReduceSum(float v) {
#pragma unroll
    for (int o = 16; o; o >>= 1) v += __shfl_xor_sync(0xffffffffu, v, o);
    return v;
}
__device__ __forceinline__ float warpReduceMax(float v) {
#pragma unroll
    for (int o = 16; o; o >>= 1) v = fmaxf(v, __shfl_xor_sync(0xffffffffu, v, o));
    return v;
}

// ---------------- smem-cached row softmax (tf32-rounded output) ----------------
__global__ void softmax_k(float* __restrict__ p, int cols) {
    extern __shared__ float sbuf[];
    float* row = p + (long long)blockIdx.x * cols;
    __shared__ float sh[8];
    __shared__ float sb;
    int tid = threadIdx.x, lane = tid & 31, wid = tid >> 5;
    float m = -1e30f;
    for (int i = tid; i < cols; i += 256) { float v = row[i]; sbuf[i] = v; m = fmaxf(m, v); }
    m = warpReduceMax(m);
    if (lane == 0) sh[wid] = m;
    __syncthreads();
    if (tid == 0) { float x = sh[0]; for (int q = 1; q < 8; q++) x = fmaxf(x, sh[q]); sb = x; }
    __syncthreads();
    m = sb;
    float s = 0.f;
    for (int i = tid; i < cols; i += 256) { float v = expf(sbuf[i] - m); sbuf[i] = v; s += v; }
    s = warpReduceSum(s);
    if (lane == 0) sh[wid] = s;
    __syncthreads();
    if (tid == 0) { float x = 0; for (int q = 0; q < 8; q++) x += sh[q]; sb = 1.f / x; }
    __syncthreads();
    float inv = sb;
    for (int i = tid; i < cols; i += 256) row[i] = tff(sbuf[i] * inv);
}

// ---------------- LayerNorm (rounded output) ----------------
__global__ void ln_k(const float* __restrict__ src, float* __restrict__ dst) {
    long long row = blockIdx.x;
    const float* x = src + row * DIM;
    float* y = dst + row * DIM;
    int tid = threadIdx.x, lane = tid & 31, wid = tid >> 5;
    float v[4], s = 0.f, s2 = 0.f;
#pragma unroll
    for (int j = 0; j < 4; j++) { v[j] = x[tid + j * 128]; s += v[j]; s2 += v[j] * v[j]; }
    s = warpReduceSum(s); s2 = warpReduceSum(s2);
    __shared__ float sh[2][4]; __shared__ float mv[2];
    if (lane == 0) { sh[0][wid] = s; sh[1][wid] = s2; }
    __syncthreads();
    if (tid == 0) {
        float a = sh[0][0] + sh[0][1] + sh[0][2] + sh[0][3];
        float b = sh[1][0] + sh[1][1] + sh[1][2] + sh[1][3];
        float mean = a / DIM;
        mv[0] = mean; mv[1] = rsqrtf(b / DIM - mean * mean + 1e-5f);
    }
    __syncthreads();
    float mean = mv[0], rstd = mv[1];
#pragma unroll
    for (int j = 0; j < 4; j++) y[tid + j * 128] = tff((v[j] - mean) * rstd);
}

// dst = LN(a+b)*w + bb (full precision); dstr = tf32-rounded copy
__global__ void ln_ra_k(const float* __restrict__ a, const float* __restrict__ b,
                        const float* __restrict__ w, const float* __restrict__ bb,
                        float* __restrict__ dst, float* __restrict__ dstr) {
    long long row = blockIdx.x;
    const float* xa = a + row * DIM;
    const float* xb = b + row * DIM;
    float* y = dst + row * DIM;
    float* yr = dstr + row * DIM;
    int tid = threadIdx.x, lane = tid & 31, wid = tid >> 5;
    float v[4], s = 0.f, s2 = 0.f;
#pragma unroll
    for (int j = 0; j < 4; j++) {
        int i = tid + j * 128;
        v[j] = xa[i] + xb[i]; s += v[j]; s2 += v[j] * v[j];
    }
    s = warpReduceSum(s); s2 = warpReduceSum(s2);
    __shared__ float sh[2][4]; __shared__ float mv[2];
    if (lane == 0) { sh[0][wid] = s; sh[1][wid] = s2; }
    __syncthreads();
    if (tid == 0) {
        float p = sh[0][0] + sh[0][1] + sh[0][2] + sh[0][3];
        float q = sh[1][0] + sh[1][1] + sh[1][2] + sh[1][3];
        float mean = p / DIM;
        mv[0] = mean; mv[1] = rsqrtf(q / DIM - mean * mean + 1e-5f);
    }
    __syncthreads();
    float mean = mv[0], rstd = mv[1];
#pragma unroll
    for (int j = 0; j < 4; j++) {
        int i = tid + j * 128;
        float o = (v[j] - mean) * rstd * w[i] + bb[i];
        y[i] = o;
        yr[i] = tff(o);
    }
}

__global__ void permute_k(const float* __restrict__ retr, float* __restrict__ rp) {
    long long i = (long long)blockIdx.x * 256 + threadIdx.x;
    if (i < (long long)NL * NTOK * DIM) {
        int d = (int)(i & (DIM - 1));
        long long r = i >> 9;
        int n = (int)(r & (NTOK - 1));
        int l = (int)(r >> 11);
        rp[((long long)n * NL + l) * DIM + d] = tff(retr[i]);
    }
}

__global__ void zero_k(float* __restrict__ p, long long n) {
    long long i = (long long)blockIdx.x * 256 + threadIdx.x;
    if (i < n) p[i] = 0.f;
}

__global__ void gate_dot_k(const float* __restrict__ outs, const float* __restrict__ gg,
                           float* __restrict__ glog) {
    int e = blockIdx.x;
    long long chunk = (long long)ND_ELEMS / gridDim.y;
    long long base = (long long)e * ND_ELEMS + (long long)blockIdx.y * chunk;
    float acc = 0.f;
    for (long long i = threadIdx.x; i < chunk; i += blockDim.x) {
        long long idx = base + i;
        acc += outs[idx] * gg[idx & (DIM - 1)];
    }
    acc = warpReduceSum(acc);
    __shared__ float sh[8];
    int lane = threadIdx.x & 31, wid = threadIdx.x >> 5;
    if (lane == 0) sh[wid] = acc;
    __syncthreads();
    if (threadIdx.x == 0) {
        float x = 0;
        for (int q = 0; q < 8; q++) x += sh[q];
        atomicAdd(&glog[e], x);
    }
}

__global__ void gate_softmax_k(const float* __restrict__ glog, float* __restrict__ gw) {
    if (threadIdx.x == 0) {
        float l[EXP], m = -1e30f;
        for (int e = 0; e < EXP; e++) {
            l[e] = fminf(fmaxf(glog[e] / (float)NTOK, -10.f), 10.f);
            m = fmaxf(m, l[e]);
        }
        float s = 0.f;
        for (int e = 0; e < EXP; e++) { l[e] = expf(l[e] - m); s += l[e]; }
        for (int e = 0; e < EXP; e++) gw[e] = l[e] / s;
    }
}

__global__ void fuse_k(const float* __restrict__ outs, const float* __restrict__ gw,
                       float* __restrict__ fused) {
    long long i = (long long)blockIdx.x * 256 + threadIdx.x;
    if (i < (long long)ND_ELEMS) {
        float r = 0.f;
#pragma unroll
        for (int e = 0; e < EXP; e++) r += gw[e] * outs[(long long)e * ND_ELEMS + i];
        fused[i] = r;
    }
}

__global__ void memupd_k(const float* __restrict__ mem, const float* __restrict__ upd,
                         float* __restrict__ o) {
    long long i = (long long)blockIdx.x * 256 + threadIdx.x;
    if (i < (long long)LMD_ELEMS) {
        float u = 0.1f * upd[i];
        u = fminf(fmaxf(u, -0.1f), 0.1f);
        o[i] = 0.9f * mem[i] + u;
    }
}

// ---------------- host ----------------
static constexpr int stgFl(int MT, int NT, bool ATR, bool BTR) {
    return (ATR ? 16 * (MT + 8) : MT * 20) + (BTR ? 16 * (NT + 8) : NT * 20);
}
#define SMEMB(MT, NT, ATR, BTR) (4 * stgFl(MT, NT, ATR, BTR) * 4)

static void tfround(const float* s, float* d, long long n) {
    tfround_k<<<(int)((n + 255) / 256), 256>>>(s, d, n);
}

extern "C" void kernel_launch(void* const* d_in, const int* in_sizes, int n_in,
                              void* d_out, int out_size) {
    const float* tokens   = (const float*)d_in[0];
    const float* memories = (const float*)d_in[1];
    const float* ipw      = (const float*)d_in[2];
    const float* ipb      = (const float*)d_in[3];
    const float* opw      = (const float*)d_in[4];
    const float* opb      = (const float*)d_in[5];
    const float* w1       = (const float*)d_in[6];
    const float* b1       = (const float*)d_in[7];
    const float* w2       = (const float*)d_in[8];
    const float* b2       = (const float*)d_in[9];
    const float* n1w      = (const float*)d_in[10];
    const float* n1b      = (const float*)d_in[11];
    const float* n2w      = (const float*)d_in[12];
    const float* n2b      = (const float*)d_in[13];
    const float* aggw     = (const float*)d_in[14];
    const float* aggb     = (const float*)d_in[15];
    const float* gg       = (const float*)d_in[16];

    float* out = (float*)d_out;
    float* out_fused = out;
    float* out_gw = out + ND_ELEMS;
    float* out_mem = out + ND_ELEMS + EXP;

    static float *p_xln = nullptr, *p_x = nullptr, *p_qkv = nullptr, *p_big = nullptr,
                 *p_sa = nullptr, *p_tmp = nullptr, *p_x1 = nullptr, *p_x1r = nullptr,
                 *p_xor = nullptr, *p_out = nullptr,
                 *p_retr = nullptr, *p_retrp = nullptr, *p_upd = nullptr, *p_glog = nullptr,
                 *p_ipw = nullptr, *p_opw = nullptr, *p_w1 = nullptr, *p_w2 = nullptr,
                 *p_aggw = nullptr, *p_mem = nullptr;
    if (!p_xln) {
        cudaGetSymbolAddress((void**)&p_xln, g_xln);
        cudaGetSymbolAddress((void**)&p_x, g_x);
        cudaGetSymbolAddress((void**)&p_qkv, g_qkv);
        cudaGetSymbolAddress((void**)&p_big, g_big);
        cudaGetSymbolAddress((void**)&p_sa, g_sa);
        cudaGetSymbolAddress((void**)&p_tmp, g_tmp);
        cudaGetSymbolAddress((void**)&p_x1, g_x1);
        cudaGetSymbolAddress((void**)&p_x1r, g_x1r);
        cudaGetSymbolAddress((void**)&p_xor, g_xor);
        cudaGetSymbolAddress((void**)&p_out, g_out);
        cudaGetSymbolAddress((void**)&p_retr, g_retr);
        cudaGetSymbolAddress((void**)&p_retrp, g_retrp);
        cudaGetSymbolAddress((void**)&p_upd, g_upd);
        cudaGetSymbolAddress((void**)&p_glog, g_glog);
        cudaGetSymbolAddress((void**)&p_ipw, g_ipw_r);
        cudaGetSymbolAddress((void**)&p_opw, g_opw_r);
        cudaGetSymbolAddress((void**)&p_w1, g_w1_r);
        cudaGetSymbolAddress((void**)&p_w2, g_w2_r);
        cudaGetSymbolAddress((void**)&p_aggw, g_aggw_r);
        cudaGetSymbolAddress((void**)&p_mem, g_mem_r);
        cudaFuncSetAttribute(gemmCP<64, 128, false, false>, cudaFuncAttributeMaxDynamicSharedMemorySize, SMEMB(64, 128, false, false));
        cudaFuncSetAttribute(gemmCP<64, 128, false, true>,  cudaFuncAttributeMaxDynamicSharedMemorySize, SMEMB(64, 128, false, true));
        cudaFuncSetAttribute(gemmCP<64, 64, false, true>,   cudaFuncAttributeMaxDynamicSharedMemorySize, SMEMB(64, 64, false, true));
        cudaFuncSetAttribute(gemmCP<64, 128, true, true>,   cudaFuncAttributeMaxDynamicSharedMemorySize, SMEMB(64, 128, true, true));
    }

    const float inv_sqrt_d = 1.0f / sqrtf((float)DIM);
    const float inv_sqrt_dh = 1.0f / sqrtf((float)DHEAD);

    // pre-round weights to tf32 (graph-replay safe: pure function of inputs)
    tfround(ipw, p_ipw, (long long)EXP * 3 * DIM * DIM);
    tfround(opw, p_opw, (long long)EXP * DIM * DIM);
    tfround(w1, p_w1, (long long)EXP * FFD * DIM);
    tfround(w2, p_w2, (long long)EXP * DIM * FFD);
    tfround(aggw, p_aggw, (long long)DIM * NL * DIM);
    tfround(memories, p_mem, (long long)LMD_ELEMS);

    zero_k<<<(LMD_ELEMS + 255) / 256, 256>>>(p_upd, LMD_ELEMS);
    zero_k<<<1, 256>>>(p_glog, EXP);
    ln_k<<<EXP * NTOK, 128>>>(tokens, p_xln);

    for (int e = 0; e < EXP; e++) {
        const float* Ax = p_xln + (long long)e * ND_ELEMS;
        float* xo = p_out + (long long)e * ND_ELEMS;

        // cross logits [2048, 6144] = clip(x @ ctx^T / sqrt(D), 10)
        gemmCP<64, 128, false, false><<<dim3(48, 32, 1), 256, SMEMB(64, 128, false, false)>>>(
            Ax, p_xln, p_big, DIM, DIM, DIM, 3 * NTOK, 0, 0, 0,
            inv_sqrt_d, nullptr, nullptr, 0, 0, 10.f, 0, e * NTOK, NTOK);
        softmax_k<<<NTOK, 256, 3 * NTOK * 4>>>(p_big, 3 * NTOK);
        // x = probs @ ctx + x (rounded out)
        gemmCP<64, 128, false, true><<<dim3(4, 32, 1), 256, SMEMB(64, 128, false, true)>>>(
            p_big, p_xln, p_x, 3 * NTOK, 3 * NTOK, DIM, DIM, 0, 0, 0,
            1.f, nullptr, Ax, 0, DIM, 0.f, GFLAG_TFOUT, e * NTOK, NTOK);
        // qkv [2048, 1536] (rounded out)
        gemmCP<64, 128, false, false><<<dim3(12, 32, 1), 256, SMEMB(64, 128, false, false)>>>(
            p_x, p_ipw + (long long)e * 3 * DIM * DIM, p_qkv, DIM, DIM, DIM, 3 * DIM, 0, 0, 0,
            1.f, ipb + e * 3 * DIM, nullptr, 0, 0, 0.f, GFLAG_TFOUT, 0, 0);
        // scores [h][2048, 2048]
        gemmCP<64, 128, false, false><<<dim3(16, 32, NH), 256, SMEMB(64, 128, false, false)>>>(
            p_qkv, p_qkv + DIM, p_big, DHEAD, 3 * DIM, 3 * DIM, NTOK,
            DHEAD, DHEAD, (long long)NTOK * NTOK,
            inv_sqrt_dh, nullptr, nullptr, 0, 0, 0.f, 0, 0, 0);
        softmax_k<<<NH * NTOK, 256, NTOK * 4>>>(p_big, NTOK);
        // sa[:, h*64:] = probs_h @ v_h (rounded out)
        gemmCP<64, 64, false, true><<<dim3(1, 32, NH), 256, SMEMB(64, 64, false, true)>>>(
            p_big, p_qkv + 2 * DIM, p_sa, NTOK, NTOK, 3 * DIM, DIM,
            (long long)NTOK * NTOK, DHEAD, DHEAD,
            1.f, nullptr, nullptr, 0, 0, 0.f, GFLAG_TFOUT, 0, 0);
        // out_proj (full out; feeds ln_ra only)
        gemmCP<64, 128, false, false><<<dim3(4, 32, 1), 256, SMEMB(64, 128, false, false)>>>(
            p_sa, p_opw + (long long)e * DIM * DIM, p_tmp, DIM, DIM, DIM, DIM, 0, 0, 0,
            1.f, opb + e * DIM, nullptr, 0, 0, 0.f, 0, 0, 0);
        ln_ra_k<<<NTOK, 128>>>(p_x, p_tmp, n1w + e * DIM, n1b + e * DIM, p_x1, p_x1r);
        // ff1 relu (rounded out)
        gemmCP<64, 128, false, false><<<dim3(16, 32, 1), 256, SMEMB(64, 128, false, false)>>>(
            p_x1r, p_w1 + (long long)e * FFD * DIM, p_tmp, DIM, DIM, DIM, FFD, 0, 0, 0,
            1.f, b1 + e * FFD, nullptr, 0, 0, 0.f, GFLAG_RELU | GFLAG_TFOUT, 0, 0);
        // ff2 (full out; feeds ln_ra only)
        gemmCP<64, 128, false, false><<<dim3(4, 32, 1), 256, SMEMB(64, 128, false, false)>>>(
            p_tmp, p_w2 + (long long)e * DIM * FFD, p_sa, FFD, FFD, FFD, DIM, 0, 0, 0,
            1.f, b2 + e * DIM, nullptr, 0, 0, 0.f, 0, 0, 0);
        ln_ra_k<<<NTOK, 128>>>(p_x1, p_sa, n2w + e * DIM, n2b + e * DIM, xo, p_xor);
        // memory logits [l][2048, 4096]
        gemmCP<64, 128, false, false><<<dim3(32, 32, NL), 256, SMEMB(64, 128, false, false)>>>(
            p_xor, p_mem, p_big, DIM, DIM, DIM, MEMSZ,
            0, (long long)MEMSZ * DIM, (long long)NTOK * MEMSZ,
            inv_sqrt_d, nullptr, nullptr, 0, 0, 10.f, 0, 0, 0);
        softmax_k<<<NL * NTOK, 256, MEMSZ * 4>>>(p_big, MEMSZ);
        // retr[l] = am[l] @ mem_l
        gemmCP<64, 128, false, true><<<dim3(4, 32, NL), 256, SMEMB(64, 128, false, true)>>>(
            p_big, p_mem, p_retr, MEMSZ, MEMSZ, DIM, DIM,
            (long long)NTOK * MEMSZ, (long long)MEMSZ * DIM, (long long)NTOK * DIM,
            1.f, nullptr, nullptr, 0, 0, 0.f, 0, 0, 0);
        // upd[l] += clip(am[l]^T @ xout, 1)
        gemmCP<64, 128, true, true><<<dim3(4, 64, NL), 256, SMEMB(64, 128, true, true)>>>(
            p_big, p_xor, p_upd, NTOK, MEMSZ, DIM, DIM,
            (long long)NTOK * MEMSZ, 0, (long long)MEMSZ * DIM,
            1.f, nullptr, nullptr, 0, 0, 1.f, GFLAG_ACCUM, 0, 0);
        permute_k<<<(NL * ND_ELEMS + 255) / 256, 256>>>(p_retr, p_retrp);
        // outs[e] = xout + retrp @ aggw^T + aggb
        gemmCP<64, 128, false, false><<<dim3(4, 32, 1), 256, SMEMB(64, 128, false, false)>>>(
            p_retrp, p_aggw, xo, NL * DIM, NL * DIM, NL * DIM, DIM, 0, 0, 0,
            1.f, aggb, xo, 0, DIM, 0.f, 0, 0, 0);
    }

    dim3 ggrid(EXP, 16);
    gate_dot_k<<<ggrid, 256>>>(p_out, gg, p_glog);
    gate_softmax_k<<<1, 32>>>(p_glog, out_gw);
    fuse_k<<<(ND_ELEMS + 255) / 256, 256>>>(p_out, out_gw, out_fused);
    memupd_k<<<(LMD_ELEMS + 255) / 256, 256>>>(memories, p_upd, out_mem);

    (void)in_sizes; (void)n_in; (void)out_size;
}

// round 7
// speedup vs baseline: 4.7475x; 1.0555x over previous
#include <cuda_runtime.h>
#include <math.h>
#include <stdint.h>

#define EXP 4
#define NTOK 2048
#define DIM 512
#define NH 8
#define DHEAD 64
#define FFD 2048
#define NL 4
#define MEMSZ 4096

#define ND_ELEMS (NTOK * DIM)
#define LMD_ELEMS (NL * MEMSZ * DIM)

#define GFLAG_RELU 1
#define GFLAG_ACCUM 2
#define GFLAG_TFOUT 4

// ---------------- scratch ----------------
__device__ float g_xln[EXP * NTOK * DIM];
__device__ float g_x[NTOK * DIM];
__device__ float g_qkv[NTOK * 3 * DIM];
__device__ float g_big[(size_t)NH * NTOK * NTOK];
__device__ float g_sa[NTOK * DIM];
__device__ float g_tmp[NTOK * FFD];
__device__ float g_x1[NTOK * DIM];
__device__ float g_x1r[NTOK * DIM];
__device__ float g_xor[NTOK * DIM];
__device__ float g_out[EXP * NTOK * DIM];
__device__ float g_retr[NL * NTOK * DIM];
__device__ float g_retrp[NTOK * NL * DIM];
__device__ float g_upd[NL * MEMSZ * DIM];
__device__ float g_glog[EXP];
// pre-rounded weights
__device__ float g_ipw_r[EXP * 3 * DIM * DIM];
__device__ float g_opw_r[EXP * DIM * DIM];
__device__ float g_w1_r[EXP * FFD * DIM];
__device__ float g_w2_r[EXP * DIM * FFD];
__device__ float g_aggw_r[DIM * NL * DIM];
__device__ float g_mem_r[LMD_ELEMS];

// ---------------- helpers ----------------
__device__ __forceinline__ uint32_t tf(float x) {
    uint32_t u; asm("cvt.rna.tf32.f32 %0, %1;" : "=r"(u) : "f"(x)); return u;
}
__device__ __forceinline__ float tff(float x) { return __uint_as_float(tf(x)); }
__device__ __forceinline__ void mma8(float* c, const uint32_t* a, const uint32_t* b) {
    asm volatile(
        "mma.sync.aligned.m16n8k8.row.col.f32.tf32.tf32.f32 "
        "{%0,%1,%2,%3}, {%4,%5,%6,%7}, {%8,%9}, {%0,%1,%2,%3};"
        : "+f"(c[0]), "+f"(c[1]), "+f"(c[2]), "+f"(c[3])
        : "r"(a[0]), "r"(a[1]), "r"(a[2]), "r"(a[3]), "r"(b[0]), "r"(b[1]));
}
__device__ __forceinline__ void cpa16(uint32_t s, const float* g) {
    asm volatile("cp.async.cg.shared.global [%0], [%1], 16;" :: "r"(s), "l"(g));
}
__device__ __forceinline__ void ldsm4(uint32_t* r, uint32_t a) {
    asm volatile("ldmatrix.sync.aligned.m8n8.x4.shared.b16 {%0,%1,%2,%3}, [%4];"
        : "=r"(r[0]), "=r"(r[1]), "=r"(r[2]), "=r"(r[3]) : "r"(a));
}
__device__ __forceinline__ void ldsm2(uint32_t* r, uint32_t a) {
    asm volatile("ldmatrix.sync.aligned.m8n8.x2.shared.b16 {%0,%1}, [%2];"
        : "=r"(r[0]), "=r"(r[1]) : "r"(a));
}

__global__ void tfround_k(const float* __restrict__ s, float* __restrict__ d, long long n) {
    long long i = (long long)blockIdx.x * 256 + threadIdx.x;
    if (i < n) d[i] = tff(s[i]);
}

// ---------------- cp.async tf32 mma GEMM (inputs pre-rounded to tf32) ----------------
// C[M,Nc] = alpha*op(A)*op(B) (+bias)(relu)(clip)(+resid)(accum)(tfout)
// ATR: A stored [K,M] (M contig). BTR: B stored [K,Nc] (Nc contig). Else K-contig rows.
// remap (rl>0): for !BTR remaps B n-rows; for BTR remaps B k-rows (ctx skip).
template <int MT, int NT, bool ATR, bool BTR>
__global__ void __launch_bounds__(256, 2) gemmCP(
    const float* __restrict__ A, const float* __restrict__ B, float* __restrict__ C,
    int K, int lda, int ldb, int ldc,
    long long aB, long long bB, long long cB,
    float alpha, const float* __restrict__ bias,
    const float* __restrict__ resid, long long residB, int residLd,
    float clipVal, int flags, int rs, int rl)
{
    constexpr int KC = 16;
    constexpr int AST = 20;
    constexpr int MST = MT + 8;
    constexpr int NST = NT + 8;
    constexpr int ASZ = ATR ? KC * MST : MT * AST;
    constexpr int BSZ = BTR ? KC * NST : NT * AST;
    constexpr int STG = ASZ + BSZ;
    constexpr int MI = MT / 32;
    constexpr int NB = NT / 32;

    extern __shared__ float sm[];
    uint32_t smb = (uint32_t)__cvta_generic_to_shared(sm);

    const int t = threadIdx.x, l = t & 31, w = t >> 5;
    const int bz = blockIdx.z;
    A += aB * bz; B += bB * bz; C += cB * bz;
    const int m0 = blockIdx.y * MT, n0 = blockIdx.x * NT;
    const int wm0 = (w >> 2) * (MT / 2), wn0 = (w & 3) * (NT / 4);

    float acc[MI][NB][4];
#pragma unroll
    for (int a = 0; a < MI; a++)
#pragma unroll
        for (int b = 0; b < NB; b++)
#pragma unroll
            for (int c = 0; c < 4; c++) acc[a][b][c] = 0.f;

    const int nK = K / KC;

    auto issue = [&](int s, int k0) {
        uint32_t ab = smb + (uint32_t)(s * STG * 4);
        uint32_t bb = ab + ASZ * 4;
        if (!ATR) {
            constexpr int ACH = MT * 4;
#pragma unroll
            for (int c0 = 0; c0 < ACH; c0 += 256) {
                int c = c0 + t;
                int row = c >> 2, kq = c & 3;
                cpa16(ab + (uint32_t)(row * AST + kq * 4) * 4,
                      &A[(long long)(m0 + row) * lda + k0 + kq * 4]);
            }
        } else {
            constexpr int AQ = MT / 4;
            constexpr int ASH = (MT == 128) ? 5 : 4;
            constexpr int ACH = KC * AQ;
#pragma unroll
            for (int c0 = 0; c0 < ACH; c0 += 256) {
                int c = c0 + t;
                int kr = c >> ASH, mq = c & (AQ - 1);
                cpa16(ab + (uint32_t)(kr * MST + mq * 4) * 4,
                      &A[(long long)(k0 + kr) * lda + m0 + mq * 4]);
            }
        }
        if (!BTR) {
            constexpr int BCH = NT * 4;
#pragma unroll
            for (int c0 = 0; c0 < BCH; c0 += 256) {
                int c = c0 + t;
                int row = c >> 2, kq = c & 3;
                int n = n0 + row;
                if (rl && n >= rs) n += rl;
                cpa16(bb + (uint32_t)(row * AST + kq * 4) * 4,
                      &B[(long long)n * ldb + k0 + kq * 4]);
            }
        } else {
            constexpr int NQ = NT / 4;
            constexpr int SH = (NT == 128) ? 5 : 4;
            constexpr int BCH = KC * NQ;
#pragma unroll
            for (int c0 = 0; c0 < BCH; c0 += 256) {
                int c = c0 + t;
                int kr = c >> SH, nq = c & (NQ - 1);
                int g = k0 + kr;
                if (rl && g >= rs) g += rl;
                cpa16(bb + (uint32_t)(kr * NST + nq * 4) * 4,
                      &B[(long long)g * ldb + n0 + nq * 4]);
            }
        }
        asm volatile("cp.async.commit_group;" ::: "memory");
    };

    issue(0, 0);
    issue(1, KC);
    issue(2, 2 * KC);

    for (int i = 0; i < nK; i++) {
        asm volatile("cp.async.wait_group 2;" ::: "memory");
        __syncthreads();
        if (i + 3 < nK) issue((i + 3) & 3, (i + 3) * KC);

        const float* Ab = sm + (i & 3) * STG;
        const float* Bb = Ab + ASZ;
        uint32_t abu = smb + (uint32_t)((i & 3) * STG * 4);
        uint32_t bbu = abu + (uint32_t)(ASZ * 4);
#pragma unroll
        for (int kk = 0; kk < 2; kk++) {
            const int kc = kk * 8;
            uint32_t af[MI][4], bf[NB][2];
#pragma unroll
            for (int mi = 0; mi < MI; mi++) {
                if (!ATR) {
                    // ldmatrix x4: submatrix s = l>>3: rows +((s&1)*8), k half +((s>>1)*4)
                    uint32_t ad = abu + (uint32_t)(((wm0 + mi * 16 + ((l >> 3 & 1) << 3) + (l & 7)) * AST
                                                   + kc + ((l >> 4) << 2)) * 4);
                    ldsm4(af[mi], ad);
                } else {
                    const uint32_t* ap = (const uint32_t*)&Ab[(kc + (l & 3)) * MST + wm0 + mi * 16 + (l >> 2)];
                    af[mi][0] = ap[0];
                    af[mi][1] = ap[8];
                    af[mi][2] = ap[4 * MST];
                    af[mi][3] = ap[4 * MST + 8];
                }
            }
#pragma unroll
            for (int ni = 0; ni < NB; ni++) {
                if (!BTR) {
                    // ldmatrix x2: submatrix s = l>>3 (lanes 0-15): k half +(s*4)
                    uint32_t bd = bbu + (uint32_t)(((wn0 + ni * 8 + (l & 7)) * AST
                                                   + kc + ((l >> 3 & 1) << 2)) * 4);
                    ldsm2(bf[ni], bd);
                } else {
                    const uint32_t* bp = (const uint32_t*)&Bb[(kc + (l & 3)) * NST + wn0 + ni * 8 + (l >> 2)];
                    bf[ni][0] = bp[0];
                    bf[ni][1] = bp[4 * NST];
                }
            }
#pragma unroll
            for (int mi = 0; mi < MI; mi++)
#pragma unroll
                for (int ni = 0; ni < NB; ni++) mma8(acc[mi][ni], af[mi], bf[ni]);
        }
    }

    // epilogue
#pragma unroll
    for (int mi = 0; mi < MI; mi++) {
        int row0 = m0 + wm0 + mi * 16 + (l >> 2);
#pragma unroll
        for (int ni = 0; ni < NB; ni++) {
            int col = n0 + wn0 + ni * 8 + (l & 3) * 2;
#pragma unroll
            for (int h = 0; h < 2; h++) {
                int row = row0 + h * 8;
                float vx = alpha * acc[mi][ni][h * 2];
                float vy = alpha * acc[mi][ni][h * 2 + 1];
                if (bias) { vx += bias[col]; vy += bias[col + 1]; }
                if (flags & GFLAG_RELU) { vx = fmaxf(vx, 0.f); vy = fmaxf(vy, 0.f); }
                if (clipVal > 0.f) {
                    vx = fminf(fmaxf(vx, -clipVal), clipVal);
                    vy = fminf(fmaxf(vy, -clipVal), clipVal);
                }
                if (resid) {
                    float2 rv = *(const float2*)&resid[residB * bz + (long long)row * residLd + col];
                    vx += rv.x; vy += rv.y;
                }
                float2* cp = (float2*)&C[(long long)row * ldc + col];
                if (flags & GFLAG_ACCUM) {
                    float2 o = *cp;
                    vx += o.x; vy += o.y;
                }
                if (flags & GFLAG_TFOUT) { vx = tff(vx); vy = tff(vy); }
                *cp = make_float2(vx, vy);
            }
        }
    }
}

// ---------------- reductions ----------------
__device__ __forceinline__ float warpReduceSum(float v) {
#pragma unroll
    for (int o = 16; o; o >>= 1) v += __shfl_xor_sync(0xffffffffu, v, o);
    return v;
}
__device__ __forceinline__ float warpReduceMax(float v) {
#pragma unroll
    for (int o = 16; o; o >>= 1) v = fmaxf(v, __shfl_xor_sync(0xffffffffu, v, o));
    return v;
}

// ---------------- smem-cached row softmax (tf32-rounded output) ----------------
__global__ void softmax_k(float* __restrict__ p, int cols) {
    extern __shared__ float sbuf[];
    float* row = p + (long long)blockIdx.x * cols;
    __shared__ float sh[8];
    __shared__ float sb;
    int tid = threadIdx.x, lane = tid & 31, wid = tid >> 5;
    float m = -1e30f;
    for (int i = tid; i < cols; i += 256) { float v = row[i]; sbuf[i] = v; m = fmaxf(m, v); }
    m = warpReduceMax(m);
    if (lane == 0) sh[wid] = m;
    __syncthreads();
    if (tid == 0) { float x = sh[0]; for (int q = 1; q < 8; q++) x = fmaxf(x, sh[q]); sb = x; }
    __syncthreads();
    m = sb;
    float s = 0.f;
    for (int i = tid; i < cols; i += 256) { float v = expf(sbuf[i] - m); sbuf[i] = v; s += v; }
    s = warpReduceSum(s);
    if (lane == 0) sh[wid] = s;
    __syncthreads();
    if (tid == 0) { float x = 0; for (int q = 0; q < 8; q++) x += sh[q]; sb = 1.f / x; }
    __syncthreads();
    float inv = sb;
    for (int i = tid; i < cols; i += 256) row[i] = tff(sbuf[i] * inv);
}

// ---------------- LayerNorm (rounded output) ----------------
__global__ void ln_k(const float* __restrict__ src, float* __restrict__ dst) {
    long long row = blockIdx.x;
    const float* x = src + row * DIM;
    float* y = dst + row * DIM;
    int tid = threadIdx.x, lane = tid & 31, wid = tid >> 5;
    float v[4], s = 0.f, s2 = 0.f;
#pragma unroll
    for (int j = 0; j < 4; j++) { v[j] = x[tid + j * 128]; s += v[j]; s2 += v[j] * v[j]; }
    s = warpReduceSum(s); s2 = warpReduceSum(s2);
    __shared__ float sh[2][4]; __shared__ float mv[2];
    if (lane == 0) { sh[0][wid] = s; sh[1][wid] = s2; }
    __syncthreads();
    if (tid == 0) {
        float a = sh[0][0] + sh[0][1] + sh[0][2] + sh[0][3];
        float b = sh[1][0] + sh[1][1] + sh[1][2] + sh[1][3];
        float mean = a / DIM;
        mv[0] = mean; mv[1] = rsqrtf(b / DIM - mean * mean + 1e-5f);
    }
    __syncthreads();
    float mean = mv[0], rstd = mv[1];
#pragma unroll
    for (int j = 0; j < 4; j++) y[tid + j * 128] = tff((v[j] - mean) * rstd);
}

// dst = LN(a+b)*w + bb (full precision); dstr = tf32-rounded copy
__global__ void ln_ra_k(const float* __restrict__ a, const float* __restrict__ b,
                        const float* __restrict__ w, const float* __restrict__ bb,
                        float* __restrict__ dst, float* __restrict__ dstr) {
    long long row = blockIdx.x;
    const float* xa = a + row * DIM;
    const float* xb = b + row * DIM;
    float* y = dst + row * DIM;
    float* yr = dstr + row * DIM;
    int tid = threadIdx.x, lane = tid & 31, wid = tid >> 5;
    float v[4], s = 0.f, s2 = 0.f;
#pragma unroll
    for (int j = 0; j < 4; j++) {
        int i = tid + j * 128;
        v[j] = xa[i] + xb[i]; s += v[j]; s2 += v[j] * v[j];
    }
    s = warpReduceSum(s); s2 = warpReduceSum(s2);
    __shared__ float sh[2][4]; __shared__ float mv[2];
    if (lane == 0) { sh[0][wid] = s; sh[1][wid] = s2; }
    __syncthreads();
    if (tid == 0) {
        float p = sh[0][0] + sh[0][1] + sh[0][2] + sh[0][3];
        float q = sh[1][0] + sh[1][1] + sh[1][2] + sh[1][3];
        float mean = p / DIM;
        mv[0] = mean; mv[1] = rsqrtf(q / DIM - mean * mean + 1e-5f);
    }
    __syncthreads();
    float mean = mv[0], rstd = mv[1];
#pragma unroll
    for (int j = 0; j < 4; j++) {
        int i = tid + j * 128;
        float o = (v[j] - mean) * rstd * w[i] + bb[i];
        y[i] = o;
        yr[i] = tff(o);
    }
}

__global__ void permute_k(const float* __restrict__ retr, float* __restrict__ rp) {
    long long i = (long long)blockIdx.x * 256 + threadIdx.x;
    if (i < (long long)NL * NTOK * DIM) {
        int d = (int)(i & (DIM - 1));
        long long r = i >> 9;
        int n = (int)(r & (NTOK - 1));
        int l = (int)(r >> 11);
        rp[((long long)n * NL + l) * DIM + d] = tff(retr[i]);
    }
}

__global__ void zero_k(float* __restrict__ p, long long n) {
    long long i = (long long)blockIdx.x * 256 + threadIdx.x;
    if (i < n) p[i] = 0.f;
}

__global__ void gate_dot_k(const float* __restrict__ outs, const float* __restrict__ gg,
                           float* __restrict__ glog) {
    int e = blockIdx.x;
    long long chunk = (long long)ND_ELEMS / gridDim.y;
    long long base = (long long)e * ND_ELEMS + (long long)blockIdx.y * chunk;
    float acc = 0.f;
    for (long long i = threadIdx.x; i < chunk; i += blockDim.x) {
        long long idx = base + i;
        acc += outs[idx] * gg[idx & (DIM - 1)];
    }
    acc = warpReduceSum(acc);
    __shared__ float sh[8];
    int lane = threadIdx.x & 31, wid = threadIdx.x >> 5;
    if (lane == 0) sh[wid] = acc;
    __syncthreads();
    if (threadIdx.x == 0) {
        float x = 0;
        for (int q = 0; q < 8; q++) x += sh[q];
        atomicAdd(&glog[e], x);
    }
}

__global__ void gate_softmax_k(const float* __restrict__ glog, float* __restrict__ gw) {
    if (threadIdx.x == 0) {
        float l[EXP], m = -1e30f;
        for (int e = 0; e < EXP; e++) {
            l[e] = fminf(fmaxf(glog[e] / (float)NTOK, -10.f), 10.f);
            m = fmaxf(m, l[e]);
        }
        float s = 0.f;
        for (int e = 0; e < EXP; e++) { l[e] = expf(l[e] - m); s += l[e]; }
        for (int e = 0; e < EXP; e++) gw[e] = l[e] / s;
    }
}

__global__ void fuse_k(const float* __restrict__ outs, const float* __restrict__ gw,
                       float* __restrict__ fused) {
    long long i = (long long)blockIdx.x * 256 + threadIdx.x;
    if (i < (long long)ND_ELEMS) {
        float r = 0.f;
#pragma unroll
        for (int e = 0; e < EXP; e++) r += gw[e] * outs[(long long)e * ND_ELEMS + i];
        fused[i] = r;
    }
}

__global__ void memupd_k(const float* __restrict__ mem, const float* __restrict__ upd,
                         float* __restrict__ o) {
    long long i = (long long)blockIdx.x * 256 + threadIdx.x;
    if (i < (long long)LMD_ELEMS) {
        float u = 0.1f * upd[i];
        u = fminf(fmaxf(u, -0.1f), 0.1f);
        o[i] = 0.9f * mem[i] + u;
    }
}

// ---------------- host ----------------
static constexpr int stgFl(int MT, int NT, bool ATR, bool BTR) {
    return (ATR ? 16 * (MT + 8) : MT * 20) + (BTR ? 16 * (NT + 8) : NT * 20);
}
#define SMEMB(MT, NT, ATR, BTR) (4 * stgFl(MT, NT, ATR, BTR) * 4)

static void tfround(const float* s, float* d, long long n) {
    tfround_k<<<(int)((n + 255) / 256), 256>>>(s, d, n);
}

extern "C" void kernel_launch(void* const* d_in, const int* in_sizes, int n_in,
                              void* d_out, int out_size) {
    const float* tokens   = (const float*)d_in[0];
    const float* memories = (const float*)d_in[1];
    const float* ipw      = (const float*)d_in[2];
    const float* ipb      = (const float*)d_in[3];
    const float* opw      = (const float*)d_in[4];
    const float* opb      = (const float*)d_in[5];
    const float* w1       = (const float*)d_in[6];
    const float* b1       = (const float*)d_in[7];
    const float* w2       = (const float*)d_in[8];
    const float* b2       = (const float*)d_in[9];
    const float* n1w      = (const float*)d_in[10];
    const float* n1b      = (const float*)d_in[11];
    const float* n2w      = (const float*)d_in[12];
    const float* n2b      = (const float*)d_in[13];
    const float* aggw     = (const float*)d_in[14];
    const float* aggb     = (const float*)d_in[15];
    const float* gg       = (const float*)d_in[16];

    float* out = (float*)d_out;
    float* out_fused = out;
    float* out_gw = out + ND_ELEMS;
    float* out_mem = out + ND_ELEMS + EXP;

    static float *p_xln = nullptr, *p_x = nullptr, *p_qkv = nullptr, *p_big = nullptr,
                 *p_sa = nullptr, *p_tmp = nullptr, *p_x1 = nullptr, *p_x1r = nullptr,
                 *p_xor = nullptr, *p_out = nullptr,
                 *p_retr = nullptr, *p_retrp = nullptr, *p_upd = nullptr, *p_glog = nullptr,
                 *p_ipw = nullptr, *p_opw = nullptr, *p_w1 = nullptr, *p_w2 = nullptr,
                 *p_aggw = nullptr, *p_mem = nullptr;
    if (!p_xln) {
        cudaGetSymbolAddress((void**)&p_xln, g_xln);
        cudaGetSymbolAddress((void**)&p_x, g_x);
        cudaGetSymbolAddress((void**)&p_qkv, g_qkv);
        cudaGetSymbolAddress((void**)&p_big, g_big);
        cudaGetSymbolAddress((void**)&p_sa, g_sa);
        cudaGetSymbolAddress((void**)&p_tmp, g_tmp);
        cudaGetSymbolAddress((void**)&p_x1, g_x1);
        cudaGetSymbolAddress((void**)&p_x1r, g_x1r);
        cudaGetSymbolAddress((void**)&p_xor, g_xor);
        cudaGetSymbolAddress((void**)&p_out, g_out);
        cudaGetSymbolAddress((void**)&p_retr, g_retr);
        cudaGetSymbolAddress((void**)&p_retrp, g_retrp);
        cudaGetSymbolAddress((void**)&p_upd, g_upd);
        cudaGetSymbolAddress((void**)&p_glog, g_glog);
        cudaGetSymbolAddress((void**)&p_ipw, g_ipw_r);
        cudaGetSymbolAddress((void**)&p_opw, g_opw_r);
        cudaGetSymbolAddress((void**)&p_w1, g_w1_r);
        cudaGetSymbolAddress((void**)&p_w2, g_w2_r);
        cudaGetSymbolAddress((void**)&p_aggw, g_aggw_r);
        cudaGetSymbolAddress((void**)&p_mem, g_mem_r);
        cudaFuncSetAttribute(gemmCP<64, 128, false, false>, cudaFuncAttributeMaxDynamicSharedMemorySize, SMEMB(64, 128, false, false));
        cudaFuncSetAttribute(gemmCP<64, 128, false, true>,  cudaFuncAttributeMaxDynamicSharedMemorySize, SMEMB(64, 128, false, true));
        cudaFuncSetAttribute(gemmCP<64, 64, false, true>,   cudaFuncAttributeMaxDynamicSharedMemorySize, SMEMB(64, 64, false, true));
        cudaFuncSetAttribute(gemmCP<64, 128, true, true>,   cudaFuncAttributeMaxDynamicSharedMemorySize, SMEMB(64, 128, true, true));
    }

    const float inv_sqrt_d = 1.0f / sqrtf((float)DIM);
    const float inv_sqrt_dh = 1.0f / sqrtf((float)DHEAD);

    // pre-round weights to tf32 (graph-replay safe: pure function of inputs)
    tfround(ipw, p_ipw, (long long)EXP * 3 * DIM * DIM);
    tfround(opw, p_opw, (long long)EXP * DIM * DIM);
    tfround(w1, p_w1, (long long)EXP * FFD * DIM);
    tfround(w2, p_w2, (long long)EXP * DIM * FFD);
    tfround(aggw, p_aggw, (long long)DIM * NL * DIM);
    tfround(memories, p_mem, (long long)LMD_ELEMS);

    zero_k<<<1, 256>>>(p_glog, EXP);
    ln_k<<<EXP * NTOK, 128>>>(tokens, p_xln);

    for (int e = 0; e < EXP; e++) {
        const float* Ax = p_xln + (long long)e * ND_ELEMS;
        float* xo = p_out + (long long)e * ND_ELEMS;

        // cross logits [2048, 6144] = clip(x @ ctx^T / sqrt(D), 10)
        gemmCP<64, 128, false, false><<<dim3(48, 32, 1), 256, SMEMB(64, 128, false, false)>>>(
            Ax, p_xln, p_big, DIM, DIM, DIM, 3 * NTOK, 0, 0, 0,
            inv_sqrt_d, nullptr, nullptr, 0, 0, 10.f, 0, e * NTOK, NTOK);
        softmax_k<<<NTOK, 256, 3 * NTOK * 4>>>(p_big, 3 * NTOK);
        // x = probs @ ctx + x (rounded out)
        gemmCP<64, 128, false, true><<<dim3(4, 32, 1), 256, SMEMB(64, 128, false, true)>>>(
            p_big, p_xln, p_x, 3 * NTOK, 3 * NTOK, DIM, DIM, 0, 0, 0,
            1.f, nullptr, Ax, 0, DIM, 0.f, GFLAG_TFOUT, e * NTOK, NTOK);
        // qkv [2048, 1536] (rounded out)
        gemmCP<64, 128, false, false><<<dim3(12, 32, 1), 256, SMEMB(64, 128, false, false)>>>(
            p_x, p_ipw + (long long)e * 3 * DIM * DIM, p_qkv, DIM, DIM, DIM, 3 * DIM, 0, 0, 0,
            1.f, ipb + e * 3 * DIM, nullptr, 0, 0, 0.f, GFLAG_TFOUT, 0, 0);
        // scores [h][2048, 2048]
        gemmCP<64, 128, false, false><<<dim3(16, 32, NH), 256, SMEMB(64, 128, false, false)>>>(
            p_qkv, p_qkv + DIM, p_big, DHEAD, 3 * DIM, 3 * DIM, NTOK,
            DHEAD, DHEAD, (long long)NTOK * NTOK,
            inv_sqrt_dh, nullptr, nullptr, 0, 0, 0.f, 0, 0, 0);
        softmax_k<<<NH * NTOK, 256, NTOK * 4>>>(p_big, NTOK);
        // sa[:, h*64:] = probs_h @ v_h (rounded out)
        gemmCP<64, 64, false, true><<<dim3(1, 32, NH), 256, SMEMB(64, 64, false, true)>>>(
            p_big, p_qkv + 2 * DIM, p_sa, NTOK, NTOK, 3 * DIM, DIM,
            (long long)NTOK * NTOK, DHEAD, DHEAD,
            1.f, nullptr, nullptr, 0, 0, 0.f, GFLAG_TFOUT, 0, 0);
        // out_proj (full out; feeds ln_ra only)
        gemmCP<64, 128, false, false><<<dim3(4, 32, 1), 256, SMEMB(64, 128, false, false)>>>(
            p_sa, p_opw + (long long)e * DIM * DIM, p_tmp, DIM, DIM, DIM, DIM, 0, 0, 0,
            1.f, opb + e * DIM, nullptr, 0, 0, 0.f, 0, 0, 0);
        ln_ra_k<<<NTOK, 128>>>(p_x, p_tmp, n1w + e * DIM, n1b + e * DIM, p_x1, p_x1r);
        // ff1 relu (rounded out)
        gemmCP<64, 128, false, false><<<dim3(16, 32, 1), 256, SMEMB(64, 128, false, false)>>>(
            p_x1r, p_w1 + (long long)e * FFD * DIM, p_tmp, DIM, DIM, DIM, FFD, 0, 0, 0,
            1.f, b1 + e * FFD, nullptr, 0, 0, 0.f, GFLAG_RELU | GFLAG_TFOUT, 0, 0);
        // ff2 (full out; feeds ln_ra only)
        gemmCP<64, 128, false, false><<<dim3(4, 32, 1), 256, SMEMB(64, 128, false, false)>>>(
            p_tmp, p_w2 + (long long)e * DIM * FFD, p_sa, FFD, FFD, FFD, DIM, 0, 0, 0,
            1.f, b2 + e * DIM, nullptr, 0, 0, 0.f, 0, 0, 0);
        ln_ra_k<<<NTOK, 128>>>(p_x1, p_sa, n2w + e * DIM, n2b + e * DIM, xo, p_xor);
        // memory logits [l][2048, 4096]
        gemmCP<64, 128, false, false><<<dim3(32, 32, NL), 256, SMEMB(64, 128, false, false)>>>(
            p_xor, p_mem, p_big, DIM, DIM, DIM, MEMSZ,
            0, (long long)MEMSZ * DIM, (long long)NTOK * MEMSZ,
            inv_sqrt_d, nullptr, nullptr, 0, 0, 10.f, 0, 0, 0);
        softmax_k<<<NL * NTOK, 256, MEMSZ * 4>>>(p_big, MEMSZ);
        // retr[l] = am[l] @ mem_l
        gemmCP<64, 128, false, true><<<dim3(4, 32, NL), 256, SMEMB(64, 128, false, true)>>>(
            p_big, p_mem, p_retr, MEMSZ, MEMSZ, DIM, DIM,
            (long long)NTOK * MEMSZ, (long long)MEMSZ * DIM, (long long)NTOK * DIM,
            1.f, nullptr, nullptr, 0, 0, 0.f, 0, 0, 0);
        // upd[l] (+)= clip(am[l]^T @ xout, 1)  — e=0 writes (no zero pass needed)
        gemmCP<64, 128, true, true><<<dim3(4, 64, NL), 256, SMEMB(64, 128, true, true)>>>(
            p_big, p_xor, p_upd, NTOK, MEMSZ, DIM, DIM,
            (long long)NTOK * MEMSZ, 0, (long long)MEMSZ * DIM,
            1.f, nullptr, nullptr, 0, 0, 1.f, e == 0 ? 0 : GFLAG_ACCUM, 0, 0);
        permute_k<<<(NL * ND_ELEMS + 255) / 256, 256>>>(p_retr, p_retrp);
        // outs[e] = xout + retrp @ aggw^T + aggb
        gemmCP<64, 128, false, false><<<dim3(4, 32, 1), 256, SMEMB(64, 128, false, false)>>>(
            p_retrp, p_aggw, xo, NL * DIM, NL * DIM, NL * DIM, DIM, 0, 0, 0,
            1.f, aggb, xo, 0, DIM, 0.f, 0, 0, 0);
    }

    dim3 ggrid(EXP, 16);
    gate_dot_k<<<ggrid, 256>>>(p_out, gg, p_glog);
    gate_softmax_k<<<1, 32>>>(p_glog, out_gw);
    fuse_k<<<(ND_ELEMS + 255) / 256, 256>>>(p_out, out_gw, out_fused);
    memupd_k<<<(LMD_ELEMS + 255) / 256, 256>>>(memories, p_upd, out_mem);

    (void)in_sizes; (void)n_in; (void)out_size;
}

// round 8
// speedup vs baseline: 4.9259x; 1.0376x over previous
#include <cuda_runtime.h>
#include <math.h>
#include <stdint.h>

#define EXP 4
#define NTOK 2048
#define DIM 512
#define NH 8
#define DHEAD 64
#define FFD 2048
#define NL 4
#define MEMSZ 4096

#define ND_ELEMS (NTOK * DIM)
#define LMD_ELEMS (NL * MEMSZ * DIM)

#define GFLAG_RELU 1
#define GFLAG_ACCUM 2
#define GFLAG_TFOUT 4

// ---------------- scratch ----------------
__device__ float g_xln[EXP * NTOK * DIM];
__device__ float g_x[NTOK * DIM];
__device__ float g_qkv[NTOK * 3 * DIM];
__device__ float g_big[(size_t)NH * NTOK * NTOK];
__device__ float g_sa[NTOK * DIM];
__device__ float g_tmp[NTOK * FFD];
__device__ float g_x1[NTOK * DIM];
__device__ float g_x1r[NTOK * DIM];
__device__ float g_xor[NTOK * DIM];
__device__ float g_out[EXP * NTOK * DIM];
__device__ float g_retr[NL * NTOK * DIM];
__device__ float g_retrp[NTOK * NL * DIM];
__device__ float g_upd[NL * MEMSZ * DIM];
__device__ float g_glog[EXP];
// pre-rounded weights
__device__ float g_ipw_r[EXP * 3 * DIM * DIM];
__device__ float g_opw_r[EXP * DIM * DIM];
__device__ float g_w1_r[EXP * FFD * DIM];
__device__ float g_w2_r[EXP * DIM * FFD];
__device__ float g_aggw_r[DIM * NL * DIM];
__device__ float g_mem_r[LMD_ELEMS];

// ---------------- helpers ----------------
__device__ __forceinline__ uint32_t tf(float x) {
    uint32_t u; asm("cvt.rna.tf32.f32 %0, %1;" : "=r"(u) : "f"(x)); return u;
}
__device__ __forceinline__ float tff(float x) { return __uint_as_float(tf(x)); }
__device__ __forceinline__ void mma8(float* c, const uint32_t* a, const uint32_t* b) {
    asm volatile(
        "mma.sync.aligned.m16n8k8.row.col.f32.tf32.tf32.f32 "
        "{%0,%1,%2,%3}, {%4,%5,%6,%7}, {%8,%9}, {%0,%1,%2,%3};"
        : "+f"(c[0]), "+f"(c[1]), "+f"(c[2]), "+f"(c[3])
        : "r"(a[0]), "r"(a[1]), "r"(a[2]), "r"(a[3]), "r"(b[0]), "r"(b[1]));
}
__device__ __forceinline__ void cpa16(uint32_t s, const float* g) {
    asm volatile("cp.async.cg.shared.global [%0], [%1], 16;" :: "r"(s), "l"(g));
}
__device__ __forceinline__ void ldsm4(uint32_t* r, uint32_t a) {
    asm volatile("ldmatrix.sync.aligned.m8n8.x4.shared.b16 {%0,%1,%2,%3}, [%4];"
        : "=r"(r[0]), "=r"(r[1]), "=r"(r[2]), "=r"(r[3]) : "r"(a));
}

__global__ void tfround_k(const float* __restrict__ s, float* __restrict__ d, long long n) {
    long long i = (long long)blockIdx.x * 256 + threadIdx.x;
    if (i < n) d[i] = tff(s[i]);
}

// ---------------- cp.async tf32 mma GEMM (inputs pre-rounded to tf32) ----------------
// C[M,Nc] = alpha*op(A)*op(B) (+bias)(relu)(clip)(+resid)(accum)(tfout)
// ATR: A stored [K,M] (M contig). BTR: B stored [K,Nc] (Nc contig). Else K-contig rows.
// remap (rl>0): for !BTR remaps B n-rows; for BTR remaps B k-rows (ctx skip).
template <int MT, int NT, bool ATR, bool BTR, int OCC>
__global__ void __launch_bounds__(256, OCC) gemmCP(
    const float* __restrict__ A, const float* __restrict__ B, float* __restrict__ C,
    int K, int lda, int ldb, int ldc,
    long long aB, long long bB, long long cB,
    float alpha, const float* __restrict__ bias,
    const float* __restrict__ resid, long long residB, int residLd,
    float clipVal, int flags, int rs, int rl)
{
    constexpr int KC = 16;
    constexpr int AST = 20;
    constexpr int MST = MT + 8;
    constexpr int NST = NT + 8;
    constexpr int ASZ = ATR ? KC * MST : MT * AST;
    constexpr int BSZ = BTR ? KC * NST : NT * AST;
    constexpr int STG = ASZ + BSZ;
    constexpr int MI = MT / 32;
    constexpr int NB = NT / 32;

    extern __shared__ float sm[];
    uint32_t smb = (uint32_t)__cvta_generic_to_shared(sm);

    const int t = threadIdx.x, l = t & 31, w = t >> 5;
    const int bz = blockIdx.z;
    A += aB * bz; B += bB * bz; C += cB * bz;
    const int m0 = blockIdx.y * MT, n0 = blockIdx.x * NT;
    const int wm0 = (w >> 2) * (MT / 2), wn0 = (w & 3) * (NT / 4);

    // precomputed per-thread fragment base offsets (bytes)
    const uint32_t aBase = (uint32_t)(((wm0 + ((l >> 3 & 1) << 3) + (l & 7)) * AST + ((l >> 4) << 2)) * 4);
    const uint32_t bBase4 = (uint32_t)(((wn0 + ((l >> 4) << 3) + (l & 7)) * AST + ((l >> 3 & 1) << 2)) * 4);
    const int atrOff = (l & 3) * MST + wm0 + (l >> 2);
    const int btrOff = (l & 3) * NST + wn0 + (l >> 2);

    float acc[MI][NB][4];
#pragma unroll
    for (int a = 0; a < MI; a++)
#pragma unroll
        for (int b = 0; b < NB; b++)
#pragma unroll
            for (int c = 0; c < 4; c++) acc[a][b][c] = 0.f;

    const int nK = K / KC;

    auto issue = [&](int s, int k0) {
        uint32_t ab = smb + (uint32_t)(s * STG * 4);
        uint32_t bb = ab + ASZ * 4;
        if (!ATR) {
            constexpr int ACH = MT * 4;
#pragma unroll
            for (int c0 = 0; c0 < ACH; c0 += 256) {
                int c = c0 + t;
                int row = c >> 2, kq = c & 3;
                cpa16(ab + (uint32_t)(row * AST + kq * 4) * 4,
                      &A[(long long)(m0 + row) * lda + k0 + kq * 4]);
            }
        } else {
            constexpr int AQ = MT / 4;
            constexpr int ASH = (MT == 128) ? 5 : 4;
            constexpr int ACH = KC * AQ;
#pragma unroll
            for (int c0 = 0; c0 < ACH; c0 += 256) {
                int c = c0 + t;
                int kr = c >> ASH, mq = c & (AQ - 1);
                cpa16(ab + (uint32_t)(kr * MST + mq * 4) * 4,
                      &A[(long long)(k0 + kr) * lda + m0 + mq * 4]);
            }
        }
        if (!BTR) {
            constexpr int BCH = NT * 4;
#pragma unroll
            for (int c0 = 0; c0 < BCH; c0 += 256) {
                int c = c0 + t;
                int row = c >> 2, kq = c & 3;
                int n = n0 + row;
                if (rl && n >= rs) n += rl;
                cpa16(bb + (uint32_t)(row * AST + kq * 4) * 4,
                      &B[(long long)n * ldb + k0 + kq * 4]);
            }
        } else {
            constexpr int NQ = NT / 4;
            constexpr int SH = (NT == 128) ? 5 : 4;
            constexpr int BCH = KC * NQ;
#pragma unroll
            for (int c0 = 0; c0 < BCH; c0 += 256) {
                int c = c0 + t;
                int kr = c >> SH, nq = c & (NQ - 1);
                int g = k0 + kr;
                if (rl && g >= rs) g += rl;
                cpa16(bb + (uint32_t)(kr * NST + nq * 4) * 4,
                      &B[(long long)g * ldb + n0 + nq * 4]);
            }
        }
        asm volatile("cp.async.commit_group;" ::: "memory");
    };

    issue(0, 0);
    issue(1, KC);
    issue(2, 2 * KC);

    for (int i = 0; i < nK; i++) {
        asm volatile("cp.async.wait_group 2;" ::: "memory");
        __syncthreads();
        if (i + 3 < nK) issue((i + 3) & 3, (i + 3) * KC);

        const float* Ab = sm + (i & 3) * STG;
        const float* Bb = Ab + ASZ;
        uint32_t abu = smb + (uint32_t)((i & 3) * STG * 4);
        uint32_t bbu = abu + (uint32_t)(ASZ * 4);
#pragma unroll
        for (int kk = 0; kk < 2; kk++) {
            const int kc = kk * 8;
            uint32_t af[MI][4], bf[NB][2];
#pragma unroll
            for (int mi = 0; mi < MI; mi++) {
                if (!ATR) {
                    ldsm4(af[mi], abu + aBase + (uint32_t)((mi * 16 * AST + kc) * 4));
                } else {
                    const uint32_t* ap = (const uint32_t*)&Ab[kc * MST + atrOff + mi * 16];
                    af[mi][0] = ap[0];
                    af[mi][1] = ap[8];
                    af[mi][2] = ap[4 * MST];
                    af[mi][3] = ap[4 * MST + 8];
                }
            }
            if (!BTR) {
#pragma unroll
                for (int nj = 0; nj < NB / 2; nj++) {
                    uint32_t r4[4];
                    ldsm4(r4, bbu + bBase4 + (uint32_t)((nj * 16 * AST + kc) * 4));
                    bf[2 * nj][0] = r4[0]; bf[2 * nj][1] = r4[1];
                    bf[2 * nj + 1][0] = r4[2]; bf[2 * nj + 1][1] = r4[3];
                }
            } else {
#pragma unroll
                for (int ni = 0; ni < NB; ni++) {
                    const uint32_t* bp = (const uint32_t*)&Bb[kc * NST + btrOff + ni * 8];
                    bf[ni][0] = bp[0];
                    bf[ni][1] = bp[4 * NST];
                }
            }
#pragma unroll
            for (int mi = 0; mi < MI; mi++)
#pragma unroll
                for (int ni = 0; ni < NB; ni++) mma8(acc[mi][ni], af[mi], bf[ni]);
        }
    }

    // epilogue
#pragma unroll
    for (int mi = 0; mi < MI; mi++) {
        int row0 = m0 + wm0 + mi * 16 + (l >> 2);
#pragma unroll
        for (int ni = 0; ni < NB; ni++) {
            int col = n0 + wn0 + ni * 8 + (l & 3) * 2;
#pragma unroll
            for (int h = 0; h < 2; h++) {
                int row = row0 + h * 8;
                float vx = alpha * acc[mi][ni][h * 2];
                float vy = alpha * acc[mi][ni][h * 2 + 1];
                if (bias) { vx += bias[col]; vy += bias[col + 1]; }
                if (flags & GFLAG_RELU) { vx = fmaxf(vx, 0.f); vy = fmaxf(vy, 0.f); }
                if (clipVal > 0.f) {
                    vx = fminf(fmaxf(vx, -clipVal), clipVal);
                    vy = fminf(fmaxf(vy, -clipVal), clipVal);
                }
                if (resid) {
                    float2 rv = *(const float2*)&resid[residB * bz + (long long)row * residLd + col];
                    vx += rv.x; vy += rv.y;
                }
                float2* cp = (float2*)&C[(long long)row * ldc + col];
                if (flags & GFLAG_ACCUM) {
                    float2 o = *cp;
                    vx += o.x; vy += o.y;
                }
                if (flags & GFLAG_TFOUT) { vx = tff(vx); vy = tff(vy); }
                *cp = make_float2(vx, vy);
            }
        }
    }
}

// ---------------- reductions ----------------
__device__ __forceinline__ float warpReduceSum(float v) {
#pragma unroll
    for (int o = 16; o; o >>= 1) v += __shfl_xor_sync(0xffffffffu, v, o);
    return v;
}
__device__ __forceinline__ float warpReduceMax(float v) {
#pragma unroll
    for (int o = 16; o; o >>= 1) v = fmaxf(v, __shfl_xor_sync(0xffffffffu, v, o));
    return v;
}

// ---------------- smem-cached row softmax (tf32-rounded output) ----------------
__global__ void softmax_k(float* __restrict__ p, int cols) {
    extern __shared__ float sbuf[];
    float* row = p + (long long)blockIdx.x * cols;
    __shared__ float sh[8];
    __shared__ float sb;
    int tid = threadIdx.x, lane = tid & 31, wid = tid >> 5;
    float m = -1e30f;
    for (int i = tid; i < cols; i += 256) { float v = row[i]; sbuf[i] = v; m = fmaxf(m, v); }
    m = warpReduceMax(m);
    if (lane == 0) sh[wid] = m;
    __syncthreads();
    if (tid == 0) { float x = sh[0]; for (int q = 1; q < 8; q++) x = fmaxf(x, sh[q]); sb = x; }
    __syncthreads();
    m = sb;
    float s = 0.f;
    for (int i = tid; i < cols; i += 256) { float v = expf(sbuf[i] - m); sbuf[i] = v; s += v; }
    s = warpReduceSum(s);
    if (lane == 0) sh[wid] = s;
    __syncthreads();
    if (tid == 0) { float x = 0; for (int q = 0; q < 8; q++) x += sh[q]; sb = 1.f / x; }
    __syncthreads();
    float inv = sb;
    for (int i = tid; i < cols; i += 256) row[i] = tff(sbuf[i] * inv);
}

// ---------------- LayerNorm (rounded output) ----------------
__global__ void ln_k(const float* __restrict__ src, float* __restrict__ dst) {
    long long row = blockIdx.x;
    const float* x = src + row * DIM;
    float* y = dst + row * DIM;
    int tid = threadIdx.x, lane = tid & 31, wid = tid >> 5;
    float v[4], s = 0.f, s2 = 0.f;
#pragma unroll
    for (int j = 0; j < 4; j++) { v[j] = x[tid + j * 128]; s += v[j]; s2 += v[j] * v[j]; }
    s = warpReduceSum(s); s2 = warpReduceSum(s2);
    __shared__ float sh[2][4]; __shared__ float mv[2];
    if (lane == 0) { sh[0][wid] = s; sh[1][wid] = s2; }
    __syncthreads();
    if (tid == 0) {
        float a = sh[0][0] + sh[0][1] + sh[0][2] + sh[0][3];
        float b = sh[1][0] + sh[1][1] + sh[1][2] + sh[1][3];
        float mean = a / DIM;
        mv[0] = mean; mv[1] = rsqrtf(b / DIM - mean * mean + 1e-5f);
    }
    __syncthreads();
    float mean = mv[0], rstd = mv[1];
#pragma unroll
    for (int j = 0; j < 4; j++) y[tid + j * 128] = tff((v[j] - mean) * rstd);
}

// dst = LN(a+b)*w + bb (full precision); dstr = tf32-rounded copy
__global__ void ln_ra_k(const float* __restrict__ a, const float* __restrict__ b,
                        const float* __restrict__ w, const float* __restrict__ bb,
                        float* __restrict__ dst, float* __restrict__ dstr) {
    long long row = blockIdx.x;
    const float* xa = a + row * DIM;
    const float* xb = b + row * DIM;
    float* y = dst + row * DIM;
    float* yr = dstr + row * DIM;
    int tid = threadIdx.x, lane = tid & 31, wid = tid >> 5;
    float v[4], s = 0.f, s2 = 0.f;
#pragma unroll
    for (int j = 0; j < 4; j++) {
        int i = tid + j * 128;
        v[j] = xa[i] + xb[i]; s += v[j]; s2 += v[j] * v[j];
    }
    s = warpReduceSum(s); s2 = warpReduceSum(s2);
    __shared__ float sh[2][4]; __shared__ float mv[2];
    if (lane == 0) { sh[0][wid] = s; sh[1][wid] = s2; }
    __syncthreads();
    if (tid == 0) {
        float p = sh[0][0] + sh[0][1] + sh[0][2] + sh[0][3];
        float q = sh[1][0] + sh[1][1] + sh[1][2] + sh[1][3];
        float mean = p / DIM;
        mv[0] = mean; mv[1] = rsqrtf(q / DIM - mean * mean + 1e-5f);
    }
    __syncthreads();
    float mean = mv[0], rstd = mv[1];
#pragma unroll
    for (int j = 0; j < 4; j++) {
        int i = tid + j * 128;
        float o = (v[j] - mean) * rstd * w[i] + bb[i];
        y[i] = o;
        yr[i] = tff(o);
    }
}

__global__ void permute_k(const float* __restrict__ retr, float* __restrict__ rp) {
    long long i = (long long)blockIdx.x * 256 + threadIdx.x;
    if (i < (long long)NL * NTOK * DIM) {
        int d = (int)(i & (DIM - 1));
        long long r = i >> 9;
        int n = (int)(r & (NTOK - 1));
        int l = (int)(r >> 11);
        rp[((long long)n * NL + l) * DIM + d] = tff(retr[i]);
    }
}

__global__ void zero_k(float* __restrict__ p, long long n) {
    long long i = (long long)blockIdx.x * 256 + threadIdx.x;
    if (i < n) p[i] = 0.f;
}

__global__ void gate_dot_k(const float* __restrict__ outs, const float* __restrict__ gg,
                           float* __restrict__ glog) {
    int e = blockIdx.x;
    long long chunk = (long long)ND_ELEMS / gridDim.y;
    long long base = (long long)e * ND_ELEMS + (long long)blockIdx.y * chunk;
    float acc = 0.f;
    for (long long i = threadIdx.x; i < chunk; i += blockDim.x) {
        long long idx = base + i;
        acc += outs[idx] * gg[idx & (DIM - 1)];
    }
    acc = warpReduceSum(acc);
    __shared__ float sh[8];
    int lane = threadIdx.x & 31, wid = threadIdx.x >> 5;
    if (lane == 0) sh[wid] = acc;
    __syncthreads();
    if (threadIdx.x == 0) {
        float x = 0;
        for (int q = 0; q < 8; q++) x += sh[q];
        atomicAdd(&glog[e], x);
    }
}

__global__ void gate_softmax_k(const float* __restrict__ glog, float* __restrict__ gw) {
    if (threadIdx.x == 0) {
        float l[EXP], m = -1e30f;
        for (int e = 0; e < EXP; e++) {
            l[e] = fminf(fmaxf(glog[e] / (float)NTOK, -10.f), 10.f);
            m = fmaxf(m, l[e]);
        }
        float s = 0.f;
        for (int e = 0; e < EXP; e++) { l[e] = expf(l[e] - m); s += l[e]; }
        for (int e = 0; e < EXP; e++) gw[e] = l[e] / s;
    }
}

__global__ void fuse_k(const float* __restrict__ outs, const float* __restrict__ gw,
                       float* __restrict__ fused) {
    long long i = (long long)blockIdx.x * 256 + threadIdx.x;
    if (i < (long long)ND_ELEMS) {
        float r = 0.f;
#pragma unroll
        for (int e = 0; e < EXP; e++) r += gw[e] * outs[(long long)e * ND_ELEMS + i];
        fused[i] = r;
    }
}

__global__ void memupd_k(const float* __restrict__ mem, const float* __restrict__ upd,
                         float* __restrict__ o) {
    long long i = (long long)blockIdx.x * 256 + threadIdx.x;
    if (i < (long long)LMD_ELEMS) {
        float u = 0.1f * upd[i];
        u = fminf(fmaxf(u, -0.1f), 0.1f);
        o[i] = 0.9f * mem[i] + u;
    }
}

// ---------------- host ----------------
static constexpr int stgFl(int MT, int NT, bool ATR, bool BTR) {
    return (ATR ? 16 * (MT + 8) : MT * 20) + (BTR ? 16 * (NT + 8) : NT * 20);
}
#define SMEMB(MT, NT, ATR, BTR) (4 * stgFl(MT, NT, ATR, BTR) * 4)

static void tfround(const float* s, float* d, long long n) {
    tfround_k<<<(int)((n + 255) / 256), 256>>>(s, d, n);
}

extern "C" void kernel_launch(void* const* d_in, const int* in_sizes, int n_in,
                              void* d_out, int out_size) {
    const float* tokens   = (const float*)d_in[0];
    const float* memories = (const float*)d_in[1];
    const float* ipw      = (const float*)d_in[2];
    const float* ipb      = (const float*)d_in[3];
    const float* opw      = (const float*)d_in[4];
    const float* opb      = (const float*)d_in[5];
    const float* w1       = (const float*)d_in[6];
    const float* b1       = (const float*)d_in[7];
    const float* w2       = (const float*)d_in[8];
    const float* b2       = (const float*)d_in[9];
    const float* n1w      = (const float*)d_in[10];
    const float* n1b      = (const float*)d_in[11];
    const float* n2w      = (const float*)d_in[12];
    const float* n2b      = (const float*)d_in[13];
    const float* aggw     = (const float*)d_in[14];
    const float* aggb     = (const float*)d_in[15];
    const float* gg       = (const float*)d_in[16];

    float* out = (float*)d_out;
    float* out_fused = out;
    float* out_gw = out + ND_ELEMS;
    float* out_mem = out + ND_ELEMS + EXP;

    static float *p_xln = nullptr, *p_x = nullptr, *p_qkv = nullptr, *p_big = nullptr,
                 *p_sa = nullptr, *p_tmp = nullptr, *p_x1 = nullptr, *p_x1r = nullptr,
                 *p_xor = nullptr, *p_out = nullptr,
                 *p_retr = nullptr, *p_retrp = nullptr, *p_upd = nullptr, *p_glog = nullptr,
                 *p_ipw = nullptr, *p_opw = nullptr, *p_w1 = nullptr, *p_w2 = nullptr,
                 *p_aggw = nullptr, *p_mem = nullptr;
    if (!p_xln) {
        cudaGetSymbolAddress((void**)&p_xln, g_xln);
        cudaGetSymbolAddress((void**)&p_x, g_x);
        cudaGetSymbolAddress((void**)&p_qkv, g_qkv);
        cudaGetSymbolAddress((void**)&p_big, g_big);
        cudaGetSymbolAddress((void**)&p_sa, g_sa);
        cudaGetSymbolAddress((void**)&p_tmp, g_tmp);
        cudaGetSymbolAddress((void**)&p_x1, g_x1);
        cudaGetSymbolAddress((void**)&p_x1r, g_x1r);
        cudaGetSymbolAddress((void**)&p_xor, g_xor);
        cudaGetSymbolAddress((void**)&p_out, g_out);
        cudaGetSymbolAddress((void**)&p_retr, g_retr);
        cudaGetSymbolAddress((void**)&p_retrp, g_retrp);
        cudaGetSymbolAddress((void**)&p_upd, g_upd);
        cudaGetSymbolAddress((void**)&p_glog, g_glog);
        cudaGetSymbolAddress((void**)&p_ipw, g_ipw_r);
        cudaGetSymbolAddress((void**)&p_opw, g_opw_r);
        cudaGetSymbolAddress((void**)&p_w1, g_w1_r);
        cudaGetSymbolAddress((void**)&p_w2, g_w2_r);
        cudaGetSymbolAddress((void**)&p_aggw, g_aggw_r);
        cudaGetSymbolAddress((void**)&p_mem, g_mem_r);
        cudaFuncSetAttribute(gemmCP<64, 128, false, false, 3>, cudaFuncAttributeMaxDynamicSharedMemorySize, SMEMB(64, 128, false, false));
        cudaFuncSetAttribute(gemmCP<64, 128, false, true, 2>,  cudaFuncAttributeMaxDynamicSharedMemorySize, SMEMB(64, 128, false, true));
        cudaFuncSetAttribute(gemmCP<64, 64, false, true, 2>,   cudaFuncAttributeMaxDynamicSharedMemorySize, SMEMB(64, 64, false, true));
        cudaFuncSetAttribute(gemmCP<64, 128, true, true, 2>,   cudaFuncAttributeMaxDynamicSharedMemorySize, SMEMB(64, 128, true, true));
    }

    const float inv_sqrt_d = 1.0f / sqrtf((float)DIM);
    const float inv_sqrt_dh = 1.0f / sqrtf((float)DHEAD);

    // pre-round weights to tf32 (graph-replay safe: pure function of inputs)
    tfround(ipw, p_ipw, (long long)EXP * 3 * DIM * DIM);
    tfround(opw, p_opw, (long long)EXP * DIM * DIM);
    tfround(w1, p_w1, (long long)EXP * FFD * DIM);
    tfround(w2, p_w2, (long long)EXP * DIM * FFD);
    tfround(aggw, p_aggw, (long long)DIM * NL * DIM);
    tfround(memories, p_mem, (long long)LMD_ELEMS);

    zero_k<<<1, 256>>>(p_glog, EXP);
    ln_k<<<EXP * NTOK, 128>>>(tokens, p_xln);

    for (int e = 0; e < EXP; e++) {
        const float* Ax = p_xln + (long long)e * ND_ELEMS;
        float* xo = p_out + (long long)e * ND_ELEMS;

        // cross logits [2048, 6144] = clip(x @ ctx^T / sqrt(D), 10)
        gemmCP<64, 128, false, false, 3><<<dim3(48, 32, 1), 256, SMEMB(64, 128, false, false)>>>(
            Ax, p_xln, p_big, DIM, DIM, DIM, 3 * NTOK, 0, 0, 0,
            inv_sqrt_d, nullptr, nullptr, 0, 0, 10.f, 0, e * NTOK, NTOK);
        softmax_k<<<NTOK, 256, 3 * NTOK * 4>>>(p_big, 3 * NTOK);
        // x = probs @ ctx + x (rounded out)
        gemmCP<64, 128, false, true, 2><<<dim3(4, 32, 1), 256, SMEMB(64, 128, false, true)>>>(
            p_big, p_xln, p_x, 3 * NTOK, 3 * NTOK, DIM, DIM, 0, 0, 0,
            1.f, nullptr, Ax, 0, DIM, 0.f, GFLAG_TFOUT, e * NTOK, NTOK);
        // qkv [2048, 1536] (rounded out)
        gemmCP<64, 128, false, false, 3><<<dim3(12, 32, 1), 256, SMEMB(64, 128, false, false)>>>(
            p_x, p_ipw + (long long)e * 3 * DIM * DIM, p_qkv, DIM, DIM, DIM, 3 * DIM, 0, 0, 0,
            1.f, ipb + e * 3 * DIM, nullptr, 0, 0, 0.f, GFLAG_TFOUT, 0, 0);
        // scores [h][2048, 2048]
        gemmCP<64, 128, false, false, 3><<<dim3(16, 32, NH), 256, SMEMB(64, 128, false, false)>>>(
            p_qkv, p_qkv + DIM, p_big, DHEAD, 3 * DIM, 3 * DIM, NTOK,
            DHEAD, DHEAD, (long long)NTOK * NTOK,
            inv_sqrt_dh, nullptr, nullptr, 0, 0, 0.f, 0, 0, 0);
        softmax_k<<<NH * NTOK, 256, NTOK * 4>>>(p_big, NTOK);
        // sa[:, h*64:] = probs_h @ v_h (rounded out)
        gemmCP<64, 64, false, true, 2><<<dim3(1, 32, NH), 256, SMEMB(64, 64, false, true)>>>(
            p_big, p_qkv + 2 * DIM, p_sa, NTOK, NTOK, 3 * DIM, DIM,
            (long long)NTOK * NTOK, DHEAD, DHEAD,
            1.f, nullptr, nullptr, 0, 0, 0.f, GFLAG_TFOUT, 0, 0);
        // out_proj (full out; feeds ln_ra only)
        gemmCP<64, 128, false, false, 3><<<dim3(4, 32, 1), 256, SMEMB(64, 128, false, false)>>>(
            p_sa, p_opw + (long long)e * DIM * DIM, p_tmp, DIM, DIM, DIM, DIM, 0, 0, 0,
            1.f, opb + e * DIM, nullptr, 0, 0, 0.f, 0, 0, 0);
        ln_ra_k<<<NTOK, 128>>>(p_x, p_tmp, n1w + e * DIM, n1b + e * DIM, p_x1, p_x1r);
        // ff1 relu (rounded out)
        gemmCP<64, 128, false, false, 3><<<dim3(16, 32, 1), 256, SMEMB(64, 128, false, false)>>>(
            p_x1r, p_w1 + (long long)e * FFD * DIM, p_tmp, DIM, DIM, DIM, FFD, 0, 0, 0,
            1.f, b1 + e * FFD, nullptr, 0, 0, 0.f, GFLAG_RELU | GFLAG_TFOUT, 0, 0);
        // ff2 (full out; feeds ln_ra only)
        gemmCP<64, 128, false, false, 3><<<dim3(4, 32, 1), 256, SMEMB(64, 128, false, false)>>>(
            p_tmp, p_w2 + (long long)e * DIM * FFD, p_sa, FFD, FFD, FFD, DIM, 0, 0, 0,
            1.f, b2 + e * DIM, nullptr, 0, 0, 0.f, 0, 0, 0);
        ln_ra_k<<<NTOK, 128>>>(p_x1, p_sa, n2w + e * DIM, n2b + e * DIM, xo, p_xor);
        // memory logits [l][2048, 4096]
        gemmCP<64, 128, false, false, 3><<<dim3(32, 32, NL), 256, SMEMB(64, 128, false, false)>>>(
            p_xor, p_mem, p_big, DIM, DIM, DIM, MEMSZ,
            0, (long long)MEMSZ * DIM, (long long)NTOK * MEMSZ,
            inv_sqrt_d, nullptr, nullptr, 0, 0, 10.f, 0, 0, 0);
        softmax_k<<<NL * NTOK, 256, MEMSZ * 4>>>(p_big, MEMSZ);
        // retr[l] = am[l] @ mem_l
        gemmCP<64, 128, false, true, 2><<<dim3(4, 32, NL), 256, SMEMB(64, 128, false, true)>>>(
            p_big, p_mem, p_retr, MEMSZ, MEMSZ, DIM, DIM,
            (long long)NTOK * MEMSZ, (long long)MEMSZ * DIM, (long long)NTOK * DIM,
            1.f, nullptr, nullptr, 0, 0, 0.f, 0, 0, 0);
        // upd[l] (+)= clip(am[l]^T @ xout, 1)  — e=0 writes (no zero pass needed)
        gemmCP<64, 128, true, true, 2><<<dim3(4, 64, NL), 256, SMEMB(64, 128, true, true)>>>(
            p_big, p_xor, p_upd, NTOK, MEMSZ, DIM, DIM,
            (long long)NTOK * MEMSZ, 0, (long long)MEMSZ * DIM,
            1.f, nullptr, nullptr, 0, 0, 1.f, e == 0 ? 0 : GFLAG_ACCUM, 0, 0);
        permute_k<<<(NL * ND_ELEMS + 255) / 256, 256>>>(p_retr, p_retrp);
        // outs[e] = xout + retrp @ aggw^T + aggb
        gemmCP<64, 128, false, false, 3><<<dim3(4, 32, 1), 256, SMEMB(64, 128, false, false)>>>(
            p_retrp, p_aggw, xo, NL * DIM, NL * DIM, NL * DIM, DIM, 0, 0, 0,
            1.f, aggb, xo, 0, DIM, 0.f, 0, 0, 0);
    }

    dim3 ggrid(EXP, 16);
    gate_dot_k<<<ggrid, 256>>>(p_out, gg, p_glog);
    gate_softmax_k<<<1, 32>>>(p_glog, out_gw);
    fuse_k<<<(ND_ELEMS + 255) / 256, 256>>>(p_out, out_gw, out_fused);
    memupd_k<<<(LMD_ELEMS + 255) / 256, 256>>>(memories, p_upd, out_mem);

    (void)in_sizes; (void)n_in; (void)out_size;
}

// round 9
// speedup vs baseline: 5.7641x; 1.1702x over previous
#include <cuda_runtime.h>
#include <math.h>
#include <stdint.h>

#define EXP 4
#define NTOK 2048
#define DIM 512
#define NH 8
#define DHEAD 64
#define FFD 2048
#define NL 4
#define MEMSZ 4096

#define ND_ELEMS (NTOK * DIM)
#define LMD_ELEMS (NL * MEMSZ * DIM)

#define GFLAG_RELU 1
#define GFLAG_ACCUM 2
#define GFLAG_TFOUT 4

// ---------------- scratch (per-expert batched) ----------------
__device__ float g_xln[EXP * NTOK * DIM];
__device__ float g_x4[EXP * NTOK * DIM];
__device__ float g_qkv4[(size_t)EXP * NTOK * 3 * DIM];
__device__ float g_big[(size_t)EXP * NH * NTOK * NTOK];   // reused: cross/scores/memlogits
__device__ float g_sa4[EXP * NTOK * DIM];
__device__ float g_op4[EXP * NTOK * DIM];
__device__ float g_tmp4[(size_t)EXP * NTOK * FFD];
__device__ float g_x14[EXP * NTOK * DIM];
__device__ float g_x1r4[EXP * NTOK * DIM];
__device__ float g_xor4[EXP * NTOK * DIM];
__device__ float g_out[EXP * NTOK * DIM];
__device__ float g_retr4[(size_t)EXP * NL * NTOK * DIM];
__device__ float g_retrp4[(size_t)EXP * NTOK * NL * DIM];
__device__ float g_upd4[(size_t)EXP * NL * MEMSZ * DIM];
__device__ float g_glog[EXP];
// pre-rounded weights
__device__ float g_ipw_r[EXP * 3 * DIM * DIM];
__device__ float g_opw_r[EXP * DIM * DIM];
__device__ float g_w1_r[EXP * FFD * DIM];
__device__ float g_w2_r[EXP * DIM * FFD];
__device__ float g_aggw_r[DIM * NL * DIM];
__device__ float g_mem_r[LMD_ELEMS];

// ---------------- helpers ----------------
__device__ __forceinline__ uint32_t tf(float x) {
    uint32_t u; asm("cvt.rna.tf32.f32 %0, %1;" : "=r"(u) : "f"(x)); return u;
}
__device__ __forceinline__ float tff(float x) { return __uint_as_float(tf(x)); }
__device__ __forceinline__ void mma8(float* c, const uint32_t* a, const uint32_t* b) {
    asm volatile(
        "mma.sync.aligned.m16n8k8.row.col.f32.tf32.tf32.f32 "
        "{%0,%1,%2,%3}, {%4,%5,%6,%7}, {%8,%9}, {%0,%1,%2,%3};"
        : "+f"(c[0]), "+f"(c[1]), "+f"(c[2]), "+f"(c[3])
        : "r"(a[0]), "r"(a[1]), "r"(a[2]), "r"(a[3]), "r"(b[0]), "r"(b[1]));
}
__device__ __forceinline__ void cpa16(uint32_t s, const float* g) {
    asm volatile("cp.async.cg.shared.global [%0], [%1], 16;" :: "r"(s), "l"(g));
}
__device__ __forceinline__ void ldsm4(uint32_t* r, uint32_t a) {
    asm volatile("ldmatrix.sync.aligned.m8n8.x4.shared.b16 {%0,%1,%2,%3}, [%4];"
        : "=r"(r[0]), "=r"(r[1]), "=r"(r[2]), "=r"(r[3]) : "r"(a));
}

__global__ void tfround_k(const float* __restrict__ s, float* __restrict__ d, long long n) {
    long long i = (long long)blockIdx.x * 256 + threadIdx.x;
    if (i < n) d[i] = tff(s[i]);
}

// ---------------- cp.async tf32 mma GEMM, expert-batched z ----------------
// z decomposed: zo = bz/zInner, zi = bz%zInner. ptr += outer*zo + inner*zi.
// rs < 0 means per-outer-batch remap start = zo*rl.
template <int MT, int NT, bool ATR, bool BTR, int OCC>
__global__ void __launch_bounds__(256, OCC) gemmCP(
    const float* __restrict__ A, const float* __restrict__ B, float* __restrict__ C,
    int K, int lda, int ldb, int ldc,
    long long aB, long long aBi, long long bB, long long bBi,
    long long cB, long long cBi, int zInner,
    float alpha, const float* __restrict__ bias, long long biasB,
    const float* __restrict__ resid, long long residB, int residLd,
    float clipVal, int flags, int rs, int rl)
{
    constexpr int KC = 16;
    constexpr int AST = 20;
    constexpr int MST = MT + 8;
    constexpr int NST = NT + 8;
    constexpr int ASZ = ATR ? KC * MST : MT * AST;
    constexpr int BSZ = BTR ? KC * NST : NT * AST;
    constexpr int STG = ASZ + BSZ;
    constexpr int MI = MT / 32;
    constexpr int NB = NT / 32;

    extern __shared__ float sm[];
    uint32_t smb = (uint32_t)__cvta_generic_to_shared(sm);

    const int t = threadIdx.x, l = t & 31, w = t >> 5;
    const int bz = blockIdx.z;
    const int zo = bz / zInner, zi = bz - zo * zInner;
    A += aB * zo + aBi * zi;
    B += bB * zo + bBi * zi;
    C += cB * zo + cBi * zi;
    if (bias) bias += biasB * zo;
    if (resid) resid += residB * zo;
    if (rs < 0) rs = zo * rl;
    const int m0 = blockIdx.y * MT, n0 = blockIdx.x * NT;
    const int wm0 = (w >> 2) * (MT / 2), wn0 = (w & 3) * (NT / 4);

    const uint32_t aBase = (uint32_t)(((wm0 + ((l >> 3 & 1) << 3) + (l & 7)) * AST + ((l >> 4) << 2)) * 4);
    const uint32_t bBase4 = (uint32_t)(((wn0 + ((l >> 4) << 3) + (l & 7)) * AST + ((l >> 3 & 1) << 2)) * 4);
    const int atrOff = (l & 3) * MST + wm0 + (l >> 2);
    const int btrOff = (l & 3) * NST + wn0 + (l >> 2);

    float acc[MI][NB][4];
#pragma unroll
    for (int a = 0; a < MI; a++)
#pragma unroll
        for (int b = 0; b < NB; b++)
#pragma unroll
            for (int c = 0; c < 4; c++) acc[a][b][c] = 0.f;

    const int nK = K / KC;

    auto issue = [&](int s, int k0) {
        uint32_t ab = smb + (uint32_t)(s * STG * 4);
        uint32_t bb = ab + ASZ * 4;
        if (!ATR) {
            constexpr int ACH = MT * 4;
#pragma unroll
            for (int c0 = 0; c0 < ACH; c0 += 256) {
                int c = c0 + t;
                int row = c >> 2, kq = c & 3;
                cpa16(ab + (uint32_t)(row * AST + kq * 4) * 4,
                      &A[(long long)(m0 + row) * lda + k0 + kq * 4]);
            }
        } else {
            constexpr int AQ = MT / 4;
            constexpr int ASH = (MT == 128) ? 5 : 4;
            constexpr int ACH = KC * AQ;
#pragma unroll
            for (int c0 = 0; c0 < ACH; c0 += 256) {
                int c = c0 + t;
                int kr = c >> ASH, mq = c & (AQ - 1);
                cpa16(ab + (uint32_t)(kr * MST + mq * 4) * 4,
                      &A[(long long)(k0 + kr) * lda + m0 + mq * 4]);
            }
        }
        if (!BTR) {
            constexpr int BCH = NT * 4;
#pragma unroll
            for (int c0 = 0; c0 < BCH; c0 += 256) {
                int c = c0 + t;
                int row = c >> 2, kq = c & 3;
                int n = n0 + row;
                if (rl && n >= rs) n += rl;
                cpa16(bb + (uint32_t)(row * AST + kq * 4) * 4,
                      &B[(long long)n * ldb + k0 + kq * 4]);
            }
        } else {
            constexpr int NQ = NT / 4;
            constexpr int SH = (NT == 128) ? 5 : 4;
            constexpr int BCH = KC * NQ;
#pragma unroll
            for (int c0 = 0; c0 < BCH; c0 += 256) {
                int c = c0 + t;
                int kr = c >> SH, nq = c & (NQ - 1);
                int g = k0 + kr;
                if (rl && g >= rs) g += rl;
                cpa16(bb + (uint32_t)(kr * NST + nq * 4) * 4,
                      &B[(long long)g * ldb + n0 + nq * 4]);
            }
        }
        asm volatile("cp.async.commit_group;" ::: "memory");
    };

    issue(0, 0);
    issue(1, KC);
    issue(2, 2 * KC);

    for (int i = 0; i < nK; i++) {
        asm volatile("cp.async.wait_group 2;" ::: "memory");
        __syncthreads();
        if (i + 3 < nK) issue((i + 3) & 3, (i + 3) * KC);

        const float* Ab = sm + (i & 3) * STG;
        const float* Bb = Ab + ASZ;
        uint32_t abu = smb + (uint32_t)((i & 3) * STG * 4);
        uint32_t bbu = abu + (uint32_t)(ASZ * 4);
#pragma unroll
        for (int kk = 0; kk < 2; kk++) {
            const int kc = kk * 8;
            uint32_t af[MI][4], bf[NB][2];
#pragma unroll
            for (int mi = 0; mi < MI; mi++) {
                if (!ATR) {
                    ldsm4(af[mi], abu + aBase + (uint32_t)((mi * 16 * AST + kc) * 4));
                } else {
                    const uint32_t* ap = (const uint32_t*)&Ab[kc * MST + atrOff + mi * 16];
                    af[mi][0] = ap[0];
                    af[mi][1] = ap[8];
                    af[mi][2] = ap[4 * MST];
                    af[mi][3] = ap[4 * MST + 8];
                }
            }
            if (!BTR) {
#pragma unroll
                for (int nj = 0; nj < NB / 2; nj++) {
                    uint32_t r4[4];
                    ldsm4(r4, bbu + bBase4 + (uint32_t)((nj * 16 * AST + kc) * 4));
                    bf[2 * nj][0] = r4[0]; bf[2 * nj][1] = r4[1];
                    bf[2 * nj + 1][0] = r4[2]; bf[2 * nj + 1][1] = r4[3];
                }
            } else {
#pragma unroll
                for (int ni = 0; ni < NB; ni++) {
                    const uint32_t* bp = (const uint32_t*)&Bb[kc * NST + btrOff + ni * 8];
                    bf[ni][0] = bp[0];
                    bf[ni][1] = bp[4 * NST];
                }
            }
#pragma unroll
            for (int mi = 0; mi < MI; mi++)
#pragma unroll
                for (int ni = 0; ni < NB; ni++) mma8(acc[mi][ni], af[mi], bf[ni]);
        }
    }

    // epilogue
#pragma unroll
    for (int mi = 0; mi < MI; mi++) {
        int row0 = m0 + wm0 + mi * 16 + (l >> 2);
#pragma unroll
        for (int ni = 0; ni < NB; ni++) {
            int col = n0 + wn0 + ni * 8 + (l & 3) * 2;
#pragma unroll
            for (int h = 0; h < 2; h++) {
                int row = row0 + h * 8;
                float vx = alpha * acc[mi][ni][h * 2];
                float vy = alpha * acc[mi][ni][h * 2 + 1];
                if (bias) { vx += bias[col]; vy += bias[col + 1]; }
                if (flags & GFLAG_RELU) { vx = fmaxf(vx, 0.f); vy = fmaxf(vy, 0.f); }
                if (clipVal > 0.f) {
                    vx = fminf(fmaxf(vx, -clipVal), clipVal);
                    vy = fminf(fmaxf(vy, -clipVal), clipVal);
                }
                if (resid) {
                    float2 rv = *(const float2*)&resid[(long long)row * residLd + col];
                    vx += rv.x; vy += rv.y;
                }
                float2* cp = (float2*)&C[(long long)row * ldc + col];
                if (flags & GFLAG_ACCUM) {
                    float2 o = *cp;
                    vx += o.x; vy += o.y;
                }
                if (flags & GFLAG_TFOUT) { vx = tff(vx); vy = tff(vy); }
                *cp = make_float2(vx, vy);
            }
        }
    }
}

// ---------------- reductions ----------------
__device__ __forceinline__ float warpReduceSum(float v) {
#pragma unroll
    for (int o = 16; o; o >>= 1) v += __shfl_xor_sync(0xffffffffu, v, o);
    return v;
}
__device__ __forceinline__ float warpReduceMax(float v) {
#pragma unroll
    for (int o = 16; o; o >>= 1) v = fmaxf(v, __shfl_xor_sync(0xffffffffu, v, o));
    return v;
}

// ---------------- smem-cached row softmax (tf32-rounded output) ----------------
__global__ void softmax_k(float* __restrict__ p, int cols) {
    extern __shared__ float sbuf[];
    float* row = p + (long long)blockIdx.x * cols;
    __shared__ float sh[8];
    __shared__ float sb;
    int tid = threadIdx.x, lane = tid & 31, wid = tid >> 5;
    float m = -1e30f;
    for (int i = tid; i < cols; i += 256) { float v = row[i]; sbuf[i] = v; m = fmaxf(m, v); }
    m = warpReduceMax(m);
    if (lane == 0) sh[wid] = m;
    __syncthreads();
    if (tid == 0) { float x = sh[0]; for (int q = 1; q < 8; q++) x = fmaxf(x, sh[q]); sb = x; }
    __syncthreads();
    m = sb;
    float s = 0.f;
    for (int i = tid; i < cols; i += 256) { float v = expf(sbuf[i] - m); sbuf[i] = v; s += v; }
    s = warpReduceSum(s);
    if (lane == 0) sh[wid] = s;
    __syncthreads();
    if (tid == 0) { float x = 0; for (int q = 0; q < 8; q++) x += sh[q]; sb = 1.f / x; }
    __syncthreads();
    float inv = sb;
    for (int i = tid; i < cols; i += 256) row[i] = tff(sbuf[i] * inv);
}

// ---------------- LayerNorm (rounded output) ----------------
__global__ void ln_k(const float* __restrict__ src, float* __restrict__ dst) {
    long long row = blockIdx.x;
    const float* x = src + row * DIM;
    float* y = dst + row * DIM;
    int tid = threadIdx.x, lane = tid & 31, wid = tid >> 5;
    float v[4], s = 0.f, s2 = 0.f;
#pragma unroll
    for (int j = 0; j < 4; j++) { v[j] = x[tid + j * 128]; s += v[j]; s2 += v[j] * v[j]; }
    s = warpReduceSum(s); s2 = warpReduceSum(s2);
    __shared__ float sh[2][4]; __shared__ float mv[2];
    if (lane == 0) { sh[0][wid] = s; sh[1][wid] = s2; }
    __syncthreads();
    if (tid == 0) {
        float a = sh[0][0] + sh[0][1] + sh[0][2] + sh[0][3];
        float b = sh[1][0] + sh[1][1] + sh[1][2] + sh[1][3];
        float mean = a / DIM;
        mv[0] = mean; mv[1] = rsqrtf(b / DIM - mean * mean + 1e-5f);
    }
    __syncthreads();
    float mean = mv[0], rstd = mv[1];
#pragma unroll
    for (int j = 0; j < 4; j++) y[tid + j * 128] = tff((v[j] - mean) * rstd);
}

// batched: e = row >> 11; w/bb indexed per expert
__global__ void ln_ra_k(const float* __restrict__ a, const float* __restrict__ b,
                        const float* __restrict__ wAll, const float* __restrict__ bAll,
                        float* __restrict__ dst, float* __restrict__ dstr) {
    long long row = blockIdx.x;
    int e = (int)(row >> 11);
    const float* xa = a + row * DIM;
    const float* xb = b + row * DIM;
    const float* w = wAll + (long long)e * DIM;
    const float* bb = bAll + (long long)e * DIM;
    float* y = dst + row * DIM;
    float* yr = dstr + row * DIM;
    int tid = threadIdx.x, lane = tid & 31, wid = tid >> 5;
    float v[4], s = 0.f, s2 = 0.f;
#pragma unroll
    for (int j = 0; j < 4; j++) {
        int i = tid + j * 128;
        v[j] = xa[i] + xb[i]; s += v[j]; s2 += v[j] * v[j];
    }
    s = warpReduceSum(s); s2 = warpReduceSum(s2);
    __shared__ float sh[2][4]; __shared__ float mv[2];
    if (lane == 0) { sh[0][wid] = s; sh[1][wid] = s2; }
    __syncthreads();
    if (tid == 0) {
        float p = sh[0][0] + sh[0][1] + sh[0][2] + sh[0][3];
        float q = sh[1][0] + sh[1][1] + sh[1][2] + sh[1][3];
        float mean = p / DIM;
        mv[0] = mean; mv[1] = rsqrtf(q / DIM - mean * mean + 1e-5f);
    }
    __syncthreads();
    float mean = mv[0], rstd = mv[1];
#pragma unroll
    for (int j = 0; j < 4; j++) {
        int i = tid + j * 128;
        float o = (v[j] - mean) * rstd * w[i] + bb[i];
        y[i] = o;
        yr[i] = tff(o);
    }
}

// retr4[e][l][n][d] -> retrp4[e][n][l*D+d], tf32-rounded
__global__ void permute_k(const float* __restrict__ retr, float* __restrict__ rp) {
    long long i = (long long)blockIdx.x * 256 + threadIdx.x;
    if (i < (long long)EXP * NL * NTOK * DIM) {
        int d = (int)(i & (DIM - 1));
        long long r = i >> 9;
        int n = (int)(r & (NTOK - 1));
        long long r2 = r >> 11;
        int lay = (int)(r2 & (NL - 1));
        long long e = r2 >> 2;
        rp[((e * NTOK + n) * NL + lay) * DIM + d] = tff(retr[i]);
    }
}

__global__ void zero_k(float* __restrict__ p, long long n) {
    long long i = (long long)blockIdx.x * 256 + threadIdx.x;
    if (i < n) p[i] = 0.f;
}

__global__ void gate_dot_k(const float* __restrict__ outs, const float* __restrict__ gg,
                           float* __restrict__ glog) {
    int e = blockIdx.x;
    long long chunk = (long long)ND_ELEMS / gridDim.y;
    long long base = (long long)e * ND_ELEMS + (long long)blockIdx.y * chunk;
    float acc = 0.f;
    for (long long i = threadIdx.x; i < chunk; i += blockDim.x) {
        long long idx = base + i;
        acc += outs[idx] * gg[idx & (DIM - 1)];
    }
    acc = warpReduceSum(acc);
    __shared__ float sh[8];
    int lane = threadIdx.x & 31, wid = threadIdx.x >> 5;
    if (lane == 0) sh[wid] = acc;
    __syncthreads();
    if (threadIdx.x == 0) {
        float x = 0;
        for (int q = 0; q < 8; q++) x += sh[q];
        atomicAdd(&glog[e], x);
    }
}

__global__ void gate_softmax_k(const float* __restrict__ glog, float* __restrict__ gw) {
    if (threadIdx.x == 0) {
        float l[EXP], m = -1e30f;
        for (int e = 0; e < EXP; e++) {
            l[e] = fminf(fmaxf(glog[e] / (float)NTOK, -10.f), 10.f);
            m = fmaxf(m, l[e]);
        }
        float s = 0.f;
        for (int e = 0; e < EXP; e++) { l[e] = expf(l[e] - m); s += l[e]; }
        for (int e = 0; e < EXP; e++) gw[e] = l[e] / s;
    }
}

__global__ void fuse_k(const float* __restrict__ outs, const float* __restrict__ gw,
                       float* __restrict__ fused) {
    long long i = (long long)blockIdx.x * 256 + threadIdx.x;
    if (i < (long long)ND_ELEMS) {
        float r = 0.f;
#pragma unroll
        for (int e = 0; e < EXP; e++) r += gw[e] * outs[(long long)e * ND_ELEMS + i];
        fused[i] = r;
    }
}

// o = 0.9*mem + clip(0.1 * sum_e upd4[e], +-0.1)
__global__ void memupd_k(const float* __restrict__ mem, const float* __restrict__ upd4,
                         float* __restrict__ o) {
    long long i = (long long)blockIdx.x * 256 + threadIdx.x;
    if (i < (long long)LMD_ELEMS) {
        float u = upd4[i];
#pragma unroll
        for (int e = 1; e < EXP; e++) u += upd4[(long long)e * LMD_ELEMS + i];
        u *= 0.1f;
        u = fminf(fmaxf(u, -0.1f), 0.1f);
        o[i] = 0.9f * mem[i] + u;
    }
}

// ---------------- host ----------------
static constexpr int stgFl(int MT, int NT, bool ATR, bool BTR) {
    return (ATR ? 16 * (MT + 8) : MT * 20) + (BTR ? 16 * (NT + 8) : NT * 20);
}
#define SMEMB(MT, NT, ATR, BTR) (4 * stgFl(MT, NT, ATR, BTR) * 4)

static void tfround(const float* s, float* d, long long n) {
    tfround_k<<<(int)((n + 255) / 256), 256>>>(s, d, n);
}

extern "C" void kernel_launch(void* const* d_in, const int* in_sizes, int n_in,
                              void* d_out, int out_size) {
    const float* tokens   = (const float*)d_in[0];
    const float* memories = (const float*)d_in[1];
    const float* ipw      = (const float*)d_in[2];
    const float* ipb      = (const float*)d_in[3];
    const float* opw      = (const float*)d_in[4];
    const float* opb      = (const float*)d_in[5];
    const float* w1       = (const float*)d_in[6];
    const float* b1       = (const float*)d_in[7];
    const float* w2       = (const float*)d_in[8];
    const float* b2       = (const float*)d_in[9];
    const float* n1w      = (const float*)d_in[10];
    const float* n1b      = (const float*)d_in[11];
    const float* n2w      = (const float*)d_in[12];
    const float* n2b      = (const float*)d_in[13];
    const float* aggw     = (const float*)d_in[14];
    const float* aggb     = (const float*)d_in[15];
    const float* gg       = (const float*)d_in[16];

    float* out = (float*)d_out;
    float* out_fused = out;
    float* out_gw = out + ND_ELEMS;
    float* out_mem = out + ND_ELEMS + EXP;

    static float *p_xln = nullptr, *p_x4 = nullptr, *p_qkv4 = nullptr, *p_big = nullptr,
                 *p_sa4 = nullptr, *p_op4 = nullptr, *p_tmp4 = nullptr,
                 *p_x14 = nullptr, *p_x1r4 = nullptr, *p_xor4 = nullptr, *p_out = nullptr,
                 *p_retr4 = nullptr, *p_retrp4 = nullptr, *p_upd4 = nullptr, *p_glog = nullptr,
                 *p_ipw = nullptr, *p_opw = nullptr, *p_w1 = nullptr, *p_w2 = nullptr,
                 *p_aggw = nullptr, *p_mem = nullptr;
    if (!p_xln) {
        cudaGetSymbolAddress((void**)&p_xln, g_xln);
        cudaGetSymbolAddress((void**)&p_x4, g_x4);
        cudaGetSymbolAddress((void**)&p_qkv4, g_qkv4);
        cudaGetSymbolAddress((void**)&p_big, g_big);
        cudaGetSymbolAddress((void**)&p_sa4, g_sa4);
        cudaGetSymbolAddress((void**)&p_op4, g_op4);
        cudaGetSymbolAddress((void**)&p_tmp4, g_tmp4);
        cudaGetSymbolAddress((void**)&p_x14, g_x14);
        cudaGetSymbolAddress((void**)&p_x1r4, g_x1r4);
        cudaGetSymbolAddress((void**)&p_xor4, g_xor4);
        cudaGetSymbolAddress((void**)&p_out, g_out);
        cudaGetSymbolAddress((void**)&p_retr4, g_retr4);
        cudaGetSymbolAddress((void**)&p_retrp4, g_retrp4);
        cudaGetSymbolAddress((void**)&p_upd4, g_upd4);
        cudaGetSymbolAddress((void**)&p_glog, g_glog);
        cudaGetSymbolAddress((void**)&p_ipw, g_ipw_r);
        cudaGetSymbolAddress((void**)&p_opw, g_opw_r);
        cudaGetSymbolAddress((void**)&p_w1, g_w1_r);
        cudaGetSymbolAddress((void**)&p_w2, g_w2_r);
        cudaGetSymbolAddress((void**)&p_aggw, g_aggw_r);
        cudaGetSymbolAddress((void**)&p_mem, g_mem_r);
        cudaFuncSetAttribute(gemmCP<64, 128, false, false, 3>, cudaFuncAttributeMaxDynamicSharedMemorySize, SMEMB(64, 128, false, false));
        cudaFuncSetAttribute(gemmCP<64, 128, false, true, 2>,  cudaFuncAttributeMaxDynamicSharedMemorySize, SMEMB(64, 128, false, true));
        cudaFuncSetAttribute(gemmCP<64, 64, false, true, 2>,   cudaFuncAttributeMaxDynamicSharedMemorySize, SMEMB(64, 64, false, true));
        cudaFuncSetAttribute(gemmCP<64, 128, true, true, 2>,   cudaFuncAttributeMaxDynamicSharedMemorySize, SMEMB(64, 128, true, true));
    }

    const float inv_sqrt_d = 1.0f / sqrtf((float)DIM);
    const float inv_sqrt_dh = 1.0f / sqrtf((float)DHEAD);

    tfround(ipw, p_ipw, (long long)EXP * 3 * DIM * DIM);
    tfround(opw, p_opw, (long long)EXP * DIM * DIM);
    tfround(w1, p_w1, (long long)EXP * FFD * DIM);
    tfround(w2, p_w2, (long long)EXP * DIM * FFD);
    tfround(aggw, p_aggw, (long long)DIM * NL * DIM);
    tfround(memories, p_mem, (long long)LMD_ELEMS);

    zero_k<<<1, 256>>>(p_glog, EXP);
    ln_k<<<EXP * NTOK, 128>>>(tokens, p_xln);

    const long long LLND = ND_ELEMS;
    const long long BIGE = (long long)NH * NTOK * NTOK;    // per-expert big stride
    const long long QKVE = (long long)NTOK * 3 * DIM;

    // 1. cross logits [e][2048, 6144]
    gemmCP<64, 128, false, false, 3><<<dim3(48, 32, EXP), 256, SMEMB(64, 128, false, false)>>>(
        p_xln, p_xln, p_big, DIM, DIM, DIM, 3 * NTOK,
        LLND, 0, 0, 0, (long long)NTOK * 3 * NTOK, 0, 1,
        inv_sqrt_d, nullptr, 0, nullptr, 0, 0, 10.f, 0, -1, NTOK);
    softmax_k<<<EXP * NTOK, 256, 3 * NTOK * 4>>>(p_big, 3 * NTOK);
    // 2. x = probs @ ctx + xln (rounded)
    gemmCP<64, 128, false, true, 2><<<dim3(4, 32, EXP), 256, SMEMB(64, 128, false, true)>>>(
        p_big, p_xln, p_x4, 3 * NTOK, 3 * NTOK, DIM, DIM,
        (long long)NTOK * 3 * NTOK, 0, 0, 0, LLND, 0, 1,
        1.f, nullptr, 0, p_xln, LLND, DIM, 0.f, GFLAG_TFOUT, -1, NTOK);
    // 3. qkv (rounded)
    gemmCP<64, 128, false, false, 3><<<dim3(12, 32, EXP), 256, SMEMB(64, 128, false, false)>>>(
        p_x4, p_ipw, p_qkv4, DIM, DIM, DIM, 3 * DIM,
        LLND, 0, (long long)3 * DIM * DIM, 0, QKVE, 0, 1,
        1.f, ipb, 3 * DIM, nullptr, 0, 0, 0.f, GFLAG_TFOUT, 0, 0);
    // 4. scores [e][h][2048,2048]
    gemmCP<64, 128, false, false, 3><<<dim3(16, 32, EXP * NH), 256, SMEMB(64, 128, false, false)>>>(
        p_qkv4, p_qkv4 + DIM, p_big, DHEAD, 3 * DIM, 3 * DIM, NTOK,
        QKVE, DHEAD, QKVE, DHEAD, BIGE, (long long)NTOK * NTOK, NH,
        inv_sqrt_dh, nullptr, 0, nullptr, 0, 0, 0.f, 0, 0, 0);
    softmax_k<<<EXP * NH * NTOK, 256, NTOK * 4>>>(p_big, NTOK);
    // 5. sa = probs @ v (rounded)
    gemmCP<64, 64, false, true, 2><<<dim3(1, 32, EXP * NH), 256, SMEMB(64, 64, false, true)>>>(
        p_big, p_qkv4 + 2 * DIM, p_sa4, NTOK, NTOK, 3 * DIM, DIM,
        BIGE, (long long)NTOK * NTOK, QKVE, DHEAD, LLND, DHEAD, NH,
        1.f, nullptr, 0, nullptr, 0, 0, 0.f, GFLAG_TFOUT, 0, 0);
    // 6. out_proj
    gemmCP<64, 128, false, false, 3><<<dim3(4, 32, EXP), 256, SMEMB(64, 128, false, false)>>>(
        p_sa4, p_opw, p_op4, DIM, DIM, DIM, DIM,
        LLND, 0, (long long)DIM * DIM, 0, LLND, 0, 1,
        1.f, opb, DIM, nullptr, 0, 0, 0.f, 0, 0, 0);
    ln_ra_k<<<EXP * NTOK, 128>>>(p_x4, p_op4, n1w, n1b, p_x14, p_x1r4);
    // 7. ff1 relu (rounded)
    gemmCP<64, 128, false, false, 3><<<dim3(16, 32, EXP), 256, SMEMB(64, 128, false, false)>>>(
        p_x1r4, p_w1, p_tmp4, DIM, DIM, DIM, FFD,
        LLND, 0, (long long)FFD * DIM, 0, (long long)NTOK * FFD, 0, 1,
        1.f, b1, FFD, nullptr, 0, 0, 0.f, GFLAG_RELU | GFLAG_TFOUT, 0, 0);
    // 8. ff2
    gemmCP<64, 128, false, false, 3><<<dim3(4, 32, EXP), 256, SMEMB(64, 128, false, false)>>>(
        p_tmp4, p_w2, p_sa4, FFD, FFD, FFD, DIM,
        (long long)NTOK * FFD, 0, (long long)DIM * FFD, 0, LLND, 0, 1,
        1.f, b2, DIM, nullptr, 0, 0, 0.f, 0, 0, 0);
    ln_ra_k<<<EXP * NTOK, 128>>>(p_x14, p_sa4, n2w, n2b, p_out, p_xor4);
    // 9. memory logits [e][l][2048,4096]
    gemmCP<64, 128, false, false, 3><<<dim3(32, 32, EXP * NL), 256, SMEMB(64, 128, false, false)>>>(
        p_xor4, p_mem, p_big, DIM, DIM, DIM, MEMSZ,
        LLND, 0, 0, (long long)MEMSZ * DIM, (long long)NL * NTOK * MEMSZ, (long long)NTOK * MEMSZ, NL,
        inv_sqrt_d, nullptr, 0, nullptr, 0, 0, 10.f, 0, 0, 0);
    softmax_k<<<EXP * NL * NTOK, 256, MEMSZ * 4>>>(p_big, MEMSZ);
    // 10. retr
    gemmCP<64, 128, false, true, 2><<<dim3(4, 32, EXP * NL), 256, SMEMB(64, 128, false, true)>>>(
        p_big, p_mem, p_retr4, MEMSZ, MEMSZ, DIM, DIM,
        (long long)NL * NTOK * MEMSZ, (long long)NTOK * MEMSZ, 0, (long long)MEMSZ * DIM,
        (long long)NL * NTOK * DIM, (long long)NTOK * DIM, NL,
        1.f, nullptr, 0, nullptr, 0, 0, 0.f, 0, 0, 0);
    // 11. upd4[e][l] = clip(am^T @ xout, 1)
    gemmCP<64, 128, true, true, 2><<<dim3(4, 64, EXP * NL), 256, SMEMB(64, 128, true, true)>>>(
        p_big, p_xor4, p_upd4, NTOK, MEMSZ, DIM, DIM,
        (long long)NL * NTOK * MEMSZ, (long long)NTOK * MEMSZ, LLND, 0,
        (long long)LMD_ELEMS, (long long)MEMSZ * DIM, NL,
        1.f, nullptr, 0, nullptr, 0, 0, 1.f, 0, 0, 0);
    permute_k<<<(EXP * NL * ND_ELEMS + 255) / 256, 256>>>(p_retr4, p_retrp4);
    // 12. outs += retrp @ aggw^T + aggb (in-place residual)
    gemmCP<64, 128, false, false, 3><<<dim3(4, 32, EXP), 256, SMEMB(64, 128, false, false)>>>(
        p_retrp4, p_aggw, p_out, NL * DIM, NL * DIM, NL * DIM, DIM,
        (long long)NTOK * NL * DIM, 0, 0, 0, LLND, 0, 1,
        1.f, aggb, 0, p_out, LLND, DIM, 0.f, 0, 0, 0);

    dim3 ggrid(EXP, 16);
    gate_dot_k<<<ggrid, 256>>>(p_out, gg, p_glog);
    gate_softmax_k<<<1, 32>>>(p_glog, out_gw);
    fuse_k<<<(ND_ELEMS + 255) / 256, 256>>>(p_out, out_gw, out_fused);
    memupd_k<<<(LMD_ELEMS + 255) / 256, 256>>>(memories, p_upd4, out_mem);

    (void)in_sizes; (void)n_in; (void)out_size;
}

// round 10
// speedup vs baseline: 5.9100x; 1.0253x over previous
#include <cuda_runtime.h>
#include <math.h>
#include <stdint.h>

#define EXP 4
#define NTOK 2048
#define DIM 512
#define NH 8
#define DHEAD 64
#define FFD 2048
#define NL 4
#define MEMSZ 4096

#define ND_ELEMS (NTOK * DIM)
#define LMD_ELEMS (NL * MEMSZ * DIM)

#define GFLAG_RELU 1
#define GFLAG_ACCUM 2
#define GFLAG_TFOUT 4

// ---------------- scratch ----------------
__device__ float g_xln[EXP * NTOK * DIM];
__device__ float g_x4[EXP * NTOK * DIM];
__device__ float g_qkv4[(size_t)EXP * NTOK * 3 * DIM];
__device__ float g_big[(size_t)EXP * NH * NTOK * NTOK];
__device__ float g_sa4[EXP * NTOK * DIM];
__device__ float g_op4[EXP * NTOK * DIM];
__device__ float g_tmp4[(size_t)EXP * NTOK * FFD];
__device__ float g_x14[EXP * NTOK * DIM];
__device__ float g_x1r4[EXP * NTOK * DIM];
__device__ float g_xor4[EXP * NTOK * DIM];
__device__ float g_out[EXP * NTOK * DIM];
__device__ float g_retr4[(size_t)EXP * NL * NTOK * DIM];
__device__ float g_retrp4[(size_t)EXP * NTOK * NL * DIM];
__device__ float g_upd4[(size_t)EXP * NL * MEMSZ * DIM];
__device__ float g_glog[EXP];
__device__ float g_vT[(size_t)EXP * NTOK * DIM];          // [e][h*64+dh][n]
__device__ float g_memT[LMD_ELEMS];                       // [l][d][m]
// pre-rounded weights
__device__ float g_ipw_r[EXP * 3 * DIM * DIM];
__device__ float g_opw_r[EXP * DIM * DIM];
__device__ float g_w1_r[EXP * FFD * DIM];
__device__ float g_w2_r[EXP * DIM * FFD];
__device__ float g_aggw_r[DIM * NL * DIM];
__device__ float g_mem_r[LMD_ELEMS];

// ---------------- helpers ----------------
__device__ __forceinline__ uint32_t tf(float x) {
    uint32_t u; asm("cvt.rna.tf32.f32 %0, %1;" : "=r"(u) : "f"(x)); return u;
}
__device__ __forceinline__ float tff(float x) { return __uint_as_float(tf(x)); }
__device__ __forceinline__ float4 tff4(float4 v) {
    return make_float4(tff(v.x), tff(v.y), tff(v.z), tff(v.w));
}
__device__ __forceinline__ void mma8(float* c, const uint32_t* a, const uint32_t* b) {
    asm volatile(
        "mma.sync.aligned.m16n8k8.row.col.f32.tf32.tf32.f32 "
        "{%0,%1,%2,%3}, {%4,%5,%6,%7}, {%8,%9}, {%0,%1,%2,%3};"
        : "+f"(c[0]), "+f"(c[1]), "+f"(c[2]), "+f"(c[3])
        : "r"(a[0]), "r"(a[1]), "r"(a[2]), "r"(a[3]), "r"(b[0]), "r"(b[1]));
}
__device__ __forceinline__ void cpa16(uint32_t s, const float* g) {
    asm volatile("cp.async.cg.shared.global [%0], [%1], 16;" :: "r"(s), "l"(g));
}
__device__ __forceinline__ void ldsm4(uint32_t* r, uint32_t a) {
    asm volatile("ldmatrix.sync.aligned.m8n8.x4.shared.b16 {%0,%1,%2,%3}, [%4];"
        : "=r"(r[0]), "=r"(r[1]), "=r"(r[2]), "=r"(r[3]) : "r"(a));
}

__global__ void tfround_k(const float4* __restrict__ s, float4* __restrict__ d, long long n4) {
    long long i = (long long)blockIdx.x * 256 + threadIdx.x;
    if (i < n4) d[i] = tff4(s[i]);
}

// 32x32 tiled transpose: in [z][rows][cols] (ldin) -> out [z][cols][rows]
template <int ROUND>
__global__ void transpose_k(const float* __restrict__ in, float* __restrict__ out,
                            int rows, int cols, int ldin,
                            long long inB, long long outB) {
    __shared__ float tile[32][33];
    int z = blockIdx.z;
    in += inB * z; out += outB * z;
    int c0 = blockIdx.x * 32, r0 = blockIdx.y * 32;
    int x = threadIdx.x, y = threadIdx.y;
#pragma unroll
    for (int j = 0; j < 32; j += 8)
        tile[y + j][x] = in[(long long)(r0 + y + j) * ldin + c0 + x];
    __syncthreads();
#pragma unroll
    for (int j = 0; j < 32; j += 8) {
        float v = tile[x][y + j];
        out[(long long)(c0 + y + j) * rows + r0 + x] = ROUND ? tff(v) : v;
    }
}

// ---------------- cp.async tf32 mma GEMM, expert-batched z ----------------
template <int MT, int NT, bool ATR, bool BTR, int OCC>
__global__ void __launch_bounds__(256, OCC) gemmCP(
    const float* __restrict__ A, const float* __restrict__ B, float* __restrict__ C,
    int K, int lda, int ldb, int ldc,
    long long aB, long long aBi, long long bB, long long bBi,
    long long cB, long long cBi, int zInner,
    float alpha, const float* __restrict__ bias, long long biasB,
    const float* __restrict__ resid, long long residB, int residLd,
    float clipVal, int flags, int rs, int rl)
{
    constexpr int KC = 16;
    constexpr int AST = 20;
    constexpr int MST = MT + 8;
    constexpr int NST = NT + 8;
    constexpr int ASZ = ATR ? KC * MST : MT * AST;
    constexpr int BSZ = BTR ? KC * NST : NT * AST;
    constexpr int STG = ASZ + BSZ;
    constexpr int MI = MT / 32;
    constexpr int NB = NT / 32;

    extern __shared__ float sm[];
    uint32_t smb = (uint32_t)__cvta_generic_to_shared(sm);

    const int t = threadIdx.x, l = t & 31, w = t >> 5;
    const int bz = blockIdx.z;
    const int zo = bz / zInner, zi = bz - zo * zInner;
    A += aB * zo + aBi * zi;
    B += bB * zo + bBi * zi;
    C += cB * zo + cBi * zi;
    if (bias) bias += biasB * zo;
    if (resid) resid += residB * zo;
    if (rs < 0) rs = zo * rl;
    const int m0 = blockIdx.y * MT, n0 = blockIdx.x * NT;
    const int wm0 = (w >> 2) * (MT / 2), wn0 = (w & 3) * (NT / 4);

    const uint32_t aBase = (uint32_t)(((wm0 + ((l >> 3 & 1) << 3) + (l & 7)) * AST + ((l >> 4) << 2)) * 4);
    const uint32_t bBase4 = (uint32_t)(((wn0 + ((l >> 4) << 3) + (l & 7)) * AST + ((l >> 3 & 1) << 2)) * 4);
    const int atrOff = (l & 3) * MST + wm0 + (l >> 2);
    const int btrOff = (l & 3) * NST + wn0 + (l >> 2);

    float acc[MI][NB][4];
#pragma unroll
    for (int a = 0; a < MI; a++)
#pragma unroll
        for (int b = 0; b < NB; b++)
#pragma unroll
            for (int c = 0; c < 4; c++) acc[a][b][c] = 0.f;

    const int nK = K / KC;

    auto issue = [&](int s, int k0) {
        uint32_t ab = smb + (uint32_t)(s * STG * 4);
        uint32_t bb = ab + ASZ * 4;
        if (!ATR) {
            constexpr int ACH = MT * 4;
#pragma unroll
            for (int c0 = 0; c0 < ACH; c0 += 256) {
                int c = c0 + t;
                int row = c >> 2, kq = c & 3;
                cpa16(ab + (uint32_t)(row * AST + kq * 4) * 4,
                      &A[(long long)(m0 + row) * lda + k0 + kq * 4]);
            }
        } else {
            constexpr int AQ = MT / 4;
            constexpr int ASH = (MT == 128) ? 5 : 4;
            constexpr int ACH = KC * AQ;
#pragma unroll
            for (int c0 = 0; c0 < ACH; c0 += 256) {
                int c = c0 + t;
                int kr = c >> ASH, mq = c & (AQ - 1);
                cpa16(ab + (uint32_t)(kr * MST + mq * 4) * 4,
                      &A[(long long)(k0 + kr) * lda + m0 + mq * 4]);
            }
        }
        if (!BTR) {
            constexpr int BCH = NT * 4;
#pragma unroll
            for (int c0 = 0; c0 < BCH; c0 += 256) {
                int c = c0 + t;
                int row = c >> 2, kq = c & 3;
                int n = n0 + row;
                if (rl && n >= rs) n += rl;
                cpa16(bb + (uint32_t)(row * AST + kq * 4) * 4,
                      &B[(long long)n * ldb + k0 + kq * 4]);
            }
        } else {
            constexpr int NQ = NT / 4;
            constexpr int SH = (NT == 128) ? 5 : 4;
            constexpr int BCH = KC * NQ;
#pragma unroll
            for (int c0 = 0; c0 < BCH; c0 += 256) {
                int c = c0 + t;
                int kr = c >> SH, nq = c & (NQ - 1);
                int g = k0 + kr;
                if (rl && g >= rs) g += rl;
                cpa16(bb + (uint32_t)(kr * NST + nq * 4) * 4,
                      &B[(long long)g * ldb + n0 + nq * 4]);
            }
        }
        asm volatile("cp.async.commit_group;" ::: "memory");
    };

    issue(0, 0);
    issue(1, KC);
    issue(2, 2 * KC);

    for (int i = 0; i < nK; i++) {
        asm volatile("cp.async.wait_group 2;" ::: "memory");
        __syncthreads();
        if (i + 3 < nK) issue((i + 3) & 3, (i + 3) * KC);

        const float* Ab = sm + (i & 3) * STG;
        const float* Bb = Ab + ASZ;
        uint32_t abu = smb + (uint32_t)((i & 3) * STG * 4);
        uint32_t bbu = abu + (uint32_t)(ASZ * 4);
#pragma unroll
        for (int kk = 0; kk < 2; kk++) {
            const int kc = kk * 8;
            uint32_t af[MI][4], bf[NB][2];
#pragma unroll
            for (int mi = 0; mi < MI; mi++) {
                if (!ATR) {
                    ldsm4(af[mi], abu + aBase + (uint32_t)((mi * 16 * AST + kc) * 4));
                } else {
                    const uint32_t* ap = (const uint32_t*)&Ab[kc * MST + atrOff + mi * 16];
                    af[mi][0] = ap[0];
                    af[mi][1] = ap[8];
                    af[mi][2] = ap[4 * MST];
                    af[mi][3] = ap[4 * MST + 8];
                }
            }
            if (!BTR) {
#pragma unroll
                for (int nj = 0; nj < NB / 2; nj++) {
                    uint32_t r4[4];
                    ldsm4(r4, bbu + bBase4 + (uint32_t)((nj * 16 * AST + kc) * 4));
                    bf[2 * nj][0] = r4[0]; bf[2 * nj][1] = r4[1];
                    bf[2 * nj + 1][0] = r4[2]; bf[2 * nj + 1][1] = r4[3];
                }
            } else {
#pragma unroll
                for (int ni = 0; ni < NB; ni++) {
                    const uint32_t* bp = (const uint32_t*)&Bb[kc * NST + btrOff + ni * 8];
                    bf[ni][0] = bp[0];
                    bf[ni][1] = bp[4 * NST];
                }
            }
#pragma unroll
            for (int mi = 0; mi < MI; mi++)
#pragma unroll
                for (int ni = 0; ni < NB; ni++) mma8(acc[mi][ni], af[mi], bf[ni]);
        }
    }

    // epilogue
#pragma unroll
    for (int mi = 0; mi < MI; mi++) {
        int row0 = m0 + wm0 + mi * 16 + (l >> 2);
#pragma unroll
        for (int ni = 0; ni < NB; ni++) {
            int col = n0 + wn0 + ni * 8 + (l & 3) * 2;
#pragma unroll
            for (int h = 0; h < 2; h++) {
                int row = row0 + h * 8;
                float vx = alpha * acc[mi][ni][h * 2];
                float vy = alpha * acc[mi][ni][h * 2 + 1];
                if (bias) { vx += bias[col]; vy += bias[col + 1]; }
                if (flags & GFLAG_RELU) { vx = fmaxf(vx, 0.f); vy = fmaxf(vy, 0.f); }
                if (clipVal > 0.f) {
                    vx = fminf(fmaxf(vx, -clipVal), clipVal);
                    vy = fminf(fmaxf(vy, -clipVal), clipVal);
                }
                if (resid) {
                    float2 rv = *(const float2*)&resid[(long long)row * residLd + col];
                    vx += rv.x; vy += rv.y;
                }
                float2* cp = (float2*)&C[(long long)row * ldc + col];
                if (flags & GFLAG_ACCUM) {
                    float2 o = *cp;
                    vx += o.x; vy += o.y;
                }
                if (flags & GFLAG_TFOUT) { vx = tff(vx); vy = tff(vy); }
                *cp = make_float2(vx, vy);
            }
        }
    }
}

// ---------------- reductions ----------------
__device__ __forceinline__ float warpReduceSum(float v) {
#pragma unroll
    for (int o = 16; o; o >>= 1) v += __shfl_xor_sync(0xffffffffu, v, o);
    return v;
}
__device__ __forceinline__ float warpReduceMax(float v) {
#pragma unroll
    for (int o = 16; o; o >>= 1) v = fmaxf(v, __shfl_xor_sync(0xffffffffu, v, o));
    return v;
}

// ---------------- vectorized smem-cached row softmax (tf32-rounded output) ----------------
__global__ void softmax_k(float* __restrict__ p, int cols) {
    extern __shared__ float4 sb4[];
    float4* row = (float4*)(p + (long long)blockIdx.x * cols);
    int nc4 = cols >> 2;
    __shared__ float sh[8];
    __shared__ float sb;
    int tid = threadIdx.x, lane = tid & 31, wid = tid >> 5;
    float m = -1e30f;
    for (int i = tid; i < nc4; i += 256) {
        float4 v = row[i]; sb4[i] = v;
        m = fmaxf(m, fmaxf(fmaxf(v.x, v.y), fmaxf(v.z, v.w)));
    }
    m = warpReduceMax(m);
    if (lane == 0) sh[wid] = m;
    __syncthreads();
    if (tid == 0) { float x = sh[0]; for (int q = 1; q < 8; q++) x = fmaxf(x, sh[q]); sb = x; }
    __syncthreads();
    m = sb;
    float s = 0.f;
    for (int i = tid; i < nc4; i += 256) {
        float4 v = sb4[i];
        v.x = expf(v.x - m); v.y = expf(v.y - m); v.z = expf(v.z - m); v.w = expf(v.w - m);
        sb4[i] = v;
        s += v.x + v.y + v.z + v.w;
    }
    s = warpReduceSum(s);
    if (lane == 0) sh[wid] = s;
    __syncthreads();
    if (tid == 0) { float x = 0; for (int q = 0; q < 8; q++) x += sh[q]; sb = 1.f / x; }
    __syncthreads();
    float inv = sb;
    for (int i = tid; i < nc4; i += 256) {
        float4 v = sb4[i];
        row[i] = make_float4(tff(v.x * inv), tff(v.y * inv), tff(v.z * inv), tff(v.w * inv));
    }
}

// ---------------- LayerNorm (vectorized, rounded output) ----------------
__global__ void ln_k(const float* __restrict__ src, float* __restrict__ dst) {
    long long row = blockIdx.x;
    const float4* x = (const float4*)(src + row * DIM);
    float4* y = (float4*)(dst + row * DIM);
    int tid = threadIdx.x, lane = tid & 31, wid = tid >> 5;
    float4 v = x[tid];
    float s = v.x + v.y + v.z + v.w;
    float s2 = v.x * v.x + v.y * v.y + v.z * v.z + v.w * v.w;
    s = warpReduceSum(s); s2 = warpReduceSum(s2);
    __shared__ float sh[2][4]; __shared__ float mv[2];
    if (lane == 0) { sh[0][wid] = s; sh[1][wid] = s2; }
    __syncthreads();
    if (tid == 0) {
        float a = sh[0][0] + sh[0][1] + sh[0][2] + sh[0][3];
        float b = sh[1][0] + sh[1][1] + sh[1][2] + sh[1][3];
        float mean = a / DIM;
        mv[0] = mean; mv[1] = rsqrtf(b / DIM - mean * mean + 1e-5f);
    }
    __syncthreads();
    float mean = mv[0], rstd = mv[1];
    y[tid] = make_float4(tff((v.x - mean) * rstd), tff((v.y - mean) * rstd),
                         tff((v.z - mean) * rstd), tff((v.w - mean) * rstd));
}

// batched: e = row >> 11
__global__ void ln_ra_k(const float* __restrict__ a, const float* __restrict__ b,
                        const float* __restrict__ wAll, const float* __restrict__ bAll,
                        float* __restrict__ dst, float* __restrict__ dstr) {
    long long row = blockIdx.x;
    int e = (int)(row >> 11);
    const float4* xa = (const float4*)(a + row * DIM);
    const float4* xb = (const float4*)(b + row * DIM);
    const float4* w = (const float4*)(wAll + (long long)e * DIM);
    const float4* bb = (const float4*)(bAll + (long long)e * DIM);
    float4* y = (float4*)(dst + row * DIM);
    float4* yr = (float4*)(dstr + row * DIM);
    int tid = threadIdx.x, lane = tid & 31, wid = tid >> 5;
    float4 va = xa[tid], vb = xb[tid];
    float4 v = make_float4(va.x + vb.x, va.y + vb.y, va.z + vb.z, va.w + vb.w);
    float s = v.x + v.y + v.z + v.w;
    float s2 = v.x * v.x + v.y * v.y + v.z * v.z + v.w * v.w;
    s = warpReduceSum(s); s2 = warpReduceSum(s2);
    __shared__ float sh[2][4]; __shared__ float mv[2];
    if (lane == 0) { sh[0][wid] = s; sh[1][wid] = s2; }
    __syncthreads();
    if (tid == 0) {
        float p = sh[0][0] + sh[0][1] + sh[0][2] + sh[0][3];
        float q = sh[1][0] + sh[1][1] + sh[1][2] + sh[1][3];
        float mean = p / DIM;
        mv[0] = mean; mv[1] = rsqrtf(q / DIM - mean * mean + 1e-5f);
    }
    __syncthreads();
    float mean = mv[0], rstd = mv[1];
    float4 ww = w[tid], bbv = bb[tid];
    float4 o = make_float4((v.x - mean) * rstd * ww.x + bbv.x,
                           (v.y - mean) * rstd * ww.y + bbv.y,
                           (v.z - mean) * rstd * ww.z + bbv.z,
                           (v.w - mean) * rstd * ww.w + bbv.w);
    y[tid] = o;
    yr[tid] = tff4(o);
}

// retr4[e][l][n][d] -> retrp4[e][n][l*D+d], tf32-rounded, float4
__global__ void permute_k(const float4* __restrict__ retr, float4* __restrict__ rp) {
    long long i = (long long)blockIdx.x * 256 + threadIdx.x;
    constexpr int D4 = DIM / 4;
    if (i < (long long)EXP * NL * NTOK * D4) {
        int d4 = (int)(i & (D4 - 1));
        long long r = i >> 7;
        int n = (int)(r & (NTOK - 1));
        long long r2 = r >> 11;
        int lay = (int)(r2 & (NL - 1));
        long long e = r2 >> 2;
        rp[((e * NTOK + n) * NL + lay) * D4 + d4] = tff4(retr[i]);
    }
}

__global__ void zero_k(float* __restrict__ p, long long n) {
    long long i = (long long)blockIdx.x * 256 + threadIdx.x;
    if (i < n) p[i] = 0.f;
}

__global__ void gate_dot_k(const float* __restrict__ outs, const float* __restrict__ gg,
                           float* __restrict__ glog) {
    int e = blockIdx.x;
    constexpr int D4 = DIM / 4;
    long long chunk4 = (long long)(ND_ELEMS / 4) / gridDim.y;
    const float4* base = (const float4*)(outs) + (long long)e * (ND_ELEMS / 4) + (long long)blockIdx.y * chunk4;
    const float4* gg4 = (const float4*)gg;
    float acc = 0.f;
    for (long long i = threadIdx.x; i < chunk4; i += blockDim.x) {
        float4 v = base[i];
        float4 g = gg4[i & (D4 - 1)];
        acc += v.x * g.x + v.y * g.y + v.z * g.z + v.w * g.w;
    }
    acc = warpReduceSum(acc);
    __shared__ float sh[8];
    int lane = threadIdx.x & 31, wid = threadIdx.x >> 5;
    if (lane == 0) sh[wid] = acc;
    __syncthreads();
    if (threadIdx.x == 0) {
        float x = 0;
        for (int q = 0; q < 8; q++) x += sh[q];
        atomicAdd(&glog[e], x);
    }
}

__global__ void gate_softmax_k(const float* __restrict__ glog, float* __restrict__ gw) {
    if (threadIdx.x == 0) {
        float l[EXP], m = -1e30f;
        for (int e = 0; e < EXP; e++) {
            l[e] = fminf(fmaxf(glog[e] / (float)NTOK, -10.f), 10.f);
            m = fmaxf(m, l[e]);
        }
        float s = 0.f;
        for (int e = 0; e < EXP; e++) { l[e] = expf(l[e] - m); s += l[e]; }
        for (int e = 0; e < EXP; e++) gw[e] = l[e] / s;
    }
}

__global__ void fuse_k(const float4* __restrict__ outs, const float* __restrict__ gw,
                       float4* __restrict__ fused) {
    long long i = (long long)blockIdx.x * 256 + threadIdx.x;
    constexpr long long N4 = ND_ELEMS / 4;
    if (i < N4) {
        float4 r = make_float4(0.f, 0.f, 0.f, 0.f);
#pragma unroll
        for (int e = 0; e < EXP; e++) {
            float4 v = outs[(long long)e * N4 + i];
            float gwe = gw[e];
            r.x += gwe * v.x; r.y += gwe * v.y; r.z += gwe * v.z; r.w += gwe * v.w;
        }
        fused[i] = r;
    }
}

// o = 0.9*mem + clip(0.1 * sum_e upd4[e], +-0.1)  (float4)
__global__ void memupd_k(const float4* __restrict__ mem, const float4* __restrict__ upd4,
                         float4* __restrict__ o) {
    long long i = (long long)blockIdx.x * 256 + threadIdx.x;
    constexpr long long N4 = (long long)LMD_ELEMS / 4;
    if (i < N4) {
        float4 u = upd4[i];
#pragma unroll
        for (int e = 1; e < EXP; e++) {
            float4 v = upd4[(long long)e * N4 + i];
            u.x += v.x; u.y += v.y; u.z += v.z; u.w += v.w;
        }
        float4 mm = mem[i];
        float4 r;
        r.x = 0.9f * mm.x + fminf(fmaxf(0.1f * u.x, -0.1f), 0.1f);
        r.y = 0.9f * mm.y + fminf(fmaxf(0.1f * u.y, -0.1f), 0.1f);
        r.z = 0.9f * mm.z + fminf(fmaxf(0.1f * u.z, -0.1f), 0.1f);
        r.w = 0.9f * mm.w + fminf(fmaxf(0.1f * u.w, -0.1f), 0.1f);
        o[i] = r;
    }
}

// ---------------- host ----------------
static constexpr int stgFl(int MT, int NT, bool ATR, bool BTR) {
    return (ATR ? 16 * (MT + 8) : MT * 20) + (BTR ? 16 * (NT + 8) : NT * 20);
}
#define SMEMB(MT, NT, ATR, BTR) (4 * stgFl(MT, NT, ATR, BTR) * 4)

static void tfround(const float* s, float* d, long long n) {
    long long n4 = n / 4;
    tfround_k<<<(int)((n4 + 255) / 256), 256>>>((const float4*)s, (float4*)d, n4);
}

extern "C" void kernel_launch(void* const* d_in, const int* in_sizes, int n_in,
                              void* d_out, int out_size) {
    const float* tokens   = (const float*)d_in[0];
    const float* memories = (const float*)d_in[1];
    const float* ipw      = (const float*)d_in[2];
    const float* ipb      = (const float*)d_in[3];
    const float* opw      = (const float*)d_in[4];
    const float* opb      = (const float*)d_in[5];
    const float* w1       = (const float*)d_in[6];
    const float* b1       = (const float*)d_in[7];
    const float* w2       = (const float*)d_in[8];
    const float* b2       = (const float*)d_in[9];
    const float* n1w      = (const float*)d_in[10];
    const float* n1b      = (const float*)d_in[11];
    const float* n2w      = (const float*)d_in[12];
    const float* n2b      = (const float*)d_in[13];
    const float* aggw     = (const float*)d_in[14];
    const float* aggb     = (const float*)d_in[15];
    const float* gg       = (const float*)d_in[16];

    float* out = (float*)d_out;
    float* out_fused = out;
    float* out_gw = out + ND_ELEMS;
    float* out_mem = out + ND_ELEMS + EXP;

    static float *p_xln = nullptr, *p_x4 = nullptr, *p_qkv4 = nullptr, *p_big = nullptr,
                 *p_sa4 = nullptr, *p_op4 = nullptr, *p_tmp4 = nullptr,
                 *p_x14 = nullptr, *p_x1r4 = nullptr, *p_xor4 = nullptr, *p_out = nullptr,
                 *p_retr4 = nullptr, *p_retrp4 = nullptr, *p_upd4 = nullptr, *p_glog = nullptr,
                 *p_vT = nullptr, *p_memT = nullptr,
                 *p_ipw = nullptr, *p_opw = nullptr, *p_w1 = nullptr, *p_w2 = nullptr,
                 *p_aggw = nullptr, *p_mem = nullptr;
    if (!p_xln) {
        cudaGetSymbolAddress((void**)&p_xln, g_xln);
        cudaGetSymbolAddress((void**)&p_x4, g_x4);
        cudaGetSymbolAddress((void**)&p_qkv4, g_qkv4);
        cudaGetSymbolAddress((void**)&p_big, g_big);
        cudaGetSymbolAddress((void**)&p_sa4, g_sa4);
        cudaGetSymbolAddress((void**)&p_op4, g_op4);
        cudaGetSymbolAddress((void**)&p_tmp4, g_tmp4);
        cudaGetSymbolAddress((void**)&p_x14, g_x14);
        cudaGetSymbolAddress((void**)&p_x1r4, g_x1r4);
        cudaGetSymbolAddress((void**)&p_xor4, g_xor4);
        cudaGetSymbolAddress((void**)&p_out, g_out);
        cudaGetSymbolAddress((void**)&p_retr4, g_retr4);
        cudaGetSymbolAddress((void**)&p_retrp4, g_retrp4);
        cudaGetSymbolAddress((void**)&p_upd4, g_upd4);
        cudaGetSymbolAddress((void**)&p_glog, g_glog);
        cudaGetSymbolAddress((void**)&p_vT, g_vT);
        cudaGetSymbolAddress((void**)&p_memT, g_memT);
        cudaGetSymbolAddress((void**)&p_ipw, g_ipw_r);
        cudaGetSymbolAddress((void**)&p_opw, g_opw_r);
        cudaGetSymbolAddress((void**)&p_w1, g_w1_r);
        cudaGetSymbolAddress((void**)&p_w2, g_w2_r);
        cudaGetSymbolAddress((void**)&p_aggw, g_aggw_r);
        cudaGetSymbolAddress((void**)&p_mem, g_mem_r);
        cudaFuncSetAttribute(gemmCP<64, 128, false, false, 3>, cudaFuncAttributeMaxDynamicSharedMemorySize, SMEMB(64, 128, false, false));
        cudaFuncSetAttribute(gemmCP<64, 64, false, false, 3>,  cudaFuncAttributeMaxDynamicSharedMemorySize, SMEMB(64, 64, false, false));
        cudaFuncSetAttribute(gemmCP<64, 128, false, true, 2>,  cudaFuncAttributeMaxDynamicSharedMemorySize, SMEMB(64, 128, false, true));
        cudaFuncSetAttribute(gemmCP<64, 128, true, true, 2>,   cudaFuncAttributeMaxDynamicSharedMemorySize, SMEMB(64, 128, true, true));
    }

    const float inv_sqrt_d = 1.0f / sqrtf((float)DIM);
    const float inv_sqrt_dh = 1.0f / sqrtf((float)DHEAD);

    tfround(ipw, p_ipw, (long long)EXP * 3 * DIM * DIM);
    tfround(opw, p_opw, (long long)EXP * DIM * DIM);
    tfround(w1, p_w1, (long long)EXP * FFD * DIM);
    tfround(w2, p_w2, (long long)EXP * DIM * FFD);
    tfround(aggw, p_aggw, (long long)DIM * NL * DIM);
    tfround(memories, p_mem, (long long)LMD_ELEMS);
    // memT[l][d][m] = tf(mem[l][m][d])
    transpose_k<1><<<dim3(DIM / 32, MEMSZ / 32, NL), dim3(32, 8)>>>(
        memories, p_memT, MEMSZ, DIM, DIM, (long long)MEMSZ * DIM, (long long)MEMSZ * DIM);

    zero_k<<<1, 256>>>(p_glog, EXP);
    ln_k<<<EXP * NTOK, 128>>>(tokens, p_xln);

    const long long LLND = ND_ELEMS;
    const long long BIGE = (long long)NH * NTOK * NTOK;
    const long long QKVE = (long long)NTOK * 3 * DIM;

    // 1. cross logits [e][2048, 6144]
    gemmCP<64, 128, false, false, 3><<<dim3(48, 32, EXP), 256, SMEMB(64, 128, false, false)>>>(
        p_xln, p_xln, p_big, DIM, DIM, DIM, 3 * NTOK,
        LLND, 0, 0, 0, (long long)NTOK * 3 * NTOK, 0, 1,
        inv_sqrt_d, nullptr, 0, nullptr, 0, 0, 10.f, 0, -1, NTOK);
    softmax_k<<<EXP * NTOK, 256, 3 * NTOK * 4>>>(p_big, 3 * NTOK);
    // 2. x = probs @ ctx + xln (rounded)
    gemmCP<64, 128, false, true, 2><<<dim3(4, 32, EXP), 256, SMEMB(64, 128, false, true)>>>(
        p_big, p_xln, p_x4, 3 * NTOK, 3 * NTOK, DIM, DIM,
        (long long)NTOK * 3 * NTOK, 0, 0, 0, LLND, 0, 1,
        1.f, nullptr, 0, p_xln, LLND, DIM, 0.f, GFLAG_TFOUT, -1, NTOK);
    // 3. qkv (rounded)
    gemmCP<64, 128, false, false, 3><<<dim3(12, 32, EXP), 256, SMEMB(64, 128, false, false)>>>(
        p_x4, p_ipw, p_qkv4, DIM, DIM, DIM, 3 * DIM,
        LLND, 0, (long long)3 * DIM * DIM, 0, QKVE, 0, 1,
        1.f, ipb, 3 * DIM, nullptr, 0, 0, 0.f, GFLAG_TFOUT, 0, 0);
    // 3b. vT[e][hd][n] = qkv[e][n][2D+hd]
    transpose_k<0><<<dim3(DIM / 32, NTOK / 32, EXP), dim3(32, 8)>>>(
        p_qkv4 + 2 * DIM, p_vT, NTOK, DIM, 3 * DIM, QKVE, LLND);
    // 4. scores [e][h][2048,2048]
    gemmCP<64, 128, false, false, 3><<<dim3(16, 32, EXP * NH), 256, SMEMB(64, 128, false, false)>>>(
        p_qkv4, p_qkv4 + DIM, p_big, DHEAD, 3 * DIM, 3 * DIM, NTOK,
        QKVE, DHEAD, QKVE, DHEAD, BIGE, (long long)NTOK * NTOK, NH,
        inv_sqrt_dh, nullptr, 0, nullptr, 0, 0, 0.f, 0, 0, 0);
    softmax_k<<<EXP * NH * NTOK, 256, NTOK * 4>>>(p_big, NTOK);
    // 5. sa = probs @ v (natural B via vT, rounded)
    gemmCP<64, 64, false, false, 3><<<dim3(1, 32, EXP * NH), 256, SMEMB(64, 64, false, false)>>>(
        p_big, p_vT, p_sa4, NTOK, NTOK, NTOK, DIM,
        BIGE, (long long)NTOK * NTOK, LLND, (long long)DHEAD * NTOK, LLND, DHEAD, NH,
        1.f, nullptr, 0, nullptr, 0, 0, 0.f, GFLAG_TFOUT, 0, 0);
    // 6. out_proj
    gemmCP<64, 128, false, false, 3><<<dim3(4, 32, EXP), 256, SMEMB(64, 128, false, false)>>>(
        p_sa4, p_opw, p_op4, DIM, DIM, DIM, DIM,
        LLND, 0, (long long)DIM * DIM, 0, LLND, 0, 1,
        1.f, opb, DIM, nullptr, 0, 0, 0.f, 0, 0, 0);
    ln_ra_k<<<EXP * NTOK, 128>>>(p_x4, p_op4, n1w, n1b, p_x14, p_x1r4);
    // 7. ff1 relu (rounded)
    gemmCP<64, 128, false, false, 3><<<dim3(16, 32, EXP), 256, SMEMB(64, 128, false, false)>>>(
        p_x1r4, p_w1, p_tmp4, DIM, DIM, DIM, FFD,
        LLND, 0, (long long)FFD * DIM, 0, (long long)NTOK * FFD, 0, 1,
        1.f, b1, FFD, nullptr, 0, 0, 0.f, GFLAG_RELU | GFLAG_TFOUT, 0, 0);
    // 8. ff2
    gemmCP<64, 128, false, false, 3><<<dim3(4, 32, EXP), 256, SMEMB(64, 128, false, false)>>>(
        p_tmp4, p_w2, p_sa4, FFD, FFD, FFD, DIM,
        (long long)NTOK * FFD, 0, (long long)DIM * FFD, 0, LLND, 0, 1,
        1.f, b2, DIM, nullptr, 0, 0, 0.f, 0, 0, 0);
    ln_ra_k<<<EXP * NTOK, 128>>>(p_x14, p_sa4, n2w, n2b, p_out, p_xor4);
    // 9. memory logits [e][l][2048,4096]
    gemmCP<64, 128, false, false, 3><<<dim3(32, 32, EXP * NL), 256, SMEMB(64, 128, false, false)>>>(
        p_xor4, p_mem, p_big, DIM, DIM, DIM, MEMSZ,
        LLND, 0, 0, (long long)MEMSZ * DIM, (long long)NL * NTOK * MEMSZ, (long long)NTOK * MEMSZ, NL,
        inv_sqrt_d, nullptr, 0, nullptr, 0, 0, 10.f, 0, 0, 0);
    softmax_k<<<EXP * NL * NTOK, 256, MEMSZ * 4>>>(p_big, MEMSZ);
    // 10. retr (natural B via memT)
    gemmCP<64, 128, false, false, 3><<<dim3(4, 32, EXP * NL), 256, SMEMB(64, 128, false, false)>>>(
        p_big, p_memT, p_retr4, MEMSZ, MEMSZ, MEMSZ, DIM,
        (long long)NL * NTOK * MEMSZ, (long long)NTOK * MEMSZ, 0, (long long)MEMSZ * DIM,
        (long long)NL * NTOK * DIM, (long long)NTOK * DIM, NL,
        1.f, nullptr, 0, nullptr, 0, 0, 0.f, 0, 0, 0);
    // 11. upd4[e][l] = clip(am^T @ xout, 1)
    gemmCP<64, 128, true, true, 2><<<dim3(4, 64, EXP * NL), 256, SMEMB(64, 128, true, true)>>>(
        p_big, p_xor4, p_upd4, NTOK, MEMSZ, DIM, DIM,
        (long long)NL * NTOK * MEMSZ, (long long)NTOK * MEMSZ, LLND, 0,
        (long long)LMD_ELEMS, (long long)MEMSZ * DIM, NL,
        1.f, nullptr, 0, nullptr, 0, 0, 1.f, 0, 0, 0);
    permute_k<<<(EXP * NL * ND_ELEMS / 4 + 255) / 256, 256>>>((const float4*)p_retr4, (float4*)p_retrp4);
    // 12. outs += retrp @ aggw^T + aggb
    gemmCP<64, 128, false, false, 3><<<dim3(4, 32, EXP), 256, SMEMB(64, 128, false, false)>>>(
        p_retrp4, p_aggw, p_out, NL * DIM, NL * DIM, NL * DIM, DIM,
        (long long)NTOK * NL * DIM, 0, 0, 0, LLND, 0, 1,
        1.f, aggb, 0, p_out, LLND, DIM, 0.f, 0, 0, 0);

    dim3 ggrid(EXP, 16);
    gate_dot_k<<<ggrid, 256>>>(p_out, gg, p_glog);
    gate_softmax_k<<<1, 32>>>(p_glog, out_gw);
    fuse_k<<<(ND_ELEMS / 4 + 255) / 256, 256>>>((const float4*)p_out, out_gw, (float4*)out_fused);
    memupd_k<<<(LMD_ELEMS / 4 + 255) / 256, 256>>>((const float4*)memories, (const float4*)p_upd4, (float4*)out_mem);

    (void)in_sizes; (void)n_in; (void)out_size;
}

// round 11
// speedup vs baseline: 5.9868x; 1.0130x over previous
#include <cuda_runtime.h>
#include <math.h>
#include <stdint.h>

#define EXP 4
#define NTOK 2048
#define DIM 512
#define NH 8
#define DHEAD 64
#define FFD 2048
#define NL 4
#define MEMSZ 4096

#define ND_ELEMS (NTOK * DIM)
#define LMD_ELEMS (NL * MEMSZ * DIM)

#define GFLAG_RELU 1
#define GFLAG_ACCUM 2
#define GFLAG_TFOUT 4
#define GFLAG_KREMAP 8

// ---------------- scratch ----------------
__device__ float g_xln[EXP * NTOK * DIM];
__device__ float g_xlnT[EXP * NTOK * DIM];                // [d][e*2048+n]
__device__ float g_x4[EXP * NTOK * DIM];
__device__ float g_qkv4[(size_t)EXP * NTOK * 3 * DIM];
__device__ float g_big[(size_t)EXP * NH * NTOK * NTOK];
__device__ float g_sa4[EXP * NTOK * DIM];
__device__ float g_op4[EXP * NTOK * DIM];
__device__ float g_tmp4[(size_t)EXP * NTOK * FFD];
__device__ float g_x14[EXP * NTOK * DIM];
__device__ float g_x1r4[EXP * NTOK * DIM];
__device__ float g_xor4[EXP * NTOK * DIM];
__device__ float g_xorT[EXP * NTOK * DIM];                // [e][d][n]
__device__ float g_out[EXP * NTOK * DIM];
__device__ float g_retr4[(size_t)EXP * NL * NTOK * DIM];
__device__ float g_retrp4[(size_t)EXP * NTOK * NL * DIM];
__device__ float g_upd4[(size_t)EXP * NL * MEMSZ * DIM];
__device__ float g_glog[EXP];
__device__ float g_vT[(size_t)EXP * NTOK * DIM];          // [e][h*64+dh][n]
__device__ float g_memT[LMD_ELEMS];                       // [l][d][m]
// pre-rounded weights
__device__ float g_ipw_r[EXP * 3 * DIM * DIM];
__device__ float g_opw_r[EXP * DIM * DIM];
__device__ float g_w1_r[EXP * FFD * DIM];
__device__ float g_w2_r[EXP * DIM * FFD];
__device__ float g_aggw_r[DIM * NL * DIM];
__device__ float g_mem_r[LMD_ELEMS];

// ---------------- helpers ----------------
__device__ __forceinline__ uint32_t tf(float x) {
    uint32_t u; asm("cvt.rna.tf32.f32 %0, %1;" : "=r"(u) : "f"(x)); return u;
}
__device__ __forceinline__ float tff(float x) { return __uint_as_float(tf(x)); }
__device__ __forceinline__ float4 tff4(float4 v) {
    return make_float4(tff(v.x), tff(v.y), tff(v.z), tff(v.w));
}
__device__ __forceinline__ void mma8(float* c, const uint32_t* a, const uint32_t* b) {
    asm volatile(
        "mma.sync.aligned.m16n8k8.row.col.f32.tf32.tf32.f32 "
        "{%0,%1,%2,%3}, {%4,%5,%6,%7}, {%8,%9}, {%0,%1,%2,%3};"
        : "+f"(c[0]), "+f"(c[1]), "+f"(c[2]), "+f"(c[3])
        : "r"(a[0]), "r"(a[1]), "r"(a[2]), "r"(a[3]), "r"(b[0]), "r"(b[1]));
}
__device__ __forceinline__ void cpa16(uint32_t s, const float* g) {
    asm volatile("cp.async.cg.shared.global [%0], [%1], 16;" :: "r"(s), "l"(g));
}
__device__ __forceinline__ void ldsm4(uint32_t* r, uint32_t a) {
    asm volatile("ldmatrix.sync.aligned.m8n8.x4.shared.b16 {%0,%1,%2,%3}, [%4];"
        : "=r"(r[0]), "=r"(r[1]), "=r"(r[2]), "=r"(r[3]) : "r"(a));
}

__global__ void tfround_k(const float4* __restrict__ s, float4* __restrict__ d, long long n4) {
    long long i = (long long)blockIdx.x * 256 + threadIdx.x;
    if (i < n4) d[i] = tff4(s[i]);
}

// 32x32 tiled transpose: in [z][rows][cols] (ldin) -> out [z][cols][rows]
template <int ROUND>
__global__ void transpose_k(const float* __restrict__ in, float* __restrict__ out,
                            int rows, int cols, int ldin,
                            long long inB, long long outB) {
    __shared__ float tile[32][33];
    int z = blockIdx.z;
    in += inB * z; out += outB * z;
    int c0 = blockIdx.x * 32, r0 = blockIdx.y * 32;
    int x = threadIdx.x, y = threadIdx.y;
#pragma unroll
    for (int j = 0; j < 32; j += 8)
        tile[y + j][x] = in[(long long)(r0 + y + j) * ldin + c0 + x];
    __syncthreads();
#pragma unroll
    for (int j = 0; j < 32; j += 8) {
        float v = tile[x][y + j];
        out[(long long)(c0 + y + j) * rows + r0 + x] = ROUND ? tff(v) : v;
    }
}

// ---------------- cp.async tf32 mma GEMM, expert-batched z ----------------
template <int MT, int NT, bool ATR, bool BTR, int OCC>
__global__ void __launch_bounds__(256, OCC) gemmCP(
    const float* __restrict__ A, const float* __restrict__ B, float* __restrict__ C,
    int K, int lda, int ldb, int ldc,
    long long aB, long long aBi, long long bB, long long bBi,
    long long cB, long long cBi, int zInner,
    float alpha, const float* __restrict__ bias, long long biasB,
    const float* __restrict__ resid, long long residB, int residLd,
    float clipVal, int flags, int rs, int rl)
{
    constexpr int KC = 16;
    constexpr int AST = 20;
    constexpr int MST = MT + 8;
    constexpr int NST = NT + 8;
    constexpr int ASZ = ATR ? KC * MST : MT * AST;
    constexpr int BSZ = BTR ? KC * NST : NT * AST;
    constexpr int STG = ASZ + BSZ;
    constexpr int MI = MT / 32;
    constexpr int NB = NT / 32;

    extern __shared__ float sm[];
    uint32_t smb = (uint32_t)__cvta_generic_to_shared(sm);

    const int t = threadIdx.x, l = t & 31, w = t >> 5;
    const int bz = blockIdx.z;
    const int zo = bz / zInner, zi = bz - zo * zInner;
    A += aB * zo + aBi * zi;
    B += bB * zo + bBi * zi;
    C += cB * zo + cBi * zi;
    if (bias) bias += biasB * zo;
    if (resid) resid += residB * zo;
    if (rs < 0) rs = zo * rl;
    const int m0 = blockIdx.y * MT, n0 = blockIdx.x * NT;
    const int wm0 = (w >> 2) * (MT / 2), wn0 = (w & 3) * (NT / 4);

    const uint32_t aBase = (uint32_t)(((wm0 + ((l >> 3 & 1) << 3) + (l & 7)) * AST + ((l >> 4) << 2)) * 4);
    const uint32_t bBase4 = (uint32_t)(((wn0 + ((l >> 4) << 3) + (l & 7)) * AST + ((l >> 3 & 1) << 2)) * 4);
    const int atrOff = (l & 3) * MST + wm0 + (l >> 2);
    const int btrOff = (l & 3) * NST + wn0 + (l >> 2);

    float acc[MI][NB][4];
#pragma unroll
    for (int a = 0; a < MI; a++)
#pragma unroll
        for (int b = 0; b < NB; b++)
#pragma unroll
            for (int c = 0; c < 4; c++) acc[a][b][c] = 0.f;

    const int nK = K / KC;
    const bool kRemap = (flags & GFLAG_KREMAP) != 0;

    auto issue = [&](int s, int k0) {
        uint32_t ab = smb + (uint32_t)(s * STG * 4);
        uint32_t bb = ab + ASZ * 4;
        if (!ATR) {
            constexpr int ACH = MT * 4;
#pragma unroll
            for (int c0 = 0; c0 < ACH; c0 += 256) {
                int c = c0 + t;
                int row = c >> 2, kq = c & 3;
                cpa16(ab + (uint32_t)(row * AST + kq * 4) * 4,
                      &A[(long long)(m0 + row) * lda + k0 + kq * 4]);
            }
        } else {
            constexpr int AQ = MT / 4;
            constexpr int ASH = (MT == 128) ? 5 : 4;
            constexpr int ACH = KC * AQ;
#pragma unroll
            for (int c0 = 0; c0 < ACH; c0 += 256) {
                int c = c0 + t;
                int kr = c >> ASH, mq = c & (AQ - 1);
                cpa16(ab + (uint32_t)(kr * MST + mq * 4) * 4,
                      &A[(long long)(k0 + kr) * lda + m0 + mq * 4]);
            }
        }
        if (!BTR) {
            constexpr int BCH = NT * 4;
#pragma unroll
            for (int c0 = 0; c0 < BCH; c0 += 256) {
                int c = c0 + t;
                int row = c >> 2, kq = c & 3;
                int n = n0 + row;
                int g = k0 + kq * 4;
                if (rl) {
                    if (kRemap) { if (g >= rs) g += rl; }
                    else { if (n >= rs) n += rl; }
                }
                cpa16(bb + (uint32_t)(row * AST + kq * 4) * 4,
                      &B[(long long)n * ldb + g]);
            }
        } else {
            constexpr int NQ = NT / 4;
            constexpr int SH = (NT == 128) ? 5 : 4;
            constexpr int BCH = KC * NQ;
#pragma unroll
            for (int c0 = 0; c0 < BCH; c0 += 256) {
                int c = c0 + t;
                int kr = c >> SH, nq = c & (NQ - 1);
                int g = k0 + kr;
                if (rl && g >= rs) g += rl;
                cpa16(bb + (uint32_t)(kr * NST + nq * 4) * 4,
                      &B[(long long)g * ldb + n0 + nq * 4]);
            }
        }
        asm volatile("cp.async.commit_group;" ::: "memory");
    };

    issue(0, 0);
    issue(1, KC);
    issue(2, 2 * KC);

    for (int i = 0; i < nK; i++) {
        asm volatile("cp.async.wait_group 2;" ::: "memory");
        __syncthreads();
        if (i + 3 < nK) issue((i + 3) & 3, (i + 3) * KC);

        const float* Ab = sm + (i & 3) * STG;
        const float* Bb = Ab + ASZ;
        uint32_t abu = smb + (uint32_t)((i & 3) * STG * 4);
        uint32_t bbu = abu + (uint32_t)(ASZ * 4);
#pragma unroll
        for (int kk = 0; kk < 2; kk++) {
            const int kc = kk * 8;
            uint32_t af[MI][4], bf[NB][2];
#pragma unroll
            for (int mi = 0; mi < MI; mi++) {
                if (!ATR) {
                    ldsm4(af[mi], abu + aBase + (uint32_t)((mi * 16 * AST + kc) * 4));
                } else {
                    const uint32_t* ap = (const uint32_t*)&Ab[kc * MST + atrOff + mi * 16];
                    af[mi][0] = ap[0];
                    af[mi][1] = ap[8];
                    af[mi][2] = ap[4 * MST];
                    af[mi][3] = ap[4 * MST + 8];
                }
            }
            if (!BTR) {
#pragma unroll
                for (int nj = 0; nj < NB / 2; nj++) {
                    uint32_t r4[4];
                    ldsm4(r4, bbu + bBase4 + (uint32_t)((nj * 16 * AST + kc) * 4));
                    bf[2 * nj][0] = r4[0]; bf[2 * nj][1] = r4[1];
                    bf[2 * nj + 1][0] = r4[2]; bf[2 * nj + 1][1] = r4[3];
                }
            } else {
#pragma unroll
                for (int ni = 0; ni < NB; ni++) {
                    const uint32_t* bp = (const uint32_t*)&Bb[kc * NST + btrOff + ni * 8];
                    bf[ni][0] = bp[0];
                    bf[ni][1] = bp[4 * NST];
                }
            }
#pragma unroll
            for (int mi = 0; mi < MI; mi++)
#pragma unroll
                for (int ni = 0; ni < NB; ni++) mma8(acc[mi][ni], af[mi], bf[ni]);
        }
    }

    // epilogue
#pragma unroll
    for (int mi = 0; mi < MI; mi++) {
        int row0 = m0 + wm0 + mi * 16 + (l >> 2);
#pragma unroll
        for (int ni = 0; ni < NB; ni++) {
            int col = n0 + wn0 + ni * 8 + (l & 3) * 2;
#pragma unroll
            for (int h = 0; h < 2; h++) {
                int row = row0 + h * 8;
                float vx = alpha * acc[mi][ni][h * 2];
                float vy = alpha * acc[mi][ni][h * 2 + 1];
                if (bias) { vx += bias[col]; vy += bias[col + 1]; }
                if (flags & GFLAG_RELU) { vx = fmaxf(vx, 0.f); vy = fmaxf(vy, 0.f); }
                if (clipVal > 0.f) {
                    vx = fminf(fmaxf(vx, -clipVal), clipVal);
                    vy = fminf(fmaxf(vy, -clipVal), clipVal);
                }
                if (resid) {
                    float2 rv = *(const float2*)&resid[(long long)row * residLd + col];
                    vx += rv.x; vy += rv.y;
                }
                float2* cp = (float2*)&C[(long long)row * ldc + col];
                if (flags & GFLAG_ACCUM) {
                    float2 o = *cp;
                    vx += o.x; vy += o.y;
                }
                if (flags & GFLAG_TFOUT) { vx = tff(vx); vy = tff(vy); }
                *cp = make_float2(vx, vy);
            }
        }
    }
}

// ---------------- reductions ----------------
__device__ __forceinline__ float warpReduceSum(float v) {
#pragma unroll
    for (int o = 16; o; o >>= 1) v += __shfl_xor_sync(0xffffffffu, v, o);
    return v;
}
__device__ __forceinline__ float warpReduceMax(float v) {
#pragma unroll
    for (int o = 16; o; o >>= 1) v = fmaxf(v, __shfl_xor_sync(0xffffffffu, v, o));
    return v;
}

// ---------------- vectorized smem-cached row softmax ----------------
__global__ void softmax_k(float* __restrict__ p, int cols) {
    extern __shared__ float4 sb4[];
    float4* row = (float4*)(p + (long long)blockIdx.x * cols);
    int nc4 = cols >> 2;
    __shared__ float sh[8];
    __shared__ float sb;
    int tid = threadIdx.x, lane = tid & 31, wid = tid >> 5;
    float m = -1e30f;
    for (int i = tid; i < nc4; i += 256) {
        float4 v = row[i]; sb4[i] = v;
        m = fmaxf(m, fmaxf(fmaxf(v.x, v.y), fmaxf(v.z, v.w)));
    }
    m = warpReduceMax(m);
    if (lane == 0) sh[wid] = m;
    __syncthreads();
    if (tid == 0) { float x = sh[0]; for (int q = 1; q < 8; q++) x = fmaxf(x, sh[q]); sb = x; }
    __syncthreads();
    m = sb;
    float s = 0.f;
    for (int i = tid; i < nc4; i += 256) {
        float4 v = sb4[i];
        v.x = expf(v.x - m); v.y = expf(v.y - m); v.z = expf(v.z - m); v.w = expf(v.w - m);
        sb4[i] = v;
        s += v.x + v.y + v.z + v.w;
    }
    s = warpReduceSum(s);
    if (lane == 0) sh[wid] = s;
    __syncthreads();
    if (tid == 0) { float x = 0; for (int q = 0; q < 8; q++) x += sh[q]; sb = 1.f / x; }
    __syncthreads();
    float inv = sb;
    for (int i = tid; i < nc4; i += 256) {
        float4 v = sb4[i];
        row[i] = make_float4(tff(v.x * inv), tff(v.y * inv), tff(v.z * inv), tff(v.w * inv));
    }
}

// ---------------- LayerNorm (vectorized, rounded output) ----------------
__global__ void ln_k(const float* __restrict__ src, float* __restrict__ dst) {
    long long row = blockIdx.x;
    const float4* x = (const float4*)(src + row * DIM);
    float4* y = (float4*)(dst + row * DIM);
    int tid = threadIdx.x, lane = tid & 31, wid = tid >> 5;
    float4 v = x[tid];
    float s = v.x + v.y + v.z + v.w;
    float s2 = v.x * v.x + v.y * v.y + v.z * v.z + v.w * v.w;
    s = warpReduceSum(s); s2 = warpReduceSum(s2);
    __shared__ float sh[2][4]; __shared__ float mv[2];
    if (lane == 0) { sh[0][wid] = s; sh[1][wid] = s2; }
    __syncthreads();
    if (tid == 0) {
        float a = sh[0][0] + sh[0][1] + sh[0][2] + sh[0][3];
        float b = sh[1][0] + sh[1][1] + sh[1][2] + sh[1][3];
        float mean = a / DIM;
        mv[0] = mean; mv[1] = rsqrtf(b / DIM - mean * mean + 1e-5f);
    }
    __syncthreads();
    float mean = mv[0], rstd = mv[1];
    y[tid] = make_float4(tff((v.x - mean) * rstd), tff((v.y - mean) * rstd),
                         tff((v.z - mean) * rstd), tff((v.w - mean) * rstd));
}

// batched: e = row >> 11
__global__ void ln_ra_k(const float* __restrict__ a, const float* __restrict__ b,
                        const float* __restrict__ wAll, const float* __restrict__ bAll,
                        float* __restrict__ dst, float* __restrict__ dstr) {
    long long row = blockIdx.x;
    int e = (int)(row >> 11);
    const float4* xa = (const float4*)(a + row * DIM);
    const float4* xb = (const float4*)(b + row * DIM);
    const float4* w = (const float4*)(wAll + (long long)e * DIM);
    const float4* bb = (const float4*)(bAll + (long long)e * DIM);
    float4* y = (float4*)(dst + row * DIM);
    float4* yr = (float4*)(dstr + row * DIM);
    int tid = threadIdx.x, lane = tid & 31, wid = tid >> 5;
    float4 va = xa[tid], vb = xb[tid];
    float4 v = make_float4(va.x + vb.x, va.y + vb.y, va.z + vb.z, va.w + vb.w);
    float s = v.x + v.y + v.z + v.w;
    float s2 = v.x * v.x + v.y * v.y + v.z * v.z + v.w * v.w;
    s = warpReduceSum(s); s2 = warpReduceSum(s2);
    __shared__ float sh[2][4]; __shared__ float mv[2];
    if (lane == 0) { sh[0][wid] = s; sh[1][wid] = s2; }
    __syncthreads();
    if (tid == 0) {
        float p = sh[0][0] + sh[0][1] + sh[0][2] + sh[0][3];
        float q = sh[1][0] + sh[1][1] + sh[1][2] + sh[1][3];
        float mean = p / DIM;
        mv[0] = mean; mv[1] = rsqrtf(q / DIM - mean * mean + 1e-5f);
    }
    __syncthreads();
    float mean = mv[0], rstd = mv[1];
    float4 ww = w[tid], bbv = bb[tid];
    float4 o = make_float4((v.x - mean) * rstd * ww.x + bbv.x,
                           (v.y - mean) * rstd * ww.y + bbv.y,
                           (v.z - mean) * rstd * ww.z + bbv.z,
                           (v.w - mean) * rstd * ww.w + bbv.w);
    y[tid] = o;
    yr[tid] = tff4(o);
}

// retr4[e][l][n][d] -> retrp4[e][n][l*D+d], tf32-rounded, float4
__global__ void permute_k(const float4* __restrict__ retr, float4* __restrict__ rp) {
    long long i = (long long)blockIdx.x * 256 + threadIdx.x;
    constexpr int D4 = DIM / 4;
    if (i < (long long)EXP * NL * NTOK * D4) {
        int d4 = (int)(i & (D4 - 1));
        long long r = i >> 7;
        int n = (int)(r & (NTOK - 1));
        long long r2 = r >> 11;
        int lay = (int)(r2 & (NL - 1));
        long long e = r2 >> 2;
        rp[((e * NTOK + n) * NL + lay) * D4 + d4] = tff4(retr[i]);
    }
}

__global__ void zero_k(float* __restrict__ p, long long n) {
    long long i = (long long)blockIdx.x * 256 + threadIdx.x;
    if (i < n) p[i] = 0.f;
}

__global__ void gate_dot_k(const float* __restrict__ outs, const float* __restrict__ gg,
                           float* __restrict__ glog) {
    int e = blockIdx.x;
    constexpr int D4 = DIM / 4;
    long long chunk4 = (long long)(ND_ELEMS / 4) / gridDim.y;
    const float4* base = (const float4*)(outs) + (long long)e * (ND_ELEMS / 4) + (long long)blockIdx.y * chunk4;
    const float4* gg4 = (const float4*)gg;
    float acc = 0.f;
    for (long long i = threadIdx.x; i < chunk4; i += blockDim.x) {
        float4 v = base[i];
        float4 g = gg4[i & (D4 - 1)];
        acc += v.x * g.x + v.y * g.y + v.z * g.z + v.w * g.w;
    }
    acc = warpReduceSum(acc);
    __shared__ float sh[8];
    int lane = threadIdx.x & 31, wid = threadIdx.x >> 5;
    if (lane == 0) sh[wid] = acc;
    __syncthreads();
    if (threadIdx.x == 0) {
        float x = 0;
        for (int q = 0; q < 8; q++) x += sh[q];
        atomicAdd(&glog[e], x);
    }
}

__global__ void gate_softmax_k(const float* __restrict__ glog, float* __restrict__ gw) {
    if (threadIdx.x == 0) {
        float l[EXP], m = -1e30f;
        for (int e = 0; e < EXP; e++) {
            l[e] = fminf(fmaxf(glog[e] / (float)NTOK, -10.f), 10.f);
            m = fmaxf(m, l[e]);
        }
        float s = 0.f;
        for (int e = 0; e < EXP; e++) { l[e] = expf(l[e] - m); s += l[e]; }
        for (int e = 0; e < EXP; e++) gw[e] = l[e] / s;
    }
}

__global__ void fuse_k(const float4* __restrict__ outs, const float* __restrict__ gw,
                       float4* __restrict__ fused) {
    long long i = (long long)blockIdx.x * 256 + threadIdx.x;
    constexpr long long N4 = ND_ELEMS / 4;
    if (i < N4) {
        float4 r = make_float4(0.f, 0.f, 0.f, 0.f);
#pragma unroll
        for (int e = 0; e < EXP; e++) {
            float4 v = outs[(long long)e * N4 + i];
            float gwe = gw[e];
            r.x += gwe * v.x; r.y += gwe * v.y; r.z += gwe * v.z; r.w += gwe * v.w;
        }
        fused[i] = r;
    }
}

__global__ void memupd_k(const float4* __restrict__ mem, const float4* __restrict__ upd4,
                         float4* __restrict__ o) {
    long long i = (long long)blockIdx.x * 256 + threadIdx.x;
    constexpr long long N4 = (long long)LMD_ELEMS / 4;
    if (i < N4) {
        float4 u = upd4[i];
#pragma unroll
        for (int e = 1; e < EXP; e++) {
            float4 v = upd4[(long long)e * N4 + i];
            u.x += v.x; u.y += v.y; u.z += v.z; u.w += v.w;
        }
        float4 mm = mem[i];
        float4 r;
        r.x = 0.9f * mm.x + fminf(fmaxf(0.1f * u.x, -0.1f), 0.1f);
        r.y = 0.9f * mm.y + fminf(fmaxf(0.1f * u.y, -0.1f), 0.1f);
        r.z = 0.9f * mm.z + fminf(fmaxf(0.1f * u.z, -0.1f), 0.1f);
        r.w = 0.9f * mm.w + fminf(fmaxf(0.1f * u.w, -0.1f), 0.1f);
        o[i] = r;
    }
}

// ---------------- host ----------------
static constexpr int stgFl(int MT, int NT, bool ATR, bool BTR) {
    return (ATR ? 16 * (MT + 8) : MT * 20) + (BTR ? 16 * (NT + 8) : NT * 20);
}
#define SMEMB(MT, NT, ATR, BTR) (4 * stgFl(MT, NT, ATR, BTR) * 4)

static void tfround(const float* s, float* d, long long n) {
    long long n4 = n / 4;
    tfround_k<<<(int)((n4 + 255) / 256), 256>>>((const float4*)s, (float4*)d, n4);
}

extern "C" void kernel_launch(void* const* d_in, const int* in_sizes, int n_in,
                              void* d_out, int out_size) {
    const float* tokens   = (const float*)d_in[0];
    const float* memories = (const float*)d_in[1];
    const float* ipw      = (const float*)d_in[2];
    const float* ipb      = (const float*)d_in[3];
    const float* opw      = (const float*)d_in[4];
    const float* opb      = (const float*)d_in[5];
    const float* w1       = (const float*)d_in[6];
    const float* b1       = (const float*)d_in[7];
    const float* w2       = (const float*)d_in[8];
    const float* b2       = (const float*)d_in[9];
    const float* n1w      = (const float*)d_in[10];
    const float* n1b      = (const float*)d_in[11];
    const float* n2w      = (const float*)d_in[12];
    const float* n2b      = (const float*)d_in[13];
    const float* aggw     = (const float*)d_in[14];
    const float* aggb     = (const float*)d_in[15];
    const float* gg       = (const float*)d_in[16];

    float* out = (float*)d_out;
    float* out_fused = out;
    float* out_gw = out + ND_ELEMS;
    float* out_mem = out + ND_ELEMS + EXP;

    static float *p_xln = nullptr, *p_xlnT = nullptr, *p_x4 = nullptr, *p_qkv4 = nullptr,
                 *p_big = nullptr, *p_sa4 = nullptr, *p_op4 = nullptr, *p_tmp4 = nullptr,
                 *p_x14 = nullptr, *p_x1r4 = nullptr, *p_xor4 = nullptr, *p_xorT = nullptr,
                 *p_out = nullptr, *p_retr4 = nullptr, *p_retrp4 = nullptr, *p_upd4 = nullptr,
                 *p_glog = nullptr, *p_vT = nullptr, *p_memT = nullptr,
                 *p_ipw = nullptr, *p_opw = nullptr, *p_w1 = nullptr, *p_w2 = nullptr,
                 *p_aggw = nullptr, *p_mem = nullptr;
    if (!p_xln) {
        cudaGetSymbolAddress((void**)&p_xln, g_xln);
        cudaGetSymbolAddress((void**)&p_xlnT, g_xlnT);
        cudaGetSymbolAddress((void**)&p_x4, g_x4);
        cudaGetSymbolAddress((void**)&p_qkv4, g_qkv4);
        cudaGetSymbolAddress((void**)&p_big, g_big);
        cudaGetSymbolAddress((void**)&p_sa4, g_sa4);
        cudaGetSymbolAddress((void**)&p_op4, g_op4);
        cudaGetSymbolAddress((void**)&p_tmp4, g_tmp4);
        cudaGetSymbolAddress((void**)&p_x14, g_x14);
        cudaGetSymbolAddress((void**)&p_x1r4, g_x1r4);
        cudaGetSymbolAddress((void**)&p_xor4, g_xor4);
        cudaGetSymbolAddress((void**)&p_xorT, g_xorT);
        cudaGetSymbolAddress((void**)&p_out, g_out);
        cudaGetSymbolAddress((void**)&p_retr4, g_retr4);
        cudaGetSymbolAddress((void**)&p_retrp4, g_retrp4);
        cudaGetSymbolAddress((void**)&p_upd4, g_upd4);
        cudaGetSymbolAddress((void**)&p_glog, g_glog);
        cudaGetSymbolAddress((void**)&p_vT, g_vT);
        cudaGetSymbolAddress((void**)&p_memT, g_memT);
        cudaGetSymbolAddress((void**)&p_ipw, g_ipw_r);
        cudaGetSymbolAddress((void**)&p_opw, g_opw_r);
        cudaGetSymbolAddress((void**)&p_w1, g_w1_r);
        cudaGetSymbolAddress((void**)&p_w2, g_w2_r);
        cudaGetSymbolAddress((void**)&p_aggw, g_aggw_r);
        cudaGetSymbolAddress((void**)&p_mem, g_mem_r);
        cudaFuncSetAttribute(gemmCP<64, 128, false, false, 3>, cudaFuncAttributeMaxDynamicSharedMemorySize, SMEMB(64, 128, false, false));
        cudaFuncSetAttribute(gemmCP<64, 64, false, false, 3>,  cudaFuncAttributeMaxDynamicSharedMemorySize, SMEMB(64, 64, false, false));
        cudaFuncSetAttribute(gemmCP<64, 128, true, false, 3>,  cudaFuncAttributeMaxDynamicSharedMemorySize, SMEMB(64, 128, true, false));
    }

    const float inv_sqrt_d = 1.0f / sqrtf((float)DIM);
    const float inv_sqrt_dh = 1.0f / sqrtf((float)DHEAD);

    tfround(ipw, p_ipw, (long long)EXP * 3 * DIM * DIM);
    tfround(opw, p_opw, (long long)EXP * DIM * DIM);
    tfround(w1, p_w1, (long long)EXP * FFD * DIM);
    tfround(w2, p_w2, (long long)EXP * DIM * FFD);
    tfround(aggw, p_aggw, (long long)DIM * NL * DIM);
    tfround(memories, p_mem, (long long)LMD_ELEMS);
    transpose_k<1><<<dim3(DIM / 32, MEMSZ / 32, NL), dim3(32, 8)>>>(
        memories, p_memT, MEMSZ, DIM, DIM, (long long)MEMSZ * DIM, (long long)MEMSZ * DIM);

    zero_k<<<1, 256>>>(p_glog, EXP);
    ln_k<<<EXP * NTOK, 128>>>(tokens, p_xln);
    // xlnT[d][e*2048+n] (already rounded)
    transpose_k<0><<<dim3(DIM / 32, EXP * NTOK / 32, 1), dim3(32, 8)>>>(
        p_xln, p_xlnT, EXP * NTOK, DIM, DIM, 0, 0);

    const long long LLND = ND_ELEMS;
    const long long BIGE = (long long)NH * NTOK * NTOK;
    const long long QKVE = (long long)NTOK * 3 * DIM;

    // 1. cross logits [e][2048, 6144]
    gemmCP<64, 128, false, false, 3><<<dim3(48, 32, EXP), 256, SMEMB(64, 128, false, false)>>>(
        p_xln, p_xln, p_big, DIM, DIM, DIM, 3 * NTOK,
        LLND, 0, 0, 0, (long long)NTOK * 3 * NTOK, 0, 1,
        inv_sqrt_d, nullptr, 0, nullptr, 0, 0, 10.f, 0, -1, NTOK);
    softmax_k<<<EXP * NTOK, 256, 3 * NTOK * 4>>>(p_big, 3 * NTOK);
    // 2. x = probs @ ctx + xln (natural via xlnT, k-remap, rounded)
    gemmCP<64, 128, false, false, 3><<<dim3(4, 32, EXP), 256, SMEMB(64, 128, false, false)>>>(
        p_big, p_xlnT, p_x4, 3 * NTOK, 3 * NTOK, EXP * NTOK, DIM,
        (long long)NTOK * 3 * NTOK, 0, 0, 0, LLND, 0, 1,
        1.f, nullptr, 0, p_xln, LLND, DIM, 0.f, GFLAG_TFOUT | GFLAG_KREMAP, -1, NTOK);
    // 3. qkv (rounded)
    gemmCP<64, 128, false, false, 3><<<dim3(12, 32, EXP), 256, SMEMB(64, 128, false, false)>>>(
        p_x4, p_ipw, p_qkv4, DIM, DIM, DIM, 3 * DIM,
        LLND, 0, (long long)3 * DIM * DIM, 0, QKVE, 0, 1,
        1.f, ipb, 3 * DIM, nullptr, 0, 0, 0.f, GFLAG_TFOUT, 0, 0);
    // 3b. vT[e][hd][n]
    transpose_k<0><<<dim3(DIM / 32, NTOK / 32, EXP), dim3(32, 8)>>>(
        p_qkv4 + 2 * DIM, p_vT, NTOK, DIM, 3 * DIM, QKVE, LLND);
    // 4. scores [e][h][2048,2048]
    gemmCP<64, 128, false, false, 3><<<dim3(16, 32, EXP * NH), 256, SMEMB(64, 128, false, false)>>>(
        p_qkv4, p_qkv4 + DIM, p_big, DHEAD, 3 * DIM, 3 * DIM, NTOK,
        QKVE, DHEAD, QKVE, DHEAD, BIGE, (long long)NTOK * NTOK, NH,
        inv_sqrt_dh, nullptr, 0, nullptr, 0, 0, 0.f, 0, 0, 0);
    softmax_k<<<EXP * NH * NTOK, 256, NTOK * 4>>>(p_big, NTOK);
    // 5. sa = probs @ v (natural via vT, rounded)
    gemmCP<64, 64, false, false, 3><<<dim3(1, 32, EXP * NH), 256, SMEMB(64, 64, false, false)>>>(
        p_big, p_vT, p_sa4, NTOK, NTOK, NTOK, DIM,
        BIGE, (long long)NTOK * NTOK, LLND, (long long)DHEAD * NTOK, LLND, DHEAD, NH,
        1.f, nullptr, 0, nullptr, 0, 0, 0.f, GFLAG_TFOUT, 0, 0);
    // 6. out_proj
    gemmCP<64, 128, false, false, 3><<<dim3(4, 32, EXP), 256, SMEMB(64, 128, false, false)>>>(
        p_sa4, p_opw, p_op4, DIM, DIM, DIM, DIM,
        LLND, 0, (long long)DIM * DIM, 0, LLND, 0, 1,
        1.f, opb, DIM, nullptr, 0, 0, 0.f, 0, 0, 0);
    ln_ra_k<<<EXP * NTOK, 128>>>(p_x4, p_op4, n1w, n1b, p_x14, p_x1r4);
    // 7. ff1 relu (rounded)
    gemmCP<64, 128, false, false, 3><<<dim3(16, 32, EXP), 256, SMEMB(64, 128, false, false)>>>(
        p_x1r4, p_w1, p_tmp4, DIM, DIM, DIM, FFD,
        LLND, 0, (long long)FFD * DIM, 0, (long long)NTOK * FFD, 0, 1,
        1.f, b1, FFD, nullptr, 0, 0, 0.f, GFLAG_RELU | GFLAG_TFOUT, 0, 0);
    // 8. ff2
    gemmCP<64, 128, false, false, 3><<<dim3(4, 32, EXP), 256, SMEMB(64, 128, false, false)>>>(
        p_tmp4, p_w2, p_sa4, FFD, FFD, FFD, DIM,
        (long long)NTOK * FFD, 0, (long long)DIM * FFD, 0, LLND, 0, 1,
        1.f, b2, DIM, nullptr, 0, 0, 0.f, 0, 0, 0);
    ln_ra_k<<<EXP * NTOK, 128>>>(p_x14, p_sa4, n2w, n2b, p_out, p_xor4);
    // 8b. xorT[e][d][n] (xor4 already rounded)
    transpose_k<0><<<dim3(DIM / 32, NTOK / 32, EXP), dim3(32, 8)>>>(
        p_xor4, p_xorT, NTOK, DIM, DIM, LLND, LLND);
    // 9. memory logits [e][l][2048,4096]
    gemmCP<64, 128, false, false, 3><<<dim3(32, 32, EXP * NL), 256, SMEMB(64, 128, false, false)>>>(
        p_xor4, p_mem, p_big, DIM, DIM, DIM, MEMSZ,
        LLND, 0, 0, (long long)MEMSZ * DIM, (long long)NL * NTOK * MEMSZ, (long long)NTOK * MEMSZ, NL,
        inv_sqrt_d, nullptr, 0, nullptr, 0, 0, 10.f, 0, 0, 0);
    softmax_k<<<EXP * NL * NTOK, 256, MEMSZ * 4>>>(p_big, MEMSZ);
    // 10. retr (natural via memT)
    gemmCP<64, 128, false, false, 3><<<dim3(4, 32, EXP * NL), 256, SMEMB(64, 128, false, false)>>>(
        p_big, p_memT, p_retr4, MEMSZ, MEMSZ, MEMSZ, DIM,
        (long long)NL * NTOK * MEMSZ, (long long)NTOK * MEMSZ, 0, (long long)MEMSZ * DIM,
        (long long)NL * NTOK * DIM, (long long)NTOK * DIM, NL,
        1.f, nullptr, 0, nullptr, 0, 0, 0.f, 0, 0, 0);
    // 11. upd4[e][l] = clip(am^T @ xout, 1)  (A transposed, B natural via xorT)
    gemmCP<64, 128, true, false, 3><<<dim3(4, 64, EXP * NL), 256, SMEMB(64, 128, true, false)>>>(
        p_big, p_xorT, p_upd4, NTOK, MEMSZ, NTOK, DIM,
        (long long)NL * NTOK * MEMSZ, (long long)NTOK * MEMSZ, LLND, 0,
        (long long)LMD_ELEMS, (long long)MEMSZ * DIM, NL,
        1.f, nullptr, 0, nullptr, 0, 0, 1.f, 0, 0, 0);
    permute_k<<<(EXP * NL * ND_ELEMS / 4 + 255) / 256, 256>>>((const float4*)p_retr4, (float4*)p_retrp4);
    // 12. outs += retrp @ aggw^T + aggb
    gemmCP<64, 128, false, false, 3><<<dim3(4, 32, EXP), 256, SMEMB(64, 128, false, false)>>>(
        p_retrp4, p_aggw, p_out, NL * DIM, NL * DIM, NL * DIM, DIM,
        (long long)NTOK * NL * DIM, 0, 0, 0, LLND, 0, 1,
        1.f, aggb, 0, p_out, LLND, DIM, 0.f, 0, 0, 0);

    dim3 ggrid(EXP, 16);
    gate_dot_k<<<ggrid, 256>>>(p_out, gg, p_glog);
    gate_softmax_k<<<1, 32>>>(p_glog, out_gw);
    fuse_k<<<(ND_ELEMS / 4 + 255) / 256, 256>>>((const float4*)p_out, out_gw, (float4*)out_fused);
    memupd_k<<<(LMD_ELEMS / 4 + 255) / 256, 256>>>((const float4*)memories, (const float4*)p_upd4, (float4*)out_mem);

    (void)in_sizes; (void)n_in; (void)out_size;
}